// round 11
// baseline (speedup 1.0000x reference)
#include <cuda_runtime.h>
#include <cuda_fp16.h>
#include <math.h>
#include <stdint.h>

#define NN   10000
#define NE   250000
#define FF   128
#define NRBF 50
#define RBFP 64

typedef unsigned long long ull;

// ---------------- scratch ----------------
__device__ float  g_x[NN * FF];
__device__ float  g_qkv[NN * 3 * 512];
__device__ __half g_rbf[(size_t)NE * RBFP];
__device__ float  g_unit[(size_t)NE * 3];
__device__ __half g_dv[(size_t)NE * 512];
__device__ float  g_logit[(size_t)NE * 4];
__device__ __half g_msg[(size_t)NE * 512];
__device__ float  g_eout[(size_t)NE * 384];
__device__ uint32_t g_wdp[384 * 16 * 16];
__device__ uint32_t g_wdkp[512 * 2 * 16];
__device__ uint32_t g_wdvp[512 * 2 * 16];
__device__ int g_cnt[NN];
__device__ int g_off[NN + 1];
__device__ int g_pos[NN];
__device__ int g_eidx[NE];

#define FMA2(acc, a, b) asm("fma.rn.f32x2 %0, %1, %2, %0;" : "+l"(acc) : "l"(a), "l"(b))
#define PACK2(dst, f)   asm("mov.b64 %0, {%1, %1};" : "=l"(dst) : "f"(f))
#define UNPACK2(lo, hi, v) asm("mov.b64 {%0, %1}, %2;" : "=f"(lo), "=f"(hi) : "l"(v))

__device__ __forceinline__ uint32_t smem_u32(const void* p) {
    uint32_t a;
    asm("{ .reg .u64 t; cvta.to.shared.u64 t, %1; cvt.u32.u64 %0, t; }" : "=r"(a) : "l"(p));
    return a;
}
__device__ __forceinline__ float silu_f(float v) {
    return v / (1.f + __expf(-v));
}

#define MMA_F16(c, a0, a1, a2, a3, b0, b1)                                \
    asm volatile("mma.sync.aligned.m16n8k16.row.col.f32.f16.f16.f32 "     \
        "{%0,%1,%2,%3}, {%4,%5,%6,%7}, {%8,%9}, {%0,%1,%2,%3};"           \
        : "+f"((c)[0]), "+f"((c)[1]), "+f"((c)[2]), "+f"((c)[3])          \
        : "r"(a0), "r"(a1), "r"(a2), "r"(a3), "r"(b0), "r"(b1))

#define CP_ASYNC16(dst, src) \
    asm volatile("cp.async.ca.shared.global [%0], [%1], 16;" :: "r"(dst), "l"(src))
#define CP_COMMIT() asm volatile("cp.async.commit_group;" ::: "memory")
#define CP_WAIT0()  asm volatile("cp.async.wait_group 0;" ::: "memory")

// ================= CSR build =================
__global__ void zero_int(int* __restrict__ p, int n) {
    int i = blockIdx.x * blockDim.x + threadIdx.x;
    if (i < n) p[i] = 0;
}
__global__ void zero_f(float* __restrict__ p, int n) {
    int i = blockIdx.x * blockDim.x + threadIdx.x;
    if (i < n) p[i] = 0.f;
}
__global__ void csr_hist(const int* __restrict__ nbrs, int* __restrict__ cnt) {
    int e = blockIdx.x * 256 + threadIdx.x;
    if (e < NE) atomicAdd(&cnt[nbrs[2 * e]], 1);
}
__global__ void __launch_bounds__(256) csr_scan(const int* __restrict__ cnt,
                                                int* __restrict__ off,
                                                int* __restrict__ pos) {
    __shared__ int base;
    __shared__ int wsum[8];
    if (threadIdx.x == 0) base = 0;
    __syncthreads();
    for (int c0 = 0; c0 < NN; c0 += 256) {
        int i = c0 + threadIdx.x;
        int v = (i < NN) ? cnt[i] : 0;
        int lane = threadIdx.x & 31, w = threadIdx.x >> 5;
        int x = v;
        #pragma unroll
        for (int o = 1; o < 32; o <<= 1) {
            int y = __shfl_up_sync(0xffffffffu, x, o);
            if (lane >= o) x += y;
        }
        if (lane == 31) wsum[w] = x;
        __syncthreads();
        int add = 0;
        #pragma unroll
        for (int k = 0; k < 8; k++) if (k < w) add += wsum[k];
        int incl = x + add;
        if (i < NN) {
            int excl = base + incl - v;
            off[i] = excl;
            pos[i] = excl;
        }
        __syncthreads();
        if (threadIdx.x == 255) base += incl;
        __syncthreads();
    }
    if (threadIdx.x == 0) off[NN] = base;
}
__global__ void csr_scatter(const int* __restrict__ nbrs, int* __restrict__ pos,
                            int* __restrict__ eidx) {
    int e = blockIdx.x * 256 + threadIdx.x;
    if (e < NE) {
        int p = atomicAdd(&pos[nbrs[2 * e]], 1);
        eidx[p] = e;
    }
}

// ================= segment-sum gather =================
__global__ void __launch_bounds__(128)
gather_kernel(const int* __restrict__ off, const int* __restrict__ eidx,
              const int* __restrict__ nbrs, const float* __restrict__ unit,
              const float* __restrict__ v_j, const float* __restrict__ eout,
              float* __restrict__ ds, float* __restrict__ dvout) {
    int i = blockIdx.x;
    int f = threadIdx.x;
    int s = off[i], t = off[i + 1];
    float a_ds = 0.f, a0 = 0.f, a1 = 0.f, a2 = 0.f;
    for (int p = s; p < t; p++) {
        int e = __ldg(eidx + p);
        int jj = __ldg(nbrs + 2 * e + 1);
        float ux = __ldg(unit + 3 * e), uy = __ldg(unit + 3 * e + 1), uz = __ldg(unit + 3 * e + 2);
        const float* o = eout + (size_t)e * 384;
        float s0 = o[f], s1 = o[128 + f], s2 = o[256 + f];
        const float* vj = v_j + ((size_t)jj * FF + f) * 3;
        a_ds += s1;
        a0 += s2 * ux + s0 * vj[0];
        a1 += s2 * uy + s0 * vj[1];
        a2 += s2 * uz + s0 * vj[2];
    }
    ds[(size_t)i * FF + f] = a_ds;
    float* dv = dvout + ((size_t)i * FF + f) * 3;
    dv[0] = a0; dv[1] = a1; dv[2] = a2;
}

// ================= B pre-permutation =================
__global__ void conv_B(const float* __restrict__ W, uint32_t* __restrict__ out,
                       int N, int nst, int Kreal, int Nld) {
    int i = blockIdx.x * 256 + threadIdx.x;
    int total = N * nst * 16;
    if (i >= total) return;
    int n = i / (nst * 16);
    int rem = i % (nst * 16);
    int s = rem >> 4, p = rem & 15;
    int bp = (p & 3) * 4 + (p >> 2);
    int k = s * 32 + bp * 2;
    float lo = (k < Kreal)     ? W[(size_t)k * Nld + n]       : 0.f;
    float hi = (k + 1 < Kreal) ? W[(size_t)(k + 1) * Nld + n] : 0.f;
    __half2 h = __floats2half2_rn(lo, hi);
    out[i] = *(uint32_t*)&h;
}

__global__ void __launch_bounds__(128) ln_kernel(const float* __restrict__ s,
                                                 const float* __restrict__ gam,
                                                 const float* __restrict__ bet,
                                                 float* __restrict__ x) {
    int n = blockIdx.x, t = threadIdx.x;
    float v = s[(size_t)n * FF + t];
    float s1 = v, s2 = v * v;
    #pragma unroll
    for (int o = 16; o; o >>= 1) {
        s1 += __shfl_down_sync(0xffffffffu, s1, o);
        s2 += __shfl_down_sync(0xffffffffu, s2, o);
    }
    __shared__ float p1[4], p2[4], mv[2];
    if ((t & 31) == 0) { p1[t >> 5] = s1; p2[t >> 5] = s2; }
    __syncthreads();
    if (t == 0) {
        float a = p1[0] + p1[1] + p1[2] + p1[3];
        float c = p2[0] + p2[1] + p2[2] + p2[3];
        float m = a / 128.f;
        mv[0] = m;
        mv[1] = rsqrtf(c / 128.f - m * m + 1e-5f);
    }
    __syncthreads();
    x[(size_t)n * FF + t] = (v - mv[0]) * mv[1] * gam[t] + bet[t];
}

__global__ void __launch_bounds__(256) edge_prep(const float* __restrict__ r,
                                                 __half* __restrict__ rbf,
                                                 float* __restrict__ unit) {
    int e = blockIdx.x * 256 + threadIdx.x;
    if (e >= NE) return;
    float x = __ldg(r + 3 * e), y = __ldg(r + 3 * e + 1), z = __ldg(r + 3 * e + 2);
    float d = sqrtf(x * x + y * y + z * z + 3e-15f);
    float inv = 1.f / d;
    unit[3 * e] = x * inv; unit[3 * e + 1] = y * inv; unit[3 * e + 2] = z * inv;
    const float width = 5.0f / 49.0f;
    const float gam = 0.5f / (width * width);
    __half2 buf[32];
    #pragma unroll
    for (int k2 = 0; k2 < 32; k2++) {
        int k0 = k2 * 2, k1 = k2 * 2 + 1;
        float d0 = d - (float)k0 * width;
        float d1 = d - (float)k1 * width;
        float v0 = (k0 < NRBF) ? __expf(-gam * d0 * d0) : 0.f;
        float v1 = (k1 < NRBF) ? __expf(-gam * d1 * d1) : 0.f;
        buf[k2] = __floats2half2_rn(v0, v1);
    }
    uint4* dst = (uint4*)(rbf + (size_t)e * RBFP);
    const uint4* src = (const uint4*)buf;
    #pragma unroll
    for (int q = 0; q < 8; q++) dst[q] = src[q];
}

// ================= qkv: fused 3-way f32x2 SGEMM =================
__global__ void __launch_bounds__(256, 2)
qkv_gemm(const float* __restrict__ Xin,
         const float* __restrict__ Wq, const float* __restrict__ Wk,
         const float* __restrict__ Wv,
         const float* __restrict__ bq, const float* __restrict__ bk,
         const float* __restrict__ bv,
         float* __restrict__ qkvout) {
    const int M = NN, N = 512, K = 128, lda = 128, ldc = 1536;
    int which = blockIdx.x >> 2;
    const float* B    = (which == 0) ? Wq : ((which == 1) ? Wk : Wv);
    const float* bias = (which == 0) ? bq : ((which == 1) ? bk : bv);
    float* C = qkvout + which * 512;
    int col0 = (blockIdx.x & 3) * 128;
    int row0 = blockIdx.y * 128;

    __shared__ float As[2][8][128];
    __shared__ float Bs[2][8][128];

    int t  = threadIdx.x;
    int ty = t >> 4, tx = t & 15;

    int arow = t >> 1;
    int acol = (t & 1) * 4;
    int am   = min(row0 + arow, M - 1);
    const float* Aptr = Xin + (size_t)am * lda + acol;

    int bk_ = t >> 5;
    int bn  = (t & 31) * 4;

    float4 ar, br;
    ar = *(const float4*)(Aptr);
    br = *(const float4*)(B + (size_t)bk_ * N + col0 + bn);

    As[0][acol + 0][arow] = ar.x;
    As[0][acol + 1][arow] = ar.y;
    As[0][acol + 2][arow] = ar.z;
    As[0][acol + 3][arow] = ar.w;
    *(float4*)&Bs[0][bk_][bn] = br;
    __syncthreads();

    ull acc[8][4];
    #pragma unroll
    for (int i = 0; i < 8; i++)
        #pragma unroll
        for (int j = 0; j < 4; j++) acc[i][j] = 0ULL;

    const int nstage = K >> 3;
    for (int s = 0; s < nstage; s++) {
        int cur = s & 1, nxt = cur ^ 1;
        bool more = (s + 1 < nstage);
        if (more) {
            int kk = (s + 1) << 3;
            ar = *(const float4*)(Aptr + kk);
            br = *(const float4*)(B + (size_t)(kk + bk_) * N + col0 + bn);
        }
        #pragma unroll
        for (int k = 0; k < 8; k++) {
            float4 a0 = *(float4*)&As[cur][k][ty * 8];
            float4 a1 = *(float4*)&As[cur][k][ty * 8 + 4];
            ulonglong2 b0 = *(ulonglong2*)&Bs[cur][k][tx * 8];
            ulonglong2 b1 = *(ulonglong2*)&Bs[cur][k][tx * 8 + 4];
            ull a2[8];
            PACK2(a2[0], a0.x); PACK2(a2[1], a0.y);
            PACK2(a2[2], a0.z); PACK2(a2[3], a0.w);
            PACK2(a2[4], a1.x); PACK2(a2[5], a1.y);
            PACK2(a2[6], a1.z); PACK2(a2[7], a1.w);
            #pragma unroll
            for (int i = 0; i < 8; i++) {
                FMA2(acc[i][0], a2[i], b0.x);
                FMA2(acc[i][1], a2[i], b0.y);
                FMA2(acc[i][2], a2[i], b1.x);
                FMA2(acc[i][3], a2[i], b1.y);
            }
        }
        if (more) {
            As[nxt][acol + 0][arow] = ar.x;
            As[nxt][acol + 1][arow] = ar.y;
            As[nxt][acol + 2][arow] = ar.z;
            As[nxt][acol + 3][arow] = ar.w;
            *(float4*)&Bs[nxt][bk_][bn] = br;
        }
        __syncthreads();
    }

    int colb = col0 + tx * 8;
    float4 bs0 = *(const float4*)(bias + colb);
    float4 bs1 = *(const float4*)(bias + colb + 4);
    #pragma unroll
    for (int i = 0; i < 8; i++) {
        int row = row0 + ty * 8 + i;
        if (row >= M) continue;
        float v[8];
        UNPACK2(v[0], v[1], acc[i][0]);
        UNPACK2(v[2], v[3], acc[i][1]);
        UNPACK2(v[4], v[5], acc[i][2]);
        UNPACK2(v[6], v[7], acc[i][3]);
        v[0] += bs0.x; v[1] += bs0.y; v[2] += bs0.z; v[3] += bs0.w;
        v[4] += bs1.x; v[5] += bs1.y; v[6] += bs1.z; v[7] += bs1.w;
        float* cp = C + (size_t)row * ldc + colb;
        *(float4*)cp       = make_float4(v[0], v[1], v[2], v[3]);
        *(float4*)(cp + 4) = make_float4(v[4], v[5], v[6], v[7]);
    }
}

// ================= attn_msg: msg = v*dv*silu(logit) =================
__global__ void __launch_bounds__(256) attn_msg(const float* __restrict__ qkv,
                                                const __half* __restrict__ dv,
                                                const float* __restrict__ logit,
                                                const int* __restrict__ nbrs,
                                                __half* __restrict__ msg) {
    int e = blockIdx.x * 8 + (threadIdx.x >> 5);
    if (e >= NE) return;
    int l = threadIdx.x & 31;
    int j = __ldg(nbrs + 2 * e + 1);
    const float4* v4 = (const float4*)(qkv + (size_t)j * 1536 + 1024);
    const uint2* dv2 = (const uint2*)(dv + (size_t)e * 512);
    float4 lg = *(const float4*)(logit + (size_t)e * 4);
    float at[4];
    at[0] = silu_f(lg.x); at[1] = silu_f(lg.y);
    at[2] = silu_f(lg.z); at[3] = silu_f(lg.w);

    __half* mrow = msg + (size_t)e * 512;
    #pragma unroll
    for (int h = 0; h < 4; h++) {
        int idx = h * 32 + l;
        float4 vv = v4[idx];
        uint2 dvv = dv2[idx];
        float2 g0 = __half22float2(*(__half2*)&dvv.x);
        float2 g1 = __half22float2(*(__half2*)&dvv.y);
        __half2 m0 = __floats2half2_rn(vv.x * g0.x * at[h], vv.y * g0.y * at[h]);
        __half2 m1 = __floats2half2_rn(vv.z * g1.x * at[h], vv.w * g1.y * at[h]);
        uint2 o2;
        o2.x = *(uint32_t*)&m0;
        o2.y = *(uint32_t*)&m1;
        *(uint2*)(mrow + h * 128 + l * 4) = o2;
    }
}

// ================= fp16 mma GEMM =================
// EPI=0: dv — silu + half store to C.
// EPI=1: big GEMM — biased float store to eout.
// EPI=2: dk — silu to smem, then fused q·k·dk dot -> atomicAdd logit[e*4+head].
#define SROWU 20
#define ABUFU (128 * SROWU)

template <int EPI, int NSLICE>
__global__ void __launch_bounds__(256)
mma_fp16(const __half* __restrict__ A, const uint32_t* __restrict__ Bp,
         const float* __restrict__ bias, __half* __restrict__ C, int ldc,
         float* __restrict__ eout,
         const float* __restrict__ qkv, const int* __restrict__ nbrs,
         float* __restrict__ logit,
         int M, int lda, int nstage) {
    extern __shared__ uint32_t sm[];
    const uint32_t sA = smem_u32(sm);
    const uint32_t sB0 = sA + 2 * ABUFU * 4;

    const int tid = threadIdx.x;
    const int wid = tid >> 5, lid = tid & 31;
    const int gq = lid >> 2, tig = lid & 3;
    const int wM = wid >> 1, wN = wid & 1;
    const int row0 = (EPI == 1 ? blockIdx.x : blockIdx.y) * 128;
    const int n0s  = (EPI == 1 ? 0 : blockIdx.x * 128);

    float acc[NSLICE][2][8][4];
    #pragma unroll
    for (int s = 0; s < NSLICE; s++)
        #pragma unroll
        for (int a = 0; a < 2; a++)
            #pragma unroll
            for (int b = 0; b < 8; b++)
                #pragma unroll
                for (int c = 0; c < 4; c++) acc[s][a][b][c] = 0.f;

    const int arow = tid >> 1, ac2 = (tid & 1) * 2;
    const __half* aRow = A + (size_t)min(row0 + arow, M - 1) * lda;

    auto stage_A = [&](int s, int buf) {
        const __half* src = aRow + s * 32 + ac2 * 8;
        uint32_t dst = sA + (buf * ABUFU + arow * SROWU + ac2 * 4) * 4;
        CP_ASYNC16(dst, src);
        CP_ASYNC16(dst + 16, src + 8);
    };

    auto stage_B = [&](int s, int buf) {
        #pragma unroll
        for (int i = 0; i < NSLICE * 2; i++) {
            int cid = tid + i * 256;
            int sl = cid >> 9;
            int c  = cid & 511;
            int n = c >> 2, q = c & 3;
            int ng = (EPI == 1 ? sl * 128 : n0s) + n;
            const uint32_t* src = Bp + ((size_t)ng * nstage + s) * 16 + q * 4;
            uint32_t dst = sB0 + ((sl * 2 + buf) * ABUFU + n * SROWU + q * 4) * 4;
            CP_ASYNC16(dst, src);
        }
    };

    stage_A(0, 0);
    stage_B(0, 0);
    CP_COMMIT();
    CP_WAIT0();
    __syncthreads();

    for (int s = 0; s < nstage; s++) {
        int cur = s & 1;
        bool more = (s + 1 < nstage);
        if (more) {
            stage_A(s + 1, cur ^ 1);
            stage_B(s + 1, cur ^ 1);
            CP_COMMIT();
        }

        uint32_t af[2][2][4];
        const uint32_t* Ab = sm + cur * ABUFU;
        #pragma unroll
        for (int mf = 0; mf < 2; mf++) {
            int r0 = wM * 32 + mf * 16 + gq;
            const uint32_t* p0 = Ab + r0 * SROWU;
            const uint32_t* p1 = Ab + (r0 + 8) * SROWU;
            #pragma unroll
            for (int ks = 0; ks < 2; ks++) {
                af[mf][ks][0] = p0[tig + 8 * ks];
                af[mf][ks][1] = p1[tig + 8 * ks];
                af[mf][ks][2] = p0[tig + 4 + 8 * ks];
                af[mf][ks][3] = p1[tig + 4 + 8 * ks];
            }
        }
        const uint32_t* Bbase = sm + 2 * ABUFU + cur * ABUFU;
        #pragma unroll
        for (int sl = 0; sl < NSLICE; sl++) {
            const uint32_t* Bb = Bbase + sl * 2 * ABUFU;
            #pragma unroll
            for (int nf = 0; nf < 8; nf++) {
                int n = wN * 64 + nf * 8 + gq;
                uint4 bv = *(const uint4*)(Bb + n * SROWU + tig * 4);
                MMA_F16(acc[sl][0][nf], af[0][0][0], af[0][0][1], af[0][0][2], af[0][0][3], bv.x, bv.y);
                MMA_F16(acc[sl][1][nf], af[1][0][0], af[1][0][1], af[1][0][2], af[1][0][3], bv.x, bv.y);
                MMA_F16(acc[sl][0][nf], af[0][1][0], af[0][1][1], af[0][1][2], af[0][1][3], bv.z, bv.w);
                MMA_F16(acc[sl][1][nf], af[1][1][0], af[1][1][1], af[1][1][2], af[1][1][3], bv.z, bv.w);
            }
        }
        if (more) CP_WAIT0();
        __syncthreads();
    }

    if constexpr (EPI == 0) {
        #pragma unroll
        for (int mf = 0; mf < 2; mf++)
        #pragma unroll
        for (int rs = 0; rs < 2; rs++) {
            int r = row0 + wM * 32 + mf * 16 + rs * 8 + gq;
            if (r >= M) continue;
            #pragma unroll
            for (int nf = 0; nf < 8; nf++) {
                int nc = wN * 64 + nf * 8 + tig * 2;
                float v0 = silu_f(acc[0][mf][nf][rs * 2 + 0] + __ldg(bias + n0s + nc));
                float v1 = silu_f(acc[0][mf][nf][rs * 2 + 1] + __ldg(bias + n0s + nc + 1));
                *(__half2*)(C + (size_t)r * ldc + n0s + nc) = __floats2half2_rn(v0, v1);
            }
        }
    } else if constexpr (EPI == 1) {
        #pragma unroll
        for (int mf = 0; mf < 2; mf++)
        #pragma unroll
        for (int rs = 0; rs < 2; rs++) {
            int e = row0 + wM * 32 + mf * 16 + rs * 8 + gq;
            if (e >= M) continue;
            float* o = eout + (size_t)e * 384;
            #pragma unroll
            for (int nf = 0; nf < 8; nf++) {
                int f = wN * 64 + nf * 8 + tig * 2;
                #pragma unroll
                for (int sl = 0; sl < NSLICE; sl++) {
                    float v0 = acc[sl][mf][nf][rs * 2 + 0] + __ldg(bias + sl * 128 + f);
                    float v1 = acc[sl][mf][nf][rs * 2 + 1] + __ldg(bias + sl * 128 + f + 1);
                    *(float2*)(o + sl * 128 + f) = make_float2(v0, v1);
                }
            }
        }
    } else {
        // dk: silu -> smem tile [128 rows][128 cols] half, then fused dot.
        __half* dks = (__half*)sm;
        #pragma unroll
        for (int mf = 0; mf < 2; mf++)
        #pragma unroll
        for (int rs = 0; rs < 2; rs++) {
            int rl = wM * 32 + mf * 16 + rs * 8 + gq;
            #pragma unroll
            for (int nf = 0; nf < 8; nf++) {
                int nc = wN * 64 + nf * 8 + tig * 2;
                float v0 = silu_f(acc[0][mf][nf][rs * 2 + 0] + __ldg(bias + n0s + nc));
                float v1 = silu_f(acc[0][mf][nf][rs * 2 + 1] + __ldg(bias + n0s + nc + 1));
                *(__half2*)(dks + rl * 128 + nc) = __floats2half2_rn(v0, v1);
            }
        }
        __syncthreads();
        int head = blockIdx.x;
        // warp wid handles edges wid*16 .. wid*16+15; lane l covers cols l*4..l*4+3
        #pragma unroll 4
        for (int el = 0; el < 16; el++) {
            int e = row0 + wid * 16 + el;
            if (e >= M) break;
            int ii = __ldg(nbrs + 2 * e), jj = __ldg(nbrs + 2 * e + 1);
            const float4 qv = *(const float4*)(qkv + (size_t)ii * 1536 + n0s + lid * 4);
            const float4 kv = *(const float4*)(qkv + (size_t)jj * 1536 + 512 + n0s + lid * 4);
            uint2 dk2 = *(uint2*)(dks + (wid * 16 + el) * 128 + lid * 4);
            float2 d0 = __half22float2(*(__half2*)&dk2.x);
            float2 d1 = __half22float2(*(__half2*)&dk2.y);
            float p = qv.x * kv.x * d0.x + qv.y * kv.y * d0.y
                    + qv.z * kv.z * d1.x + qv.w * kv.w * d1.y;
            #pragma unroll
            for (int o = 16; o; o >>= 1) p += __shfl_xor_sync(0xffffffffu, p, o);
            if (lid == 0) atomicAdd(logit + (size_t)e * 4 + head, p);
        }
    }
}

// ================= launch =================
extern "C" void kernel_launch(void* const* d_in, const int* in_sizes, int n_in,
                              void* d_out, int out_size) {
    const float* s_j  = (const float*)d_in[0];
    const float* v_j  = (const float*)d_in[1];
    const float* r_ij = (const float*)d_in[2];
    const int*   nbrs = (const int*)  d_in[3];
    const float* ln_g = (const float*)d_in[4];
    const float* ln_b = (const float*)d_in[5];
    const float* Wq   = (const float*)d_in[6];
    const float* bq   = (const float*)d_in[7];
    const float* Wk   = (const float*)d_in[8];
    const float* bk   = (const float*)d_in[9];
    const float* Wv   = (const float*)d_in[10];
    const float* bv   = (const float*)d_in[11];
    const float* Wdk  = (const float*)d_in[12];
    const float* bdk  = (const float*)d_in[13];
    const float* Wdv  = (const float*)d_in[14];
    const float* bdv  = (const float*)d_in[15];
    const float* Wd   = (const float*)d_in[16];
    const float* bd   = (const float*)d_in[17];
    float* out = (float*)d_out;

    float *x, *qkv, *unit, *eout, *logit;
    __half *rbf, *dv, *msg;
    uint32_t *wdp, *wdkp, *wdvp;
    int *cnt, *off, *pos, *eidx;
    cudaGetSymbolAddress((void**)&x,    g_x);
    cudaGetSymbolAddress((void**)&qkv,  g_qkv);
    cudaGetSymbolAddress((void**)&rbf,  g_rbf);
    cudaGetSymbolAddress((void**)&unit, g_unit);
    cudaGetSymbolAddress((void**)&dv,   g_dv);
    cudaGetSymbolAddress((void**)&logit, g_logit);
    cudaGetSymbolAddress((void**)&msg,  g_msg);
    cudaGetSymbolAddress((void**)&eout, g_eout);
    cudaGetSymbolAddress((void**)&wdp,  g_wdp);
    cudaGetSymbolAddress((void**)&wdkp, g_wdkp);
    cudaGetSymbolAddress((void**)&wdvp, g_wdvp);
    cudaGetSymbolAddress((void**)&cnt,  g_cnt);
    cudaGetSymbolAddress((void**)&off,  g_off);
    cudaGetSymbolAddress((void**)&pos,  g_pos);
    cudaGetSymbolAddress((void**)&eidx, g_eidx);

    const int SMEM_SMALL = (2 + 1 * 2) * ABUFU * 4;   // 40960
    const int SMEM_BIG   = (2 + 3 * 2) * ABUFU * 4;   // 81920
    cudaFuncSetAttribute(mma_fp16<0, 1>, cudaFuncAttributeMaxDynamicSharedMemorySize, SMEM_SMALL);
    cudaFuncSetAttribute(mma_fp16<2, 1>, cudaFuncAttributeMaxDynamicSharedMemorySize, SMEM_SMALL);
    cudaFuncSetAttribute(mma_fp16<1, 3>, cudaFuncAttributeMaxDynamicSharedMemorySize, SMEM_BIG);

    // CSR build (independent)
    zero_int<<<(NN + 255) / 256, 256>>>(cnt, NN);
    csr_hist<<<(NE + 255) / 256, 256>>>(nbrs, cnt);
    csr_scan<<<1, 256>>>(cnt, off, pos);
    csr_scatter<<<(NE + 255) / 256, 256>>>(nbrs, pos, eidx);

    zero_f<<<(NE * 4 + 255) / 256, 256>>>(logit, NE * 4);

    conv_B<<<(384 * 16 * 16 + 255) / 256, 256>>>(Wd,  wdp,  384, 16, 512, 384);
    conv_B<<<(512 * 2 * 16 + 255) / 256, 256>>>(Wdk, wdkp, 512, 2, 50, 512);
    conv_B<<<(512 * 2 * 16 + 255) / 256, 256>>>(Wdv, wdvp, 512, 2, 50, 512);

    ln_kernel<<<NN, 128>>>(s_j, ln_g, ln_b, x);

    dim3 gq3(12, (NN + 127) / 128);
    qkv_gemm<<<gq3, 256>>>(x, Wq, Wk, Wv, bq, bk, bv, qkv);

    edge_prep<<<(NE + 255) / 256, 256>>>(r_ij, rbf, unit);

    int mtiles = (NE + 127) / 128;   // 1954
    dim3 ge(4, mtiles);
    // dv: store half
    mma_fp16<0, 1><<<ge, 256, SMEM_SMALL>>>(rbf, wdvp, bdv, dv, 512, nullptr,
                                            nullptr, nullptr, nullptr,
                                            NE, RBFP, 2);
    // dk: fused attention-logit dot (needs qkv)
    mma_fp16<2, 1><<<ge, 256, SMEM_SMALL>>>(rbf, wdkp, bdk, nullptr, 0, nullptr,
                                            qkv, nbrs, logit,
                                            NE, RBFP, 2);

    attn_msg<<<(NE + 7) / 8, 256>>>(qkv, dv, logit, nbrs, msg);

    mma_fp16<1, 3><<<mtiles, 256, SMEM_BIG>>>(msg, wdp, bd, nullptr, 0, eout,
                                              nullptr, nullptr, nullptr,
                                              NE, 512, 16);

    gather_kernel<<<NN, 128>>>(off, eidx, nbrs, unit, v_j, eout,
                               out, out + NN * FF);
}

// round 12
// speedup vs baseline: 1.0141x; 1.0141x over previous
#include <cuda_runtime.h>
#include <cuda_fp16.h>
#include <math.h>
#include <stdint.h>

#define NN   10000
#define NE   250000
#define FF   128
#define NRBF 50
#define RBFP 64

typedef unsigned long long ull;

// ---------------- scratch ----------------
__device__ float  g_x[NN * FF];
__device__ float  g_qkv[NN * 3 * 512];
__device__ __half g_rbf[(size_t)NE * RBFP];
__device__ float  g_unit[(size_t)NE * 3];
__device__ __half g_dkdv[(size_t)NE * 1024];
__device__ __half g_msg[(size_t)NE * 512];
__device__ float  g_eout[(size_t)NE * 384];
__device__ uint32_t g_wdp[384 * 16 * 16];
__device__ uint32_t g_wdkp[512 * 2 * 16];
__device__ uint32_t g_wdvp[512 * 2 * 16];
__device__ int g_cnt[NN];
__device__ int g_off[NN + 1];
__device__ int g_pos[NN];
__device__ int g_eidx[NE];

#define FMA2(acc, a, b) asm("fma.rn.f32x2 %0, %1, %2, %0;" : "+l"(acc) : "l"(a), "l"(b))
#define PACK2(dst, f)   asm("mov.b64 %0, {%1, %1};" : "=l"(dst) : "f"(f))
#define UNPACK2(lo, hi, v) asm("mov.b64 {%0, %1}, %2;" : "=f"(lo), "=f"(hi) : "l"(v))

__device__ __forceinline__ uint32_t smem_u32(const void* p) {
    uint32_t a;
    asm("{ .reg .u64 t; cvta.to.shared.u64 t, %1; cvt.u32.u64 %0, t; }" : "=r"(a) : "l"(p));
    return a;
}
__device__ __forceinline__ float silu_f(float v) {
    return v / (1.f + __expf(-v));
}

#define MMA_F16(c, a0, a1, a2, a3, b0, b1)                                \
    asm volatile("mma.sync.aligned.m16n8k16.row.col.f32.f16.f16.f32 "     \
        "{%0,%1,%2,%3}, {%4,%5,%6,%7}, {%8,%9}, {%0,%1,%2,%3};"           \
        : "+f"((c)[0]), "+f"((c)[1]), "+f"((c)[2]), "+f"((c)[3])          \
        : "r"(a0), "r"(a1), "r"(a2), "r"(a3), "r"(b0), "r"(b1))

#define CP_ASYNC16(dst, src) \
    asm volatile("cp.async.ca.shared.global [%0], [%1], 16;" :: "r"(dst), "l"(src))
#define CP_COMMIT() asm volatile("cp.async.commit_group;" ::: "memory")
#define CP_WAIT0()  asm volatile("cp.async.wait_group 0;" ::: "memory")

// ================= CSR build =================
__global__ void zero_int(int* __restrict__ p, int n) {
    int i = blockIdx.x * blockDim.x + threadIdx.x;
    if (i < n) p[i] = 0;
}
__global__ void csr_hist(const int* __restrict__ nbrs, int* __restrict__ cnt) {
    int e = blockIdx.x * 256 + threadIdx.x;
    if (e < NE) atomicAdd(&cnt[nbrs[2 * e]], 1);
}
__global__ void __launch_bounds__(256) csr_scan(const int* __restrict__ cnt,
                                                int* __restrict__ off,
                                                int* __restrict__ pos) {
    __shared__ int base;
    __shared__ int wsum[8];
    if (threadIdx.x == 0) base = 0;
    __syncthreads();
    for (int c0 = 0; c0 < NN; c0 += 256) {
        int i = c0 + threadIdx.x;
        int v = (i < NN) ? cnt[i] : 0;
        int lane = threadIdx.x & 31, w = threadIdx.x >> 5;
        int x = v;
        #pragma unroll
        for (int o = 1; o < 32; o <<= 1) {
            int y = __shfl_up_sync(0xffffffffu, x, o);
            if (lane >= o) x += y;
        }
        if (lane == 31) wsum[w] = x;
        __syncthreads();
        int add = 0;
        #pragma unroll
        for (int k = 0; k < 8; k++) if (k < w) add += wsum[k];
        int incl = x + add;
        if (i < NN) {
            int excl = base + incl - v;
            off[i] = excl;
            pos[i] = excl;
        }
        __syncthreads();
        if (threadIdx.x == 255) base += incl;
        __syncthreads();
    }
    if (threadIdx.x == 0) off[NN] = base;
}
__global__ void csr_scatter(const int* __restrict__ nbrs, int* __restrict__ pos,
                            int* __restrict__ eidx) {
    int e = blockIdx.x * 256 + threadIdx.x;
    if (e < NE) {
        int p = atomicAdd(&pos[nbrs[2 * e]], 1);
        eidx[p] = e;
    }
}

// ================= segment-sum gather =================
__global__ void __launch_bounds__(128)
gather_kernel(const int* __restrict__ off, const int* __restrict__ eidx,
              const int* __restrict__ nbrs, const float* __restrict__ unit,
              const float* __restrict__ v_j, const float* __restrict__ eout,
              float* __restrict__ ds, float* __restrict__ dvout) {
    int i = blockIdx.x;
    int f = threadIdx.x;
    int s = off[i], t = off[i + 1];
    float a_ds = 0.f, a0 = 0.f, a1 = 0.f, a2 = 0.f;
    for (int p = s; p < t; p++) {
        int e = __ldg(eidx + p);
        int jj = __ldg(nbrs + 2 * e + 1);
        float ux = __ldg(unit + 3 * e), uy = __ldg(unit + 3 * e + 1), uz = __ldg(unit + 3 * e + 2);
        const float* o = eout + (size_t)e * 384;
        float s0 = o[f], s1 = o[128 + f], s2 = o[256 + f];
        const float* vj = v_j + ((size_t)jj * FF + f) * 3;
        a_ds += s1;
        a0 += s2 * ux + s0 * vj[0];
        a1 += s2 * uy + s0 * vj[1];
        a2 += s2 * uz + s0 * vj[2];
    }
    ds[(size_t)i * FF + f] = a_ds;
    float* dv = dvout + ((size_t)i * FF + f) * 3;
    dv[0] = a0; dv[1] = a1; dv[2] = a2;
}

// ================= B pre-permutation =================
__global__ void conv_B(const float* __restrict__ W, uint32_t* __restrict__ out,
                       int N, int nst, int Kreal, int Nld) {
    int i = blockIdx.x * 256 + threadIdx.x;
    int total = N * nst * 16;
    if (i >= total) return;
    int n = i / (nst * 16);
    int rem = i % (nst * 16);
    int s = rem >> 4, p = rem & 15;
    int bp = (p & 3) * 4 + (p >> 2);
    int k = s * 32 + bp * 2;
    float lo = (k < Kreal)     ? W[(size_t)k * Nld + n]       : 0.f;
    float hi = (k + 1 < Kreal) ? W[(size_t)(k + 1) * Nld + n] : 0.f;
    __half2 h = __floats2half2_rn(lo, hi);
    out[i] = *(uint32_t*)&h;
}

__global__ void __launch_bounds__(128) ln_kernel(const float* __restrict__ s,
                                                 const float* __restrict__ gam,
                                                 const float* __restrict__ bet,
                                                 float* __restrict__ x) {
    int n = blockIdx.x, t = threadIdx.x;
    float v = s[(size_t)n * FF + t];
    float s1 = v, s2 = v * v;
    #pragma unroll
    for (int o = 16; o; o >>= 1) {
        s1 += __shfl_down_sync(0xffffffffu, s1, o);
        s2 += __shfl_down_sync(0xffffffffu, s2, o);
    }
    __shared__ float p1[4], p2[4], mv[2];
    if ((t & 31) == 0) { p1[t >> 5] = s1; p2[t >> 5] = s2; }
    __syncthreads();
    if (t == 0) {
        float a = p1[0] + p1[1] + p1[2] + p1[3];
        float c = p2[0] + p2[1] + p2[2] + p2[3];
        float m = a / 128.f;
        mv[0] = m;
        mv[1] = rsqrtf(c / 128.f - m * m + 1e-5f);
    }
    __syncthreads();
    x[(size_t)n * FF + t] = (v - mv[0]) * mv[1] * gam[t] + bet[t];
}

__global__ void __launch_bounds__(256) edge_prep(const float* __restrict__ r,
                                                 __half* __restrict__ rbf,
                                                 float* __restrict__ unit) {
    int e = blockIdx.x * 256 + threadIdx.x;
    if (e >= NE) return;
    float x = __ldg(r + 3 * e), y = __ldg(r + 3 * e + 1), z = __ldg(r + 3 * e + 2);
    float d = sqrtf(x * x + y * y + z * z + 3e-15f);
    float inv = 1.f / d;
    unit[3 * e] = x * inv; unit[3 * e + 1] = y * inv; unit[3 * e + 2] = z * inv;
    const float width = 5.0f / 49.0f;
    const float gam = 0.5f / (width * width);
    __half2 buf[32];
    #pragma unroll
    for (int k2 = 0; k2 < 32; k2++) {
        int k0 = k2 * 2, k1 = k2 * 2 + 1;
        float d0 = d - (float)k0 * width;
        float d1 = d - (float)k1 * width;
        float v0 = (k0 < NRBF) ? __expf(-gam * d0 * d0) : 0.f;
        float v1 = (k1 < NRBF) ? __expf(-gam * d1 * d1) : 0.f;
        buf[k2] = __floats2half2_rn(v0, v1);
    }
    uint4* dst = (uint4*)(rbf + (size_t)e * RBFP);
    const uint4* src = (const uint4*)buf;
    #pragma unroll
    for (int q = 0; q < 8; q++) dst[q] = src[q];
}

// ================= qkv: fused 3-way f32x2 SGEMM =================
__global__ void __launch_bounds__(256, 2)
qkv_gemm(const float* __restrict__ Xin,
         const float* __restrict__ Wq, const float* __restrict__ Wk,
         const float* __restrict__ Wv,
         const float* __restrict__ bq, const float* __restrict__ bk,
         const float* __restrict__ bv,
         float* __restrict__ qkvout) {
    const int M = NN, N = 512, K = 128, lda = 128, ldc = 1536;
    int which = blockIdx.x >> 2;
    const float* B    = (which == 0) ? Wq : ((which == 1) ? Wk : Wv);
    const float* bias = (which == 0) ? bq : ((which == 1) ? bk : bv);
    float* C = qkvout + which * 512;
    int col0 = (blockIdx.x & 3) * 128;
    int row0 = blockIdx.y * 128;

    __shared__ float As[2][8][128];
    __shared__ float Bs[2][8][128];

    int t  = threadIdx.x;
    int ty = t >> 4, tx = t & 15;

    int arow = t >> 1;
    int acol = (t & 1) * 4;
    int am   = min(row0 + arow, M - 1);
    const float* Aptr = Xin + (size_t)am * lda + acol;

    int bk_ = t >> 5;
    int bn  = (t & 31) * 4;

    float4 ar, br;
    ar = *(const float4*)(Aptr);
    br = *(const float4*)(B + (size_t)bk_ * N + col0 + bn);

    As[0][acol + 0][arow] = ar.x;
    As[0][acol + 1][arow] = ar.y;
    As[0][acol + 2][arow] = ar.z;
    As[0][acol + 3][arow] = ar.w;
    *(float4*)&Bs[0][bk_][bn] = br;
    __syncthreads();

    ull acc[8][4];
    #pragma unroll
    for (int i = 0; i < 8; i++)
        #pragma unroll
        for (int j = 0; j < 4; j++) acc[i][j] = 0ULL;

    const int nstage = K >> 3;
    for (int s = 0; s < nstage; s++) {
        int cur = s & 1, nxt = cur ^ 1;
        bool more = (s + 1 < nstage);
        if (more) {
            int kk = (s + 1) << 3;
            ar = *(const float4*)(Aptr + kk);
            br = *(const float4*)(B + (size_t)(kk + bk_) * N + col0 + bn);
        }
        #pragma unroll
        for (int k = 0; k < 8; k++) {
            float4 a0 = *(float4*)&As[cur][k][ty * 8];
            float4 a1 = *(float4*)&As[cur][k][ty * 8 + 4];
            ulonglong2 b0 = *(ulonglong2*)&Bs[cur][k][tx * 8];
            ulonglong2 b1 = *(ulonglong2*)&Bs[cur][k][tx * 8 + 4];
            ull a2[8];
            PACK2(a2[0], a0.x); PACK2(a2[1], a0.y);
            PACK2(a2[2], a0.z); PACK2(a2[3], a0.w);
            PACK2(a2[4], a1.x); PACK2(a2[5], a1.y);
            PACK2(a2[6], a1.z); PACK2(a2[7], a1.w);
            #pragma unroll
            for (int i = 0; i < 8; i++) {
                FMA2(acc[i][0], a2[i], b0.x);
                FMA2(acc[i][1], a2[i], b0.y);
                FMA2(acc[i][2], a2[i], b1.x);
                FMA2(acc[i][3], a2[i], b1.y);
            }
        }
        if (more) {
            As[nxt][acol + 0][arow] = ar.x;
            As[nxt][acol + 1][arow] = ar.y;
            As[nxt][acol + 2][arow] = ar.z;
            As[nxt][acol + 3][arow] = ar.w;
            *(float4*)&Bs[nxt][bk_][bn] = br;
        }
        __syncthreads();
    }

    int colb = col0 + tx * 8;
    float4 bs0 = *(const float4*)(bias + colb);
    float4 bs1 = *(const float4*)(bias + colb + 4);
    #pragma unroll
    for (int i = 0; i < 8; i++) {
        int row = row0 + ty * 8 + i;
        if (row >= M) continue;
        float v[8];
        UNPACK2(v[0], v[1], acc[i][0]);
        UNPACK2(v[2], v[3], acc[i][1]);
        UNPACK2(v[4], v[5], acc[i][2]);
        UNPACK2(v[6], v[7], acc[i][3]);
        v[0] += bs0.x; v[1] += bs0.y; v[2] += bs0.z; v[3] += bs0.w;
        v[4] += bs1.x; v[5] += bs1.y; v[6] += bs1.z; v[7] += bs1.w;
        float* cp = C + (size_t)row * ldc + colb;
        *(float4*)cp       = make_float4(v[0], v[1], v[2], v[3]);
        *(float4*)(cp + 4) = make_float4(v[4], v[5], v[6], v[7]);
    }
}

// ================= attn + msg: warp-per-edge =================
__global__ void __launch_bounds__(256) attn_msg(const float* __restrict__ qkv,
                                                const __half* __restrict__ dkdv,
                                                const int* __restrict__ nbrs,
                                                __half* __restrict__ msg) {
    int e = blockIdx.x * 8 + (threadIdx.x >> 5);
    if (e >= NE) return;
    int l = threadIdx.x & 31;
    int i = __ldg(nbrs + 2 * e), j = __ldg(nbrs + 2 * e + 1);
    const float4* q4 = (const float4*)(qkv + (size_t)i * 1536);
    const float4* k4 = (const float4*)(qkv + (size_t)j * 1536 + 512);
    const float4* v4 = (const float4*)(qkv + (size_t)j * 1536 + 1024);
    const uint2* dk2 = (const uint2*)(dkdv + (size_t)e * 1024);
    const uint2* dv2 = dk2 + 128;

    float4 qv[4], kv[4], vv[4];
    uint2 dkv[4], dvv[4];
    #pragma unroll
    for (int h = 0; h < 4; h++) {
        int idx = h * 32 + l;
        qv[h] = q4[idx]; kv[h] = k4[idx]; vv[h] = v4[idx];
        dkv[h] = dk2[idx]; dvv[h] = dv2[idx];
    }
    float p[4];
    #pragma unroll
    for (int h = 0; h < 4; h++) {
        float2 f0 = __half22float2(*(__half2*)&dkv[h].x);
        float2 f1 = __half22float2(*(__half2*)&dkv[h].y);
        p[h] = qv[h].x * kv[h].x * f0.x + qv[h].y * kv[h].y * f0.y
             + qv[h].z * kv[h].z * f1.x + qv[h].w * kv[h].w * f1.y;
    }
    #pragma unroll
    for (int o = 16; o; o >>= 1)
        #pragma unroll
        for (int h = 0; h < 4; h++) p[h] += __shfl_xor_sync(0xffffffffu, p[h], o);

    __half* mrow = msg + (size_t)e * 512;
    #pragma unroll
    for (int h = 0; h < 4; h++) {
        float at = silu_f(p[h]);
        float2 g0 = __half22float2(*(__half2*)&dvv[h].x);
        float2 g1 = __half22float2(*(__half2*)&dvv[h].y);
        __half2 m0 = __floats2half2_rn(vv[h].x * g0.x * at, vv[h].y * g0.y * at);
        __half2 m1 = __floats2half2_rn(vv[h].z * g1.x * at, vv[h].w * g1.y * at);
        uint2 o2;
        o2.x = *(uint32_t*)&m0;
        o2.y = *(uint32_t*)&m1;
        *(uint2*)(mrow + h * 128 + l * 4) = o2;
    }
}

// ================= fp16 mma GEMM (128x128 tile, 2 CTAs/SM) =================
// EPI=0: dk/dv — silu + half store to C at cols n0s.
// EPI=1: big GEMM slice — biased float store to eout at cols n0s.
#define SROWU 20
#define ABUFU (128 * SROWU)

template <int EPI>
__global__ void __launch_bounds__(256, 2)
mma_fp16(const __half* __restrict__ A, const uint32_t* __restrict__ Bp,
         const float* __restrict__ bias, __half* __restrict__ C, int ldc,
         float* __restrict__ eout,
         int M, int lda, int nstage) {
    extern __shared__ uint32_t sm[];
    const uint32_t sA = smem_u32(sm);
    const uint32_t sB0 = sA + 2 * ABUFU * 4;

    const int tid = threadIdx.x;
    const int wid = tid >> 5, lid = tid & 31;
    const int gq = lid >> 2, tig = lid & 3;
    const int wM = wid >> 1, wN = wid & 1;
    const int row0 = blockIdx.y * 128;
    const int n0s  = blockIdx.x * 128;

    float acc[2][8][4];
    #pragma unroll
    for (int a = 0; a < 2; a++)
        #pragma unroll
        for (int b = 0; b < 8; b++)
            #pragma unroll
            for (int c = 0; c < 4; c++) acc[a][b][c] = 0.f;

    const int arow = tid >> 1, ac2 = (tid & 1) * 2;
    const __half* aRow = A + (size_t)min(row0 + arow, M - 1) * lda;

    auto stage_A = [&](int s, int buf) {
        const __half* src = aRow + s * 32 + ac2 * 8;
        uint32_t dst = sA + (buf * ABUFU + arow * SROWU + ac2 * 4) * 4;
        CP_ASYNC16(dst, src);
        CP_ASYNC16(dst + 16, src + 8);
    };

    auto stage_B = [&](int s, int buf) {
        #pragma unroll
        for (int i = 0; i < 2; i++) {
            int c = tid + i * 256;            // 0..511
            int n = c >> 2, q = c & 3;
            int ng = n0s + n;
            const uint32_t* src = Bp + ((size_t)ng * nstage + s) * 16 + q * 4;
            uint32_t dst = sB0 + (buf * ABUFU + n * SROWU + q * 4) * 4;
            CP_ASYNC16(dst, src);
        }
    };

    stage_A(0, 0);
    stage_B(0, 0);
    CP_COMMIT();
    CP_WAIT0();
    __syncthreads();

    for (int s = 0; s < nstage; s++) {
        int cur = s & 1;
        bool more = (s + 1 < nstage);
        if (more) {
            stage_A(s + 1, cur ^ 1);
            stage_B(s + 1, cur ^ 1);
            CP_COMMIT();
        }

        uint32_t af[2][2][4];
        const uint32_t* Ab = sm + cur * ABUFU;
        #pragma unroll
        for (int mf = 0; mf < 2; mf++) {
            int r0 = wM * 32 + mf * 16 + gq;
            const uint32_t* p0 = Ab + r0 * SROWU;
            const uint32_t* p1 = Ab + (r0 + 8) * SROWU;
            #pragma unroll
            for (int ks = 0; ks < 2; ks++) {
                af[mf][ks][0] = p0[tig + 8 * ks];
                af[mf][ks][1] = p1[tig + 8 * ks];
                af[mf][ks][2] = p0[tig + 4 + 8 * ks];
                af[mf][ks][3] = p1[tig + 4 + 8 * ks];
            }
        }
        const uint32_t* Bb = sm + 2 * ABUFU + cur * ABUFU;
        #pragma unroll
        for (int nf = 0; nf < 8; nf++) {
            int n = wN * 64 + nf * 8 + gq;
            uint4 bv = *(const uint4*)(Bb + n * SROWU + tig * 4);
            MMA_F16(acc[0][nf], af[0][0][0], af[0][0][1], af[0][0][2], af[0][0][3], bv.x, bv.y);
            MMA_F16(acc[1][nf], af[1][0][0], af[1][0][1], af[1][0][2], af[1][0][3], bv.x, bv.y);
            MMA_F16(acc[0][nf], af[0][1][0], af[0][1][1], af[0][1][2], af[0][1][3], bv.z, bv.w);
            MMA_F16(acc[1][nf], af[1][1][0], af[1][1][1], af[1][1][2], af[1][1][3], bv.z, bv.w);
        }
        if (more) CP_WAIT0();
        __syncthreads();
    }

    if constexpr (EPI == 0) {
        #pragma unroll
        for (int mf = 0; mf < 2; mf++)
        #pragma unroll
        for (int rs = 0; rs < 2; rs++) {
            int r = row0 + wM * 32 + mf * 16 + rs * 8 + gq;
            if (r >= M) continue;
            #pragma unroll
            for (int nf = 0; nf < 8; nf++) {
                int nc = wN * 64 + nf * 8 + tig * 2;
                float v0 = silu_f(acc[mf][nf][rs * 2 + 0] + __ldg(bias + n0s + nc));
                float v1 = silu_f(acc[mf][nf][rs * 2 + 1] + __ldg(bias + n0s + nc + 1));
                *(__half2*)(C + (size_t)r * ldc + n0s + nc) = __floats2half2_rn(v0, v1);
            }
        }
    } else {
        #pragma unroll
        for (int mf = 0; mf < 2; mf++)
        #pragma unroll
        for (int rs = 0; rs < 2; rs++) {
            int e = row0 + wM * 32 + mf * 16 + rs * 8 + gq;
            if (e >= M) continue;
            float* o = eout + (size_t)e * 384 + n0s;
            #pragma unroll
            for (int nf = 0; nf < 8; nf++) {
                int f = wN * 64 + nf * 8 + tig * 2;
                float v0 = acc[mf][nf][rs * 2 + 0] + __ldg(bias + n0s + f);
                float v1 = acc[mf][nf][rs * 2 + 1] + __ldg(bias + n0s + f + 1);
                *(float2*)(o + f) = make_float2(v0, v1);
            }
        }
    }
}

// ================= launch =================
extern "C" void kernel_launch(void* const* d_in, const int* in_sizes, int n_in,
                              void* d_out, int out_size) {
    const float* s_j  = (const float*)d_in[0];
    const float* v_j  = (const float*)d_in[1];
    const float* r_ij = (const float*)d_in[2];
    const int*   nbrs = (const int*)  d_in[3];
    const float* ln_g = (const float*)d_in[4];
    const float* ln_b = (const float*)d_in[5];
    const float* Wq   = (const float*)d_in[6];
    const float* bq   = (const float*)d_in[7];
    const float* Wk   = (const float*)d_in[8];
    const float* bk   = (const float*)d_in[9];
    const float* Wv   = (const float*)d_in[10];
    const float* bv   = (const float*)d_in[11];
    const float* Wdk  = (const float*)d_in[12];
    const float* bdk  = (const float*)d_in[13];
    const float* Wdv  = (const float*)d_in[14];
    const float* bdv  = (const float*)d_in[15];
    const float* Wd   = (const float*)d_in[16];
    const float* bd   = (const float*)d_in[17];
    float* out = (float*)d_out;

    float *x, *qkv, *unit, *eout;
    __half *rbf, *dkdv, *msg;
    uint32_t *wdp, *wdkp, *wdvp;
    int *cnt, *off, *pos, *eidx;
    cudaGetSymbolAddress((void**)&x,    g_x);
    cudaGetSymbolAddress((void**)&qkv,  g_qkv);
    cudaGetSymbolAddress((void**)&rbf,  g_rbf);
    cudaGetSymbolAddress((void**)&unit, g_unit);
    cudaGetSymbolAddress((void**)&dkdv, g_dkdv);
    cudaGetSymbolAddress((void**)&msg,  g_msg);
    cudaGetSymbolAddress((void**)&eout, g_eout);
    cudaGetSymbolAddress((void**)&wdp,  g_wdp);
    cudaGetSymbolAddress((void**)&wdkp, g_wdkp);
    cudaGetSymbolAddress((void**)&wdvp, g_wdvp);
    cudaGetSymbolAddress((void**)&cnt,  g_cnt);
    cudaGetSymbolAddress((void**)&off,  g_off);
    cudaGetSymbolAddress((void**)&pos,  g_pos);
    cudaGetSymbolAddress((void**)&eidx, g_eidx);

    const int SMEM_MMA = 4 * ABUFU * 4;   // 40960
    cudaFuncSetAttribute(mma_fp16<0>, cudaFuncAttributeMaxDynamicSharedMemorySize, SMEM_MMA);
    cudaFuncSetAttribute(mma_fp16<1>, cudaFuncAttributeMaxDynamicSharedMemorySize, SMEM_MMA);

    // CSR build (independent of GEMM chain)
    zero_int<<<(NN + 255) / 256, 256>>>(cnt, NN);
    csr_hist<<<(NE + 255) / 256, 256>>>(nbrs, cnt);
    csr_scan<<<1, 256>>>(cnt, off, pos);
    csr_scatter<<<(NE + 255) / 256, 256>>>(nbrs, pos, eidx);

    // weight pre-permutation
    conv_B<<<(384 * 16 * 16 + 255) / 256, 256>>>(Wd,  wdp,  384, 16, 512, 384);
    conv_B<<<(512 * 2 * 16 + 255) / 256, 256>>>(Wdk, wdkp, 512, 2, 50, 512);
    conv_B<<<(512 * 2 * 16 + 255) / 256, 256>>>(Wdv, wdvp, 512, 2, 50, 512);

    ln_kernel<<<NN, 128>>>(s_j, ln_g, ln_b, x);

    dim3 gq3(12, (NN + 127) / 128);
    qkv_gemm<<<gq3, 256>>>(x, Wq, Wk, Wv, bq, bk, bv, qkv);

    edge_prep<<<(NE + 255) / 256, 256>>>(r_ij, rbf, unit);

    int mtiles = (NE + 127) / 128;   // 1954
    dim3 ge(4, mtiles);
    mma_fp16<0><<<ge, 256, SMEM_MMA>>>(rbf, wdkp, bdk, dkdv, 1024, nullptr,
                                       NE, RBFP, 2);
    mma_fp16<0><<<ge, 256, SMEM_MMA>>>(rbf, wdvp, bdv, dkdv + 512, 1024, nullptr,
                                       NE, RBFP, 2);

    attn_msg<<<(NE + 7) / 8, 256>>>(qkv, dkdv, nbrs, msg);

    dim3 gb(3, mtiles);
    mma_fp16<1><<<gb, 256, SMEM_MMA>>>(msg, wdp, bd, nullptr, 0, eout,
                                       NE, 512, 16);

    gather_kernel<<<NN, 128>>>(off, eidx, nbrs, unit, v_j, eout,
                               out, out + NN * FF);
}

// round 13
// speedup vs baseline: 1.0748x; 1.0599x over previous
#include <cuda_runtime.h>
#include <cuda_fp16.h>
#include <math.h>
#include <stdint.h>

#define NN   10000
#define NE   250000
#define FF   128
#define NRBF 50
#define RBFP 64

typedef unsigned long long ull;

// ---------------- scratch ----------------
__device__ float  g_x[NN * FF];
__device__ float  g_qkv[NN * 3 * 512];
__device__ __half g_rbf[(size_t)NE * RBFP];
__device__ float  g_unit[(size_t)NE * 3];
__device__ __half g_dkdv[(size_t)NE * 1024];
__device__ __half g_msg[(size_t)NE * 512];
__device__ float  g_eout[(size_t)NE * 256];     // per-edge s0|s2 (biased)
__device__ float  g_ms[(size_t)NN * 512];       // segment-summed msg
__device__ uint32_t g_wdp[256 * 16 * 16];       // Wd cols 0-127 & 256-383
__device__ uint32_t g_wdkp[512 * 2 * 16];
__device__ uint32_t g_wdvp[512 * 2 * 16];
__device__ int g_cnt[NN];
__device__ int g_off[NN + 1];
__device__ int g_pos[NN];
__device__ int g_eidx[NE];

#define FMA2(acc, a, b) asm("fma.rn.f32x2 %0, %1, %2, %0;" : "+l"(acc) : "l"(a), "l"(b))
#define PACK2(dst, f)   asm("mov.b64 %0, {%1, %1};" : "=l"(dst) : "f"(f))
#define UNPACK2(lo, hi, v) asm("mov.b64 {%0, %1}, %2;" : "=f"(lo), "=f"(hi) : "l"(v))

__device__ __forceinline__ uint32_t smem_u32(const void* p) {
    uint32_t a;
    asm("{ .reg .u64 t; cvta.to.shared.u64 t, %1; cvt.u32.u64 %0, t; }" : "=r"(a) : "l"(p));
    return a;
}
__device__ __forceinline__ float silu_f(float v) {
    return v / (1.f + __expf(-v));
}

#define MMA_F16(c, a0, a1, a2, a3, b0, b1)                                \
    asm volatile("mma.sync.aligned.m16n8k16.row.col.f32.f16.f16.f32 "     \
        "{%0,%1,%2,%3}, {%4,%5,%6,%7}, {%8,%9}, {%0,%1,%2,%3};"           \
        : "+f"((c)[0]), "+f"((c)[1]), "+f"((c)[2]), "+f"((c)[3])          \
        : "r"(a0), "r"(a1), "r"(a2), "r"(a3), "r"(b0), "r"(b1))

#define CP_ASYNC16(dst, src) \
    asm volatile("cp.async.ca.shared.global [%0], [%1], 16;" :: "r"(dst), "l"(src))
#define CP_COMMIT() asm volatile("cp.async.commit_group;" ::: "memory")
#define CP_WAIT0()  asm volatile("cp.async.wait_group 0;" ::: "memory")

// ================= CSR build =================
__global__ void zero_int(int* __restrict__ p, int n) {
    int i = blockIdx.x * blockDim.x + threadIdx.x;
    if (i < n) p[i] = 0;
}
__global__ void csr_hist(const int* __restrict__ nbrs, int* __restrict__ cnt) {
    int e = blockIdx.x * 256 + threadIdx.x;
    if (e < NE) atomicAdd(&cnt[nbrs[2 * e]], 1);
}
__global__ void __launch_bounds__(256) csr_scan(const int* __restrict__ cnt,
                                                int* __restrict__ off,
                                                int* __restrict__ pos) {
    __shared__ int base;
    __shared__ int wsum[8];
    if (threadIdx.x == 0) base = 0;
    __syncthreads();
    for (int c0 = 0; c0 < NN; c0 += 256) {
        int i = c0 + threadIdx.x;
        int v = (i < NN) ? cnt[i] : 0;
        int lane = threadIdx.x & 31, w = threadIdx.x >> 5;
        int x = v;
        #pragma unroll
        for (int o = 1; o < 32; o <<= 1) {
            int y = __shfl_up_sync(0xffffffffu, x, o);
            if (lane >= o) x += y;
        }
        if (lane == 31) wsum[w] = x;
        __syncthreads();
        int add = 0;
        #pragma unroll
        for (int k = 0; k < 8; k++) if (k < w) add += wsum[k];
        int incl = x + add;
        if (i < NN) {
            int excl = base + incl - v;
            off[i] = excl;
            pos[i] = excl;
        }
        __syncthreads();
        if (threadIdx.x == 255) base += incl;
        __syncthreads();
    }
    if (threadIdx.x == 0) off[NN] = base;
}
__global__ void csr_scatter(const int* __restrict__ nbrs, int* __restrict__ pos,
                            int* __restrict__ eidx) {
    int e = blockIdx.x * 256 + threadIdx.x;
    if (e < NE) {
        int p = atomicAdd(&pos[nbrs[2 * e]], 1);
        eidx[p] = e;
    }
}

// ================= msg segment-sum (for ds path) =================
__global__ void __launch_bounds__(128)
msg_segsum(const int* __restrict__ off, const int* __restrict__ eidx,
           const __half* __restrict__ msg, float* __restrict__ ms) {
    int i = blockIdx.x;
    int t = threadIdx.x;
    int s = off[i], tend = off[i + 1];
    float a0 = 0.f, a1 = 0.f, a2 = 0.f, a3 = 0.f;
    for (int p = s; p < tend; p++) {
        int e = __ldg(eidx + p);
        uint2 m = *(const uint2*)(msg + (size_t)e * 512 + t * 4);
        float2 x0 = __half22float2(*(__half2*)&m.x);
        float2 x1 = __half22float2(*(__half2*)&m.y);
        a0 += x0.x; a1 += x0.y; a2 += x1.x; a3 += x1.y;
    }
    *(float4*)(ms + (size_t)i * 512 + t * 4) = make_float4(a0, a1, a2, a3);
}

// ================= ds GEMM: ds = ms @ Wd[:,128:256] + deg*bd1 =================
__global__ void __launch_bounds__(256, 2)
ds_gemm(const float* __restrict__ ms, const float* __restrict__ Wd1,
        const float* __restrict__ bias, const int* __restrict__ off,
        float* __restrict__ ds) {
    const int M = NN, K = 512;
    int row0 = blockIdx.y * 128;

    __shared__ float As[2][8][128];
    __shared__ float Bs[2][8][128];

    int t  = threadIdx.x;
    int ty = t >> 4, tx = t & 15;

    int arow = t >> 1;
    int acol = (t & 1) * 4;
    int am   = min(row0 + arow, M - 1);
    const float* Aptr = ms + (size_t)am * K + acol;

    int bk_ = t >> 5;
    int bn  = (t & 31) * 4;

    float4 ar, br;
    ar = *(const float4*)(Aptr);
    br = *(const float4*)(Wd1 + (size_t)bk_ * 384 + bn);

    As[0][acol + 0][arow] = ar.x;
    As[0][acol + 1][arow] = ar.y;
    As[0][acol + 2][arow] = ar.z;
    As[0][acol + 3][arow] = ar.w;
    *(float4*)&Bs[0][bk_][bn] = br;
    __syncthreads();

    ull acc[8][4];
    #pragma unroll
    for (int i = 0; i < 8; i++)
        #pragma unroll
        for (int j = 0; j < 4; j++) acc[i][j] = 0ULL;

    const int nstage = K >> 3;
    for (int s = 0; s < nstage; s++) {
        int cur = s & 1, nxt = cur ^ 1;
        bool more = (s + 1 < nstage);
        if (more) {
            int kk = (s + 1) << 3;
            ar = *(const float4*)(Aptr + kk);
            br = *(const float4*)(Wd1 + (size_t)(kk + bk_) * 384 + bn);
        }
        #pragma unroll
        for (int k = 0; k < 8; k++) {
            float4 a0 = *(float4*)&As[cur][k][ty * 8];
            float4 a1 = *(float4*)&As[cur][k][ty * 8 + 4];
            ulonglong2 b0 = *(ulonglong2*)&Bs[cur][k][tx * 8];
            ulonglong2 b1 = *(ulonglong2*)&Bs[cur][k][tx * 8 + 4];
            ull a2[8];
            PACK2(a2[0], a0.x); PACK2(a2[1], a0.y);
            PACK2(a2[2], a0.z); PACK2(a2[3], a0.w);
            PACK2(a2[4], a1.x); PACK2(a2[5], a1.y);
            PACK2(a2[6], a1.z); PACK2(a2[7], a1.w);
            #pragma unroll
            for (int i = 0; i < 8; i++) {
                FMA2(acc[i][0], a2[i], b0.x);
                FMA2(acc[i][1], a2[i], b0.y);
                FMA2(acc[i][2], a2[i], b1.x);
                FMA2(acc[i][3], a2[i], b1.y);
            }
        }
        if (more) {
            As[nxt][acol + 0][arow] = ar.x;
            As[nxt][acol + 1][arow] = ar.y;
            As[nxt][acol + 2][arow] = ar.z;
            As[nxt][acol + 3][arow] = ar.w;
            *(float4*)&Bs[nxt][bk_][bn] = br;
        }
        __syncthreads();
    }

    int colb = tx * 8;
    float4 bs0 = *(const float4*)(bias + colb);
    float4 bs1 = *(const float4*)(bias + colb + 4);
    #pragma unroll
    for (int i = 0; i < 8; i++) {
        int row = row0 + ty * 8 + i;
        if (row >= M) continue;
        float deg = (float)(__ldg(off + row + 1) - __ldg(off + row));
        float v[8];
        UNPACK2(v[0], v[1], acc[i][0]);
        UNPACK2(v[2], v[3], acc[i][1]);
        UNPACK2(v[4], v[5], acc[i][2]);
        UNPACK2(v[6], v[7], acc[i][3]);
        v[0] += deg * bs0.x; v[1] += deg * bs0.y; v[2] += deg * bs0.z; v[3] += deg * bs0.w;
        v[4] += deg * bs1.x; v[5] += deg * bs1.y; v[6] += deg * bs1.z; v[7] += deg * bs1.w;
        float* cp = ds + (size_t)row * 128 + colb;
        *(float4*)cp       = make_float4(v[0], v[1], v[2], v[3]);
        *(float4*)(cp + 4) = make_float4(v[4], v[5], v[6], v[7]);
    }
}

// ================= dv gather (no ds) =================
__global__ void __launch_bounds__(128)
gather_kernel(const int* __restrict__ off, const int* __restrict__ eidx,
              const int* __restrict__ nbrs, const float* __restrict__ unit,
              const float* __restrict__ v_j, const float* __restrict__ eout,
              float* __restrict__ dvout) {
    int i = blockIdx.x;
    int f = threadIdx.x;
    int s = off[i], t = off[i + 1];
    float a0 = 0.f, a1 = 0.f, a2 = 0.f;
    for (int p = s; p < t; p++) {
        int e = __ldg(eidx + p);
        int jj = __ldg(nbrs + 2 * e + 1);
        float ux = __ldg(unit + 3 * e), uy = __ldg(unit + 3 * e + 1), uz = __ldg(unit + 3 * e + 2);
        const float* o = eout + (size_t)e * 256;
        float s0 = o[f], s2 = o[128 + f];
        const float* vj = v_j + ((size_t)jj * FF + f) * 3;
        a0 += s2 * ux + s0 * vj[0];
        a1 += s2 * uy + s0 * vj[1];
        a2 += s2 * uz + s0 * vj[2];
    }
    float* dv = dvout + ((size_t)i * FF + f) * 3;
    dv[0] = a0; dv[1] = a1; dv[2] = a2;
}

// ================= B pre-permutation =================
__global__ void conv_B(const float* __restrict__ W, uint32_t* __restrict__ out,
                       int N, int nst, int Kreal, int Nld) {
    int i = blockIdx.x * 256 + threadIdx.x;
    int total = N * nst * 16;
    if (i >= total) return;
    int n = i / (nst * 16);
    int rem = i % (nst * 16);
    int s = rem >> 4, p = rem & 15;
    int bp = (p & 3) * 4 + (p >> 2);
    int k = s * 32 + bp * 2;
    float lo = (k < Kreal)     ? W[(size_t)k * Nld + n]       : 0.f;
    float hi = (k + 1 < Kreal) ? W[(size_t)(k + 1) * Nld + n] : 0.f;
    __half2 h = __floats2half2_rn(lo, hi);
    out[i] = *(uint32_t*)&h;
}

__global__ void __launch_bounds__(128) ln_kernel(const float* __restrict__ s,
                                                 const float* __restrict__ gam,
                                                 const float* __restrict__ bet,
                                                 float* __restrict__ x) {
    int n = blockIdx.x, t = threadIdx.x;
    float v = s[(size_t)n * FF + t];
    float s1 = v, s2 = v * v;
    #pragma unroll
    for (int o = 16; o; o >>= 1) {
        s1 += __shfl_down_sync(0xffffffffu, s1, o);
        s2 += __shfl_down_sync(0xffffffffu, s2, o);
    }
    __shared__ float p1[4], p2[4], mv[2];
    if ((t & 31) == 0) { p1[t >> 5] = s1; p2[t >> 5] = s2; }
    __syncthreads();
    if (t == 0) {
        float a = p1[0] + p1[1] + p1[2] + p1[3];
        float c = p2[0] + p2[1] + p2[2] + p2[3];
        float m = a / 128.f;
        mv[0] = m;
        mv[1] = rsqrtf(c / 128.f - m * m + 1e-5f);
    }
    __syncthreads();
    x[(size_t)n * FF + t] = (v - mv[0]) * mv[1] * gam[t] + bet[t];
}

__global__ void __launch_bounds__(256) edge_prep(const float* __restrict__ r,
                                                 __half* __restrict__ rbf,
                                                 float* __restrict__ unit) {
    int e = blockIdx.x * 256 + threadIdx.x;
    if (e >= NE) return;
    float x = __ldg(r + 3 * e), y = __ldg(r + 3 * e + 1), z = __ldg(r + 3 * e + 2);
    float d = sqrtf(x * x + y * y + z * z + 3e-15f);
    float inv = 1.f / d;
    unit[3 * e] = x * inv; unit[3 * e + 1] = y * inv; unit[3 * e + 2] = z * inv;
    const float width = 5.0f / 49.0f;
    const float gam = 0.5f / (width * width);
    __half2 buf[32];
    #pragma unroll
    for (int k2 = 0; k2 < 32; k2++) {
        int k0 = k2 * 2, k1 = k2 * 2 + 1;
        float d0 = d - (float)k0 * width;
        float d1 = d - (float)k1 * width;
        float v0 = (k0 < NRBF) ? __expf(-gam * d0 * d0) : 0.f;
        float v1 = (k1 < NRBF) ? __expf(-gam * d1 * d1) : 0.f;
        buf[k2] = __floats2half2_rn(v0, v1);
    }
    uint4* dst = (uint4*)(rbf + (size_t)e * RBFP);
    const uint4* src = (const uint4*)buf;
    #pragma unroll
    for (int q = 0; q < 8; q++) dst[q] = src[q];
}

// ================= qkv: fused 3-way f32x2 SGEMM =================
__global__ void __launch_bounds__(256, 2)
qkv_gemm(const float* __restrict__ Xin,
         const float* __restrict__ Wq, const float* __restrict__ Wk,
         const float* __restrict__ Wv,
         const float* __restrict__ bq, const float* __restrict__ bk,
         const float* __restrict__ bv,
         float* __restrict__ qkvout) {
    const int M = NN, N = 512, K = 128, lda = 128, ldc = 1536;
    int which = blockIdx.x >> 2;
    const float* B    = (which == 0) ? Wq : ((which == 1) ? Wk : Wv);
    const float* bias = (which == 0) ? bq : ((which == 1) ? bk : bv);
    float* C = qkvout + which * 512;
    int col0 = (blockIdx.x & 3) * 128;
    int row0 = blockIdx.y * 128;

    __shared__ float As[2][8][128];
    __shared__ float Bs[2][8][128];

    int t  = threadIdx.x;
    int ty = t >> 4, tx = t & 15;

    int arow = t >> 1;
    int acol = (t & 1) * 4;
    int am   = min(row0 + arow, M - 1);
    const float* Aptr = Xin + (size_t)am * lda + acol;

    int bk_ = t >> 5;
    int bn  = (t & 31) * 4;

    float4 ar, br;
    ar = *(const float4*)(Aptr);
    br = *(const float4*)(B + (size_t)bk_ * N + col0 + bn);

    As[0][acol + 0][arow] = ar.x;
    As[0][acol + 1][arow] = ar.y;
    As[0][acol + 2][arow] = ar.z;
    As[0][acol + 3][arow] = ar.w;
    *(float4*)&Bs[0][bk_][bn] = br;
    __syncthreads();

    ull acc[8][4];
    #pragma unroll
    for (int i = 0; i < 8; i++)
        #pragma unroll
        for (int j = 0; j < 4; j++) acc[i][j] = 0ULL;

    const int nstage = K >> 3;
    for (int s = 0; s < nstage; s++) {
        int cur = s & 1, nxt = cur ^ 1;
        bool more = (s + 1 < nstage);
        if (more) {
            int kk = (s + 1) << 3;
            ar = *(const float4*)(Aptr + kk);
            br = *(const float4*)(B + (size_t)(kk + bk_) * N + col0 + bn);
        }
        #pragma unroll
        for (int k = 0; k < 8; k++) {
            float4 a0 = *(float4*)&As[cur][k][ty * 8];
            float4 a1 = *(float4*)&As[cur][k][ty * 8 + 4];
            ulonglong2 b0 = *(ulonglong2*)&Bs[cur][k][tx * 8];
            ulonglong2 b1 = *(ulonglong2*)&Bs[cur][k][tx * 8 + 4];
            ull a2[8];
            PACK2(a2[0], a0.x); PACK2(a2[1], a0.y);
            PACK2(a2[2], a0.z); PACK2(a2[3], a0.w);
            PACK2(a2[4], a1.x); PACK2(a2[5], a1.y);
            PACK2(a2[6], a1.z); PACK2(a2[7], a1.w);
            #pragma unroll
            for (int i = 0; i < 8; i++) {
                FMA2(acc[i][0], a2[i], b0.x);
                FMA2(acc[i][1], a2[i], b0.y);
                FMA2(acc[i][2], a2[i], b1.x);
                FMA2(acc[i][3], a2[i], b1.y);
            }
        }
        if (more) {
            As[nxt][acol + 0][arow] = ar.x;
            As[nxt][acol + 1][arow] = ar.y;
            As[nxt][acol + 2][arow] = ar.z;
            As[nxt][acol + 3][arow] = ar.w;
            *(float4*)&Bs[nxt][bk_][bn] = br;
        }
        __syncthreads();
    }

    int colb = col0 + tx * 8;
    float4 bs0 = *(const float4*)(bias + colb);
    float4 bs1 = *(const float4*)(bias + colb + 4);
    #pragma unroll
    for (int i = 0; i < 8; i++) {
        int row = row0 + ty * 8 + i;
        if (row >= M) continue;
        float v[8];
        UNPACK2(v[0], v[1], acc[i][0]);
        UNPACK2(v[2], v[3], acc[i][1]);
        UNPACK2(v[4], v[5], acc[i][2]);
        UNPACK2(v[6], v[7], acc[i][3]);
        v[0] += bs0.x; v[1] += bs0.y; v[2] += bs0.z; v[3] += bs0.w;
        v[4] += bs1.x; v[5] += bs1.y; v[6] += bs1.z; v[7] += bs1.w;
        float* cp = C + (size_t)row * ldc + colb;
        *(float4*)cp       = make_float4(v[0], v[1], v[2], v[3]);
        *(float4*)(cp + 4) = make_float4(v[4], v[5], v[6], v[7]);
    }
}

// ================= attn + msg: warp-per-edge =================
__global__ void __launch_bounds__(256) attn_msg(const float* __restrict__ qkv,
                                                const __half* __restrict__ dkdv,
                                                const int* __restrict__ nbrs,
                                                __half* __restrict__ msg) {
    int e = blockIdx.x * 8 + (threadIdx.x >> 5);
    if (e >= NE) return;
    int l = threadIdx.x & 31;
    int i = __ldg(nbrs + 2 * e), j = __ldg(nbrs + 2 * e + 1);
    const float4* q4 = (const float4*)(qkv + (size_t)i * 1536);
    const float4* k4 = (const float4*)(qkv + (size_t)j * 1536 + 512);
    const float4* v4 = (const float4*)(qkv + (size_t)j * 1536 + 1024);
    const uint2* dk2 = (const uint2*)(dkdv + (size_t)e * 1024);
    const uint2* dv2 = dk2 + 128;

    float4 qv[4], kv[4], vv[4];
    uint2 dkv[4], dvv[4];
    #pragma unroll
    for (int h = 0; h < 4; h++) {
        int idx = h * 32 + l;
        qv[h] = q4[idx]; kv[h] = k4[idx]; vv[h] = v4[idx];
        dkv[h] = dk2[idx]; dvv[h] = dv2[idx];
    }
    float p[4];
    #pragma unroll
    for (int h = 0; h < 4; h++) {
        float2 f0 = __half22float2(*(__half2*)&dkv[h].x);
        float2 f1 = __half22float2(*(__half2*)&dkv[h].y);
        p[h] = qv[h].x * kv[h].x * f0.x + qv[h].y * kv[h].y * f0.y
             + qv[h].z * kv[h].z * f1.x + qv[h].w * kv[h].w * f1.y;
    }
    #pragma unroll
    for (int o = 16; o; o >>= 1)
        #pragma unroll
        for (int h = 0; h < 4; h++) p[h] += __shfl_xor_sync(0xffffffffu, p[h], o);

    __half* mrow = msg + (size_t)e * 512;
    #pragma unroll
    for (int h = 0; h < 4; h++) {
        float at = silu_f(p[h]);
        float2 g0 = __half22float2(*(__half2*)&dvv[h].x);
        float2 g1 = __half22float2(*(__half2*)&dvv[h].y);
        __half2 m0 = __floats2half2_rn(vv[h].x * g0.x * at, vv[h].y * g0.y * at);
        __half2 m1 = __floats2half2_rn(vv[h].z * g1.x * at, vv[h].w * g1.y * at);
        uint2 o2;
        o2.x = *(uint32_t*)&m0;
        o2.y = *(uint32_t*)&m1;
        *(uint2*)(mrow + h * 128 + l * 4) = o2;
    }
}

// ================= fp16 mma GEMM (r10 structure) =================
// EPI=0: dk/dv — silu + half store to C at cols n0s.
// EPI=1: big GEMM — NSLICE=2 (s0, s2), biased float store to eout (stride 256).
#define SROWU 20
#define ABUFU (128 * SROWU)

template <int EPI, int NSLICE>
__global__ void __launch_bounds__(256)
mma_fp16(const __half* __restrict__ A, const uint32_t* __restrict__ Bp,
         const float* __restrict__ bias, __half* __restrict__ C, int ldc,
         float* __restrict__ eout,
         int M, int lda, int nstage) {
    extern __shared__ uint32_t sm[];
    const uint32_t sA = smem_u32(sm);
    const uint32_t sB0 = sA + 2 * ABUFU * 4;

    const int tid = threadIdx.x;
    const int wid = tid >> 5, lid = tid & 31;
    const int gq = lid >> 2, tig = lid & 3;
    const int wM = wid >> 1, wN = wid & 1;
    const int row0 = (EPI == 1 ? blockIdx.x : blockIdx.y) * 128;
    const int n0s  = (EPI == 1 ? 0 : blockIdx.x * 128);

    float acc[NSLICE][2][8][4];
    #pragma unroll
    for (int s = 0; s < NSLICE; s++)
        #pragma unroll
        for (int a = 0; a < 2; a++)
            #pragma unroll
            for (int b = 0; b < 8; b++)
                #pragma unroll
                for (int c = 0; c < 4; c++) acc[s][a][b][c] = 0.f;

    const int arow = tid >> 1, ac2 = (tid & 1) * 2;
    const __half* aRow = A + (size_t)min(row0 + arow, M - 1) * lda;

    auto stage_A = [&](int s, int buf) {
        const __half* src = aRow + s * 32 + ac2 * 8;
        uint32_t dst = sA + (buf * ABUFU + arow * SROWU + ac2 * 4) * 4;
        CP_ASYNC16(dst, src);
        CP_ASYNC16(dst + 16, src + 8);
    };

    auto stage_B = [&](int s, int buf) {
        #pragma unroll
        for (int i = 0; i < NSLICE * 2; i++) {
            int cid = tid + i * 256;
            int sl = cid >> 9;
            int c  = cid & 511;
            int n = c >> 2, q = c & 3;
            int ng = (EPI == 1 ? sl * 128 : n0s) + n;
            const uint32_t* src = Bp + ((size_t)ng * nstage + s) * 16 + q * 4;
            uint32_t dst = sB0 + ((sl * 2 + buf) * ABUFU + n * SROWU + q * 4) * 4;
            CP_ASYNC16(dst, src);
        }
    };

    stage_A(0, 0);
    stage_B(0, 0);
    CP_COMMIT();
    CP_WAIT0();
    __syncthreads();

    for (int s = 0; s < nstage; s++) {
        int cur = s & 1;
        bool more = (s + 1 < nstage);
        if (more) {
            stage_A(s + 1, cur ^ 1);
            stage_B(s + 1, cur ^ 1);
            CP_COMMIT();
        }

        uint32_t af[2][2][4];
        const uint32_t* Ab = sm + cur * ABUFU;
        #pragma unroll
        for (int mf = 0; mf < 2; mf++) {
            int r0 = wM * 32 + mf * 16 + gq;
            const uint32_t* p0 = Ab + r0 * SROWU;
            const uint32_t* p1 = Ab + (r0 + 8) * SROWU;
            #pragma unroll
            for (int ks = 0; ks < 2; ks++) {
                af[mf][ks][0] = p0[tig + 8 * ks];
                af[mf][ks][1] = p1[tig + 8 * ks];
                af[mf][ks][2] = p0[tig + 4 + 8 * ks];
                af[mf][ks][3] = p1[tig + 4 + 8 * ks];
            }
        }
        const uint32_t* Bbase = sm + 2 * ABUFU + cur * ABUFU;
        #pragma unroll
        for (int sl = 0; sl < NSLICE; sl++) {
            const uint32_t* Bb = Bbase + sl * 2 * ABUFU;
            #pragma unroll
            for (int nf = 0; nf < 8; nf++) {
                int n = wN * 64 + nf * 8 + gq;
                uint4 bv = *(const uint4*)(Bb + n * SROWU + tig * 4);
                MMA_F16(acc[sl][0][nf], af[0][0][0], af[0][0][1], af[0][0][2], af[0][0][3], bv.x, bv.y);
                MMA_F16(acc[sl][1][nf], af[1][0][0], af[1][0][1], af[1][0][2], af[1][0][3], bv.x, bv.y);
                MMA_F16(acc[sl][0][nf], af[0][1][0], af[0][1][1], af[0][1][2], af[0][1][3], bv.z, bv.w);
                MMA_F16(acc[sl][1][nf], af[1][1][0], af[1][1][1], af[1][1][2], af[1][1][3], bv.z, bv.w);
            }
        }
        if (more) CP_WAIT0();
        __syncthreads();
    }

    if constexpr (EPI == 0) {
        #pragma unroll
        for (int mf = 0; mf < 2; mf++)
        #pragma unroll
        for (int rs = 0; rs < 2; rs++) {
            int r = row0 + wM * 32 + mf * 16 + rs * 8 + gq;
            if (r >= M) continue;
            #pragma unroll
            for (int nf = 0; nf < 8; nf++) {
                int nc = wN * 64 + nf * 8 + tig * 2;
                float v0 = silu_f(acc[0][mf][nf][rs * 2 + 0] + __ldg(bias + n0s + nc));
                float v1 = silu_f(acc[0][mf][nf][rs * 2 + 1] + __ldg(bias + n0s + nc + 1));
                *(__half2*)(C + (size_t)r * ldc + n0s + nc) = __floats2half2_rn(v0, v1);
            }
        }
    } else {
        // slices: sl=0 -> Wd cols 0-127 (bias bd+0), sl=1 -> Wd cols 256-383 (bias bd+256)
        #pragma unroll
        for (int mf = 0; mf < 2; mf++)
        #pragma unroll
        for (int rs = 0; rs < 2; rs++) {
            int e = row0 + wM * 32 + mf * 16 + rs * 8 + gq;
            if (e >= M) continue;
            float* o = eout + (size_t)e * 256;
            #pragma unroll
            for (int nf = 0; nf < 8; nf++) {
                int f = wN * 64 + nf * 8 + tig * 2;
                #pragma unroll
                for (int sl = 0; sl < NSLICE; sl++) {
                    float v0 = acc[sl][mf][nf][rs * 2 + 0] + __ldg(bias + sl * 256 + f);
                    float v1 = acc[sl][mf][nf][rs * 2 + 1] + __ldg(bias + sl * 256 + f + 1);
                    *(float2*)(o + sl * 128 + f) = make_float2(v0, v1);
                }
            }
        }
    }
}

// ================= launch =================
extern "C" void kernel_launch(void* const* d_in, const int* in_sizes, int n_in,
                              void* d_out, int out_size) {
    const float* s_j  = (const float*)d_in[0];
    const float* v_j  = (const float*)d_in[1];
    const float* r_ij = (const float*)d_in[2];
    const int*   nbrs = (const int*)  d_in[3];
    const float* ln_g = (const float*)d_in[4];
    const float* ln_b = (const float*)d_in[5];
    const float* Wq   = (const float*)d_in[6];
    const float* bq   = (const float*)d_in[7];
    const float* Wk   = (const float*)d_in[8];
    const float* bk   = (const float*)d_in[9];
    const float* Wv   = (const float*)d_in[10];
    const float* bv   = (const float*)d_in[11];
    const float* Wdk  = (const float*)d_in[12];
    const float* bdk  = (const float*)d_in[13];
    const float* Wdv  = (const float*)d_in[14];
    const float* bdv  = (const float*)d_in[15];
    const float* Wd   = (const float*)d_in[16];
    const float* bd   = (const float*)d_in[17];
    float* out = (float*)d_out;

    float *x, *qkv, *unit, *eout, *ms;
    __half *rbf, *dkdv, *msg;
    uint32_t *wdp, *wdkp, *wdvp;
    int *cnt, *off, *pos, *eidx;
    cudaGetSymbolAddress((void**)&x,    g_x);
    cudaGetSymbolAddress((void**)&qkv,  g_qkv);
    cudaGetSymbolAddress((void**)&rbf,  g_rbf);
    cudaGetSymbolAddress((void**)&unit, g_unit);
    cudaGetSymbolAddress((void**)&dkdv, g_dkdv);
    cudaGetSymbolAddress((void**)&msg,  g_msg);
    cudaGetSymbolAddress((void**)&eout, g_eout);
    cudaGetSymbolAddress((void**)&ms,   g_ms);
    cudaGetSymbolAddress((void**)&wdp,  g_wdp);
    cudaGetSymbolAddress((void**)&wdkp, g_wdkp);
    cudaGetSymbolAddress((void**)&wdvp, g_wdvp);
    cudaGetSymbolAddress((void**)&cnt,  g_cnt);
    cudaGetSymbolAddress((void**)&off,  g_off);
    cudaGetSymbolAddress((void**)&pos,  g_pos);
    cudaGetSymbolAddress((void**)&eidx, g_eidx);

    const int SMEM_SMALL = (2 + 1 * 2) * ABUFU * 4;   // 40960
    const int SMEM_BIG   = (2 + 2 * 2) * ABUFU * 4;   // 61440
    cudaFuncSetAttribute(mma_fp16<0, 1>, cudaFuncAttributeMaxDynamicSharedMemorySize, SMEM_SMALL);
    cudaFuncSetAttribute(mma_fp16<1, 2>, cudaFuncAttributeMaxDynamicSharedMemorySize, SMEM_BIG);

    // CSR build
    zero_int<<<(NN + 255) / 256, 256>>>(cnt, NN);
    csr_hist<<<(NE + 255) / 256, 256>>>(nbrs, cnt);
    csr_scan<<<1, 256>>>(cnt, off, pos);
    csr_scatter<<<(NE + 255) / 256, 256>>>(nbrs, pos, eidx);

    // weight pre-permutation: wdp = [Wd cols 0-127 | Wd cols 256-383]
    conv_B<<<(128 * 16 * 16 + 255) / 256, 256>>>(Wd,       wdp,                128, 16, 512, 384);
    conv_B<<<(128 * 16 * 16 + 255) / 256, 256>>>(Wd + 256, wdp + 128 * 16 * 16, 128, 16, 512, 384);
    conv_B<<<(512 * 2 * 16 + 255) / 256, 256>>>(Wdk, wdkp, 512, 2, 50, 512);
    conv_B<<<(512 * 2 * 16 + 255) / 256, 256>>>(Wdv, wdvp, 512, 2, 50, 512);

    ln_kernel<<<NN, 128>>>(s_j, ln_g, ln_b, x);

    dim3 gq3(12, (NN + 127) / 128);
    qkv_gemm<<<gq3, 256>>>(x, Wq, Wk, Wv, bq, bk, bv, qkv);

    edge_prep<<<(NE + 255) / 256, 256>>>(r_ij, rbf, unit);

    int mtiles = (NE + 127) / 128;   // 1954
    dim3 ge(4, mtiles);
    mma_fp16<0, 1><<<ge, 256, SMEM_SMALL>>>(rbf, wdkp, bdk, dkdv, 1024, nullptr,
                                            NE, RBFP, 2);
    mma_fp16<0, 1><<<ge, 256, SMEM_SMALL>>>(rbf, wdvp, bdv, dkdv + 512, 1024, nullptr,
                                            NE, RBFP, 2);

    attn_msg<<<(NE + 7) / 8, 256>>>(qkv, dkdv, nbrs, msg);

    // ds path: segment-sum msg, then small fp32 GEMM
    msg_segsum<<<NN, 128>>>(off, eidx, msg, ms);
    dim3 gds(1, (NN + 127) / 128);
    ds_gemm<<<gds, 256>>>(ms, Wd + 128, bd + 128, off, out);

    // dv path: big GEMM (s0, s2 slices) + gather
    mma_fp16<1, 2><<<mtiles, 256, SMEM_BIG>>>(msg, wdp, bd, nullptr, 0, eout,
                                              NE, 512, 16);

    gather_kernel<<<NN, 128>>>(off, eidx, nbrs, unit, v_j, eout,
                               out + NN * FF);
}

// round 14
// speedup vs baseline: 1.0904x; 1.0145x over previous
#include <cuda_runtime.h>
#include <cuda_fp16.h>
#include <math.h>
#include <stdint.h>

#define NN   10000
#define NE   250000
#define FF   128
#define NRBF 50
#define RBFP 64

typedef unsigned long long ull;

// ---------------- scratch ----------------
__device__ float  g_x[NN * FF];
__device__ float  g_qkv[NN * 3 * 512];
__device__ __half g_rbf[(size_t)NE * RBFP];
__device__ float  g_unit[(size_t)NE * 3];
__device__ __half g_dkdv[(size_t)NE * 1024];
__device__ __half g_msg[(size_t)NE * 512];
__device__ float  g_eout[(size_t)NE * 128];       // per-edge s0 (biased)
__device__ float  g_ms[(size_t)4 * NN * 512];     // [ms | T0 | T1 | T2]
__device__ float  g_su[NN * 3];
__device__ float  g_u[(size_t)3 * NN * 128];      // U planes
__device__ uint32_t g_wdp[128 * 16 * 16];         // Wd cols 0-127
__device__ uint32_t g_wdkp[512 * 2 * 16];
__device__ uint32_t g_wdvp[512 * 2 * 16];
__device__ int g_cnt[NN];
__device__ int g_off[NN + 1];
__device__ int g_pos[NN];
__device__ int g_eidx[NE];

#define FMA2(acc, a, b) asm("fma.rn.f32x2 %0, %1, %2, %0;" : "+l"(acc) : "l"(a), "l"(b))
#define PACK2(dst, f)   asm("mov.b64 %0, {%1, %1};" : "=l"(dst) : "f"(f))
#define UNPACK2(lo, hi, v) asm("mov.b64 {%0, %1}, %2;" : "=f"(lo), "=f"(hi) : "l"(v))

__device__ __forceinline__ uint32_t smem_u32(const void* p) {
    uint32_t a;
    asm("{ .reg .u64 t; cvta.to.shared.u64 t, %1; cvt.u32.u64 %0, t; }" : "=r"(a) : "l"(p));
    return a;
}
__device__ __forceinline__ float silu_f(float v) {
    return v / (1.f + __expf(-v));
}

#define MMA_F16(c, a0, a1, a2, a3, b0, b1)                                \
    asm volatile("mma.sync.aligned.m16n8k16.row.col.f32.f16.f16.f32 "     \
        "{%0,%1,%2,%3}, {%4,%5,%6,%7}, {%8,%9}, {%0,%1,%2,%3};"           \
        : "+f"((c)[0]), "+f"((c)[1]), "+f"((c)[2]), "+f"((c)[3])          \
        : "r"(a0), "r"(a1), "r"(a2), "r"(a3), "r"(b0), "r"(b1))

#define CP_ASYNC16(dst, src) \
    asm volatile("cp.async.ca.shared.global [%0], [%1], 16;" :: "r"(dst), "l"(src))
#define CP_COMMIT() asm volatile("cp.async.commit_group;" ::: "memory")
#define CP_WAIT0()  asm volatile("cp.async.wait_group 0;" ::: "memory")

// ================= CSR build =================
__global__ void zero_int(int* __restrict__ p, int n) {
    int i = blockIdx.x * blockDim.x + threadIdx.x;
    if (i < n) p[i] = 0;
}
__global__ void csr_hist(const int* __restrict__ nbrs, int* __restrict__ cnt) {
    int e = blockIdx.x * 256 + threadIdx.x;
    if (e < NE) atomicAdd(&cnt[nbrs[2 * e]], 1);
}
__global__ void __launch_bounds__(256) csr_scan(const int* __restrict__ cnt,
                                                int* __restrict__ off,
                                                int* __restrict__ pos) {
    __shared__ int base;
    __shared__ int wsum[8];
    if (threadIdx.x == 0) base = 0;
    __syncthreads();
    for (int c0 = 0; c0 < NN; c0 += 256) {
        int i = c0 + threadIdx.x;
        int v = (i < NN) ? cnt[i] : 0;
        int lane = threadIdx.x & 31, w = threadIdx.x >> 5;
        int x = v;
        #pragma unroll
        for (int o = 1; o < 32; o <<= 1) {
            int y = __shfl_up_sync(0xffffffffu, x, o);
            if (lane >= o) x += y;
        }
        if (lane == 31) wsum[w] = x;
        __syncthreads();
        int add = 0;
        #pragma unroll
        for (int k = 0; k < 8; k++) if (k < w) add += wsum[k];
        int incl = x + add;
        if (i < NN) {
            int excl = base + incl - v;
            off[i] = excl;
            pos[i] = excl;
        }
        __syncthreads();
        if (threadIdx.x == 255) base += incl;
        __syncthreads();
    }
    if (threadIdx.x == 0) off[NN] = base;
}
__global__ void csr_scatter(const int* __restrict__ nbrs, int* __restrict__ pos,
                            int* __restrict__ eidx) {
    int e = blockIdx.x * 256 + threadIdx.x;
    if (e < NE) {
        int p = atomicAdd(&pos[nbrs[2 * e]], 1);
        eidx[p] = e;
    }
}

// ================= msg segment-sum + unit-weighted sums =================
__global__ void __launch_bounds__(128)
msg_segsum(const int* __restrict__ off, const int* __restrict__ eidx,
           const __half* __restrict__ msg, const float* __restrict__ unit,
           float* __restrict__ ms, float* __restrict__ su) {
    int i = blockIdx.x;
    int t = threadIdx.x;
    int s = off[i], tend = off[i + 1];
    float a[4]  = {0.f, 0.f, 0.f, 0.f};
    float t0[4] = {0.f, 0.f, 0.f, 0.f};
    float t1[4] = {0.f, 0.f, 0.f, 0.f};
    float t2[4] = {0.f, 0.f, 0.f, 0.f};
    float sux = 0.f, suy = 0.f, suz = 0.f;
    for (int p = s; p < tend; p++) {
        int e = __ldg(eidx + p);
        float ux = __ldg(unit + 3 * e), uy = __ldg(unit + 3 * e + 1), uz = __ldg(unit + 3 * e + 2);
        uint2 m = *(const uint2*)(msg + (size_t)e * 512 + t * 4);
        float2 x0 = __half22float2(*(__half2*)&m.x);
        float2 x1 = __half22float2(*(__half2*)&m.y);
        float v[4] = {x0.x, x0.y, x1.x, x1.y};
        #pragma unroll
        for (int q = 0; q < 4; q++) {
            a[q]  += v[q];
            t0[q] += v[q] * ux;
            t1[q] += v[q] * uy;
            t2[q] += v[q] * uz;
        }
        sux += ux; suy += uy; suz += uz;
    }
    size_t base = (size_t)i * 512 + t * 4;
    const size_t plane = (size_t)NN * 512;
    *(float4*)(ms + base)             = make_float4(a[0], a[1], a[2], a[3]);
    *(float4*)(ms + plane + base)     = make_float4(t0[0], t0[1], t0[2], t0[3]);
    *(float4*)(ms + 2 * plane + base) = make_float4(t1[0], t1[1], t1[2], t1[3]);
    *(float4*)(ms + 3 * plane + base) = make_float4(t2[0], t2[1], t2[2], t2[3]);
    if (t == 0) {
        su[3 * i] = sux; su[3 * i + 1] = suy; su[3 * i + 2] = suz;
    }
}

// ================= node GEMM: ds and U planes =================
// which=0: ds = ms@Wd[:,128:256] + deg*bd1 -> dsout
// which=c+1: U_c = T_c@Wd[:,256:384] + su_c*bd2 -> U + c*NN*128
__global__ void __launch_bounds__(256, 2)
node_gemm(const float* __restrict__ msbase, const float* __restrict__ Wd,
          const float* __restrict__ bd, const int* __restrict__ off,
          const float* __restrict__ su,
          float* __restrict__ dsout, float* __restrict__ U) {
    const int M = NN, K = 512;
    int which = blockIdx.x;
    const float* A    = msbase + (size_t)which * NN * 512;
    const float* B    = Wd + ((which == 0) ? 128 : 256);
    const float* bias = bd + ((which == 0) ? 128 : 256);
    float* C = (which == 0) ? dsout : (U + (size_t)(which - 1) * NN * 128);
    int row0 = blockIdx.y * 128;

    __shared__ float As[2][8][128];
    __shared__ float Bs[2][8][128];

    int t  = threadIdx.x;
    int ty = t >> 4, tx = t & 15;

    int arow = t >> 1;
    int acol = (t & 1) * 4;
    int am   = min(row0 + arow, M - 1);
    const float* Aptr = A + (size_t)am * K + acol;

    int bk_ = t >> 5;
    int bn  = (t & 31) * 4;

    float4 ar, br;
    ar = *(const float4*)(Aptr);
    br = *(const float4*)(B + (size_t)bk_ * 384 + bn);

    As[0][acol + 0][arow] = ar.x;
    As[0][acol + 1][arow] = ar.y;
    As[0][acol + 2][arow] = ar.z;
    As[0][acol + 3][arow] = ar.w;
    *(float4*)&Bs[0][bk_][bn] = br;
    __syncthreads();

    ull acc[8][4];
    #pragma unroll
    for (int i = 0; i < 8; i++)
        #pragma unroll
        for (int j = 0; j < 4; j++) acc[i][j] = 0ULL;

    const int nstage = K >> 3;
    for (int s = 0; s < nstage; s++) {
        int cur = s & 1, nxt = cur ^ 1;
        bool more = (s + 1 < nstage);
        if (more) {
            int kk = (s + 1) << 3;
            ar = *(const float4*)(Aptr + kk);
            br = *(const float4*)(B + (size_t)(kk + bk_) * 384 + bn);
        }
        #pragma unroll
        for (int k = 0; k < 8; k++) {
            float4 a0 = *(float4*)&As[cur][k][ty * 8];
            float4 a1 = *(float4*)&As[cur][k][ty * 8 + 4];
            ulonglong2 b0 = *(ulonglong2*)&Bs[cur][k][tx * 8];
            ulonglong2 b1 = *(ulonglong2*)&Bs[cur][k][tx * 8 + 4];
            ull a2[8];
            PACK2(a2[0], a0.x); PACK2(a2[1], a0.y);
            PACK2(a2[2], a0.z); PACK2(a2[3], a0.w);
            PACK2(a2[4], a1.x); PACK2(a2[5], a1.y);
            PACK2(a2[6], a1.z); PACK2(a2[7], a1.w);
            #pragma unroll
            for (int i = 0; i < 8; i++) {
                FMA2(acc[i][0], a2[i], b0.x);
                FMA2(acc[i][1], a2[i], b0.y);
                FMA2(acc[i][2], a2[i], b1.x);
                FMA2(acc[i][3], a2[i], b1.y);
            }
        }
        if (more) {
            As[nxt][acol + 0][arow] = ar.x;
            As[nxt][acol + 1][arow] = ar.y;
            As[nxt][acol + 2][arow] = ar.z;
            As[nxt][acol + 3][arow] = ar.w;
            *(float4*)&Bs[nxt][bk_][bn] = br;
        }
        __syncthreads();
    }

    int colb = tx * 8;
    float4 bs0 = *(const float4*)(bias + colb);
    float4 bs1 = *(const float4*)(bias + colb + 4);
    #pragma unroll
    for (int i = 0; i < 8; i++) {
        int row = row0 + ty * 8 + i;
        if (row >= M) continue;
        float sc = (which == 0)
                 ? (float)(__ldg(off + row + 1) - __ldg(off + row))
                 : __ldg(su + 3 * row + (which - 1));
        float v[8];
        UNPACK2(v[0], v[1], acc[i][0]);
        UNPACK2(v[2], v[3], acc[i][1]);
        UNPACK2(v[4], v[5], acc[i][2]);
        UNPACK2(v[6], v[7], acc[i][3]);
        v[0] += sc * bs0.x; v[1] += sc * bs0.y; v[2] += sc * bs0.z; v[3] += sc * bs0.w;
        v[4] += sc * bs1.x; v[5] += sc * bs1.y; v[6] += sc * bs1.z; v[7] += sc * bs1.w;
        float* cp = C + (size_t)row * 128 + colb;
        *(float4*)cp       = make_float4(v[0], v[1], v[2], v[3]);
        *(float4*)(cp + 4) = make_float4(v[4], v[5], v[6], v[7]);
    }
}

// ================= dv gather: s0*v_j + U =================
__global__ void __launch_bounds__(128)
gather_kernel(const int* __restrict__ off, const int* __restrict__ eidx,
              const int* __restrict__ nbrs,
              const float* __restrict__ v_j, const float* __restrict__ eout,
              const float* __restrict__ U, float* __restrict__ dvout) {
    int i = blockIdx.x;
    int f = threadIdx.x;
    int s = off[i], t = off[i + 1];
    float a0 = 0.f, a1 = 0.f, a2 = 0.f;
    for (int p = s; p < t; p++) {
        int e = __ldg(eidx + p);
        int jj = __ldg(nbrs + 2 * e + 1);
        float s0 = __ldg(eout + (size_t)e * 128 + f);
        const float* vj = v_j + ((size_t)jj * FF + f) * 3;
        a0 += s0 * vj[0];
        a1 += s0 * vj[1];
        a2 += s0 * vj[2];
    }
    size_t idx = (size_t)i * 128 + f;
    const size_t pl = (size_t)NN * 128;
    float* dv = dvout + idx * 3;
    dv[0] = a0 + __ldg(U + idx);
    dv[1] = a1 + __ldg(U + pl + idx);
    dv[2] = a2 + __ldg(U + 2 * pl + idx);
}

// ================= B pre-permutation =================
__global__ void conv_B(const float* __restrict__ W, uint32_t* __restrict__ out,
                       int N, int nst, int Kreal, int Nld) {
    int i = blockIdx.x * 256 + threadIdx.x;
    int total = N * nst * 16;
    if (i >= total) return;
    int n = i / (nst * 16);
    int rem = i % (nst * 16);
    int s = rem >> 4, p = rem & 15;
    int bp = (p & 3) * 4 + (p >> 2);
    int k = s * 32 + bp * 2;
    float lo = (k < Kreal)     ? W[(size_t)k * Nld + n]       : 0.f;
    float hi = (k + 1 < Kreal) ? W[(size_t)(k + 1) * Nld + n] : 0.f;
    __half2 h = __floats2half2_rn(lo, hi);
    out[i] = *(uint32_t*)&h;
}

__global__ void __launch_bounds__(128) ln_kernel(const float* __restrict__ s,
                                                 const float* __restrict__ gam,
                                                 const float* __restrict__ bet,
                                                 float* __restrict__ x) {
    int n = blockIdx.x, t = threadIdx.x;
    float v = s[(size_t)n * FF + t];
    float s1 = v, s2 = v * v;
    #pragma unroll
    for (int o = 16; o; o >>= 1) {
        s1 += __shfl_down_sync(0xffffffffu, s1, o);
        s2 += __shfl_down_sync(0xffffffffu, s2, o);
    }
    __shared__ float p1[4], p2[4], mv[2];
    if ((t & 31) == 0) { p1[t >> 5] = s1; p2[t >> 5] = s2; }
    __syncthreads();
    if (t == 0) {
        float a = p1[0] + p1[1] + p1[2] + p1[3];
        float c = p2[0] + p2[1] + p2[2] + p2[3];
        float m = a / 128.f;
        mv[0] = m;
        mv[1] = rsqrtf(c / 128.f - m * m + 1e-5f);
    }
    __syncthreads();
    x[(size_t)n * FF + t] = (v - mv[0]) * mv[1] * gam[t] + bet[t];
}

__global__ void __launch_bounds__(256) edge_prep(const float* __restrict__ r,
                                                 __half* __restrict__ rbf,
                                                 float* __restrict__ unit) {
    int e = blockIdx.x * 256 + threadIdx.x;
    if (e >= NE) return;
    float x = __ldg(r + 3 * e), y = __ldg(r + 3 * e + 1), z = __ldg(r + 3 * e + 2);
    float d = sqrtf(x * x + y * y + z * z + 3e-15f);
    float inv = 1.f / d;
    unit[3 * e] = x * inv; unit[3 * e + 1] = y * inv; unit[3 * e + 2] = z * inv;
    const float width = 5.0f / 49.0f;
    const float gam = 0.5f / (width * width);
    __half2 buf[32];
    #pragma unroll
    for (int k2 = 0; k2 < 32; k2++) {
        int k0 = k2 * 2, k1 = k2 * 2 + 1;
        float d0 = d - (float)k0 * width;
        float d1 = d - (float)k1 * width;
        float v0 = (k0 < NRBF) ? __expf(-gam * d0 * d0) : 0.f;
        float v1 = (k1 < NRBF) ? __expf(-gam * d1 * d1) : 0.f;
        buf[k2] = __floats2half2_rn(v0, v1);
    }
    uint4* dst = (uint4*)(rbf + (size_t)e * RBFP);
    const uint4* src = (const uint4*)buf;
    #pragma unroll
    for (int q = 0; q < 8; q++) dst[q] = src[q];
}

// ================= qkv: fused 3-way f32x2 SGEMM =================
__global__ void __launch_bounds__(256, 2)
qkv_gemm(const float* __restrict__ Xin,
         const float* __restrict__ Wq, const float* __restrict__ Wk,
         const float* __restrict__ Wv,
         const float* __restrict__ bq, const float* __restrict__ bk,
         const float* __restrict__ bv,
         float* __restrict__ qkvout) {
    const int M = NN, N = 512, K = 128, lda = 128, ldc = 1536;
    int which = blockIdx.x >> 2;
    const float* B    = (which == 0) ? Wq : ((which == 1) ? Wk : Wv);
    const float* bias = (which == 0) ? bq : ((which == 1) ? bk : bv);
    float* C = qkvout + which * 512;
    int col0 = (blockIdx.x & 3) * 128;
    int row0 = blockIdx.y * 128;

    __shared__ float As[2][8][128];
    __shared__ float Bs[2][8][128];

    int t  = threadIdx.x;
    int ty = t >> 4, tx = t & 15;

    int arow = t >> 1;
    int acol = (t & 1) * 4;
    int am   = min(row0 + arow, M - 1);
    const float* Aptr = Xin + (size_t)am * lda + acol;

    int bk_ = t >> 5;
    int bn  = (t & 31) * 4;

    float4 ar, br;
    ar = *(const float4*)(Aptr);
    br = *(const float4*)(B + (size_t)bk_ * N + col0 + bn);

    As[0][acol + 0][arow] = ar.x;
    As[0][acol + 1][arow] = ar.y;
    As[0][acol + 2][arow] = ar.z;
    As[0][acol + 3][arow] = ar.w;
    *(float4*)&Bs[0][bk_][bn] = br;
    __syncthreads();

    ull acc[8][4];
    #pragma unroll
    for (int i = 0; i < 8; i++)
        #pragma unroll
        for (int j = 0; j < 4; j++) acc[i][j] = 0ULL;

    const int nstage = K >> 3;
    for (int s = 0; s < nstage; s++) {
        int cur = s & 1, nxt = cur ^ 1;
        bool more = (s + 1 < nstage);
        if (more) {
            int kk = (s + 1) << 3;
            ar = *(const float4*)(Aptr + kk);
            br = *(const float4*)(B + (size_t)(kk + bk_) * N + col0 + bn);
        }
        #pragma unroll
        for (int k = 0; k < 8; k++) {
            float4 a0 = *(float4*)&As[cur][k][ty * 8];
            float4 a1 = *(float4*)&As[cur][k][ty * 8 + 4];
            ulonglong2 b0 = *(ulonglong2*)&Bs[cur][k][tx * 8];
            ulonglong2 b1 = *(ulonglong2*)&Bs[cur][k][tx * 8 + 4];
            ull a2[8];
            PACK2(a2[0], a0.x); PACK2(a2[1], a0.y);
            PACK2(a2[2], a0.z); PACK2(a2[3], a0.w);
            PACK2(a2[4], a1.x); PACK2(a2[5], a1.y);
            PACK2(a2[6], a1.z); PACK2(a2[7], a1.w);
            #pragma unroll
            for (int i = 0; i < 8; i++) {
                FMA2(acc[i][0], a2[i], b0.x);
                FMA2(acc[i][1], a2[i], b0.y);
                FMA2(acc[i][2], a2[i], b1.x);
                FMA2(acc[i][3], a2[i], b1.y);
            }
        }
        if (more) {
            As[nxt][acol + 0][arow] = ar.x;
            As[nxt][acol + 1][arow] = ar.y;
            As[nxt][acol + 2][arow] = ar.z;
            As[nxt][acol + 3][arow] = ar.w;
            *(float4*)&Bs[nxt][bk_][bn] = br;
        }
        __syncthreads();
    }

    int colb = col0 + tx * 8;
    float4 bs0 = *(const float4*)(bias + colb);
    float4 bs1 = *(const float4*)(bias + colb + 4);
    #pragma unroll
    for (int i = 0; i < 8; i++) {
        int row = row0 + ty * 8 + i;
        if (row >= M) continue;
        float v[8];
        UNPACK2(v[0], v[1], acc[i][0]);
        UNPACK2(v[2], v[3], acc[i][1]);
        UNPACK2(v[4], v[5], acc[i][2]);
        UNPACK2(v[6], v[7], acc[i][3]);
        v[0] += bs0.x; v[1] += bs0.y; v[2] += bs0.z; v[3] += bs0.w;
        v[4] += bs1.x; v[5] += bs1.y; v[6] += bs1.z; v[7] += bs1.w;
        float* cp = C + (size_t)row * ldc + colb;
        *(float4*)cp       = make_float4(v[0], v[1], v[2], v[3]);
        *(float4*)(cp + 4) = make_float4(v[4], v[5], v[6], v[7]);
    }
}

// ================= attn + msg: warp-per-edge =================
__global__ void __launch_bounds__(256) attn_msg(const float* __restrict__ qkv,
                                                const __half* __restrict__ dkdv,
                                                const int* __restrict__ nbrs,
                                                __half* __restrict__ msg) {
    int e = blockIdx.x * 8 + (threadIdx.x >> 5);
    if (e >= NE) return;
    int l = threadIdx.x & 31;
    int i = __ldg(nbrs + 2 * e), j = __ldg(nbrs + 2 * e + 1);
    const float4* q4 = (const float4*)(qkv + (size_t)i * 1536);
    const float4* k4 = (const float4*)(qkv + (size_t)j * 1536 + 512);
    const float4* v4 = (const float4*)(qkv + (size_t)j * 1536 + 1024);
    const uint2* dk2 = (const uint2*)(dkdv + (size_t)e * 1024);
    const uint2* dv2 = dk2 + 128;

    float4 qv[4], kv[4], vv[4];
    uint2 dkv[4], dvv[4];
    #pragma unroll
    for (int h = 0; h < 4; h++) {
        int idx = h * 32 + l;
        qv[h] = q4[idx]; kv[h] = k4[idx]; vv[h] = v4[idx];
        dkv[h] = dk2[idx]; dvv[h] = dv2[idx];
    }
    float p[4];
    #pragma unroll
    for (int h = 0; h < 4; h++) {
        float2 f0 = __half22float2(*(__half2*)&dkv[h].x);
        float2 f1 = __half22float2(*(__half2*)&dkv[h].y);
        p[h] = qv[h].x * kv[h].x * f0.x + qv[h].y * kv[h].y * f0.y
             + qv[h].z * kv[h].z * f1.x + qv[h].w * kv[h].w * f1.y;
    }
    #pragma unroll
    for (int o = 16; o; o >>= 1)
        #pragma unroll
        for (int h = 0; h < 4; h++) p[h] += __shfl_xor_sync(0xffffffffu, p[h], o);

    __half* mrow = msg + (size_t)e * 512;
    #pragma unroll
    for (int h = 0; h < 4; h++) {
        float at = silu_f(p[h]);
        float2 g0 = __half22float2(*(__half2*)&dvv[h].x);
        float2 g1 = __half22float2(*(__half2*)&dvv[h].y);
        __half2 m0 = __floats2half2_rn(vv[h].x * g0.x * at, vv[h].y * g0.y * at);
        __half2 m1 = __floats2half2_rn(vv[h].z * g1.x * at, vv[h].w * g1.y * at);
        uint2 o2;
        o2.x = *(uint32_t*)&m0;
        o2.y = *(uint32_t*)&m1;
        *(uint2*)(mrow + h * 128 + l * 4) = o2;
    }
}

// ================= fp16 mma GEMM =================
// EPI=0: dk/dv — silu + half store to C at cols n0s.
// EPI=1: big GEMM — NSLICE=1 (s0), biased float store to eout (stride 128).
#define SROWU 20
#define ABUFU (128 * SROWU)

template <int EPI, int NSLICE>
__global__ void __launch_bounds__(256)
mma_fp16(const __half* __restrict__ A, const uint32_t* __restrict__ Bp,
         const float* __restrict__ bias, __half* __restrict__ C, int ldc,
         float* __restrict__ eout,
         int M, int lda, int nstage) {
    extern __shared__ uint32_t sm[];
    const uint32_t sA = smem_u32(sm);
    const uint32_t sB0 = sA + 2 * ABUFU * 4;

    const int tid = threadIdx.x;
    const int wid = tid >> 5, lid = tid & 31;
    const int gq = lid >> 2, tig = lid & 3;
    const int wM = wid >> 1, wN = wid & 1;
    const int row0 = (EPI == 1 ? blockIdx.x : blockIdx.y) * 128;
    const int n0s  = (EPI == 1 ? 0 : blockIdx.x * 128);

    float acc[NSLICE][2][8][4];
    #pragma unroll
    for (int s = 0; s < NSLICE; s++)
        #pragma unroll
        for (int a = 0; a < 2; a++)
            #pragma unroll
            for (int b = 0; b < 8; b++)
                #pragma unroll
                for (int c = 0; c < 4; c++) acc[s][a][b][c] = 0.f;

    const int arow = tid >> 1, ac2 = (tid & 1) * 2;
    const __half* aRow = A + (size_t)min(row0 + arow, M - 1) * lda;

    auto stage_A = [&](int s, int buf) {
        const __half* src = aRow + s * 32 + ac2 * 8;
        uint32_t dst = sA + (buf * ABUFU + arow * SROWU + ac2 * 4) * 4;
        CP_ASYNC16(dst, src);
        CP_ASYNC16(dst + 16, src + 8);
    };

    auto stage_B = [&](int s, int buf) {
        #pragma unroll
        for (int i = 0; i < NSLICE * 2; i++) {
            int cid = tid + i * 256;
            int sl = cid >> 9;
            int c  = cid & 511;
            int n = c >> 2, q = c & 3;
            int ng = (EPI == 1 ? sl * 128 : n0s) + n;
            const uint32_t* src = Bp + ((size_t)ng * nstage + s) * 16 + q * 4;
            uint32_t dst = sB0 + ((sl * 2 + buf) * ABUFU + n * SROWU + q * 4) * 4;
            CP_ASYNC16(dst, src);
        }
    };

    stage_A(0, 0);
    stage_B(0, 0);
    CP_COMMIT();
    CP_WAIT0();
    __syncthreads();

    for (int s = 0; s < nstage; s++) {
        int cur = s & 1;
        bool more = (s + 1 < nstage);
        if (more) {
            stage_A(s + 1, cur ^ 1);
            stage_B(s + 1, cur ^ 1);
            CP_COMMIT();
        }

        uint32_t af[2][2][4];
        const uint32_t* Ab = sm + cur * ABUFU;
        #pragma unroll
        for (int mf = 0; mf < 2; mf++) {
            int r0 = wM * 32 + mf * 16 + gq;
            const uint32_t* p0 = Ab + r0 * SROWU;
            const uint32_t* p1 = Ab + (r0 + 8) * SROWU;
            #pragma unroll
            for (int ks = 0; ks < 2; ks++) {
                af[mf][ks][0] = p0[tig + 8 * ks];
                af[mf][ks][1] = p1[tig + 8 * ks];
                af[mf][ks][2] = p0[tig + 4 + 8 * ks];
                af[mf][ks][3] = p1[tig + 4 + 8 * ks];
            }
        }
        const uint32_t* Bbase = sm + 2 * ABUFU + cur * ABUFU;
        #pragma unroll
        for (int sl = 0; sl < NSLICE; sl++) {
            const uint32_t* Bb = Bbase + sl * 2 * ABUFU;
            #pragma unroll
            for (int nf = 0; nf < 8; nf++) {
                int n = wN * 64 + nf * 8 + gq;
                uint4 bv = *(const uint4*)(Bb + n * SROWU + tig * 4);
                MMA_F16(acc[sl][0][nf], af[0][0][0], af[0][0][1], af[0][0][2], af[0][0][3], bv.x, bv.y);
                MMA_F16(acc[sl][1][nf], af[1][0][0], af[1][0][1], af[1][0][2], af[1][0][3], bv.x, bv.y);
                MMA_F16(acc[sl][0][nf], af[0][1][0], af[0][1][1], af[0][1][2], af[0][1][3], bv.z, bv.w);
                MMA_F16(acc[sl][1][nf], af[1][1][0], af[1][1][1], af[1][1][2], af[1][1][3], bv.z, bv.w);
            }
        }
        if (more) CP_WAIT0();
        __syncthreads();
    }

    if constexpr (EPI == 0) {
        #pragma unroll
        for (int mf = 0; mf < 2; mf++)
        #pragma unroll
        for (int rs = 0; rs < 2; rs++) {
            int r = row0 + wM * 32 + mf * 16 + rs * 8 + gq;
            if (r >= M) continue;
            #pragma unroll
            for (int nf = 0; nf < 8; nf++) {
                int nc = wN * 64 + nf * 8 + tig * 2;
                float v0 = silu_f(acc[0][mf][nf][rs * 2 + 0] + __ldg(bias + n0s + nc));
                float v1 = silu_f(acc[0][mf][nf][rs * 2 + 1] + __ldg(bias + n0s + nc + 1));
                *(__half2*)(C + (size_t)r * ldc + n0s + nc) = __floats2half2_rn(v0, v1);
            }
        }
    } else {
        #pragma unroll
        for (int mf = 0; mf < 2; mf++)
        #pragma unroll
        for (int rs = 0; rs < 2; rs++) {
            int e = row0 + wM * 32 + mf * 16 + rs * 8 + gq;
            if (e >= M) continue;
            float* o = eout + (size_t)e * 128;
            #pragma unroll
            for (int nf = 0; nf < 8; nf++) {
                int f = wN * 64 + nf * 8 + tig * 2;
                float v0 = acc[0][mf][nf][rs * 2 + 0] + __ldg(bias + f);
                float v1 = acc[0][mf][nf][rs * 2 + 1] + __ldg(bias + f + 1);
                *(float2*)(o + f) = make_float2(v0, v1);
            }
        }
    }
}

// ================= launch =================
extern "C" void kernel_launch(void* const* d_in, const int* in_sizes, int n_in,
                              void* d_out, int out_size) {
    const float* s_j  = (const float*)d_in[0];
    const float* v_j  = (const float*)d_in[1];
    const float* r_ij = (const float*)d_in[2];
    const int*   nbrs = (const int*)  d_in[3];
    const float* ln_g = (const float*)d_in[4];
    const float* ln_b = (const float*)d_in[5];
    const float* Wq   = (const float*)d_in[6];
    const float* bq   = (const float*)d_in[7];
    const float* Wk   = (const float*)d_in[8];
    const float* bk   = (const float*)d_in[9];
    const float* Wv   = (const float*)d_in[10];
    const float* bv   = (const float*)d_in[11];
    const float* Wdk  = (const float*)d_in[12];
    const float* bdk  = (const float*)d_in[13];
    const float* Wdv  = (const float*)d_in[14];
    const float* bdv  = (const float*)d_in[15];
    const float* Wd   = (const float*)d_in[16];
    const float* bd   = (const float*)d_in[17];
    float* out = (float*)d_out;

    float *x, *qkv, *unit, *eout, *ms, *su, *U;
    __half *rbf, *dkdv, *msg;
    uint32_t *wdp, *wdkp, *wdvp;
    int *cnt, *off, *pos, *eidx;
    cudaGetSymbolAddress((void**)&x,    g_x);
    cudaGetSymbolAddress((void**)&qkv,  g_qkv);
    cudaGetSymbolAddress((void**)&rbf,  g_rbf);
    cudaGetSymbolAddress((void**)&unit, g_unit);
    cudaGetSymbolAddress((void**)&dkdv, g_dkdv);
    cudaGetSymbolAddress((void**)&msg,  g_msg);
    cudaGetSymbolAddress((void**)&eout, g_eout);
    cudaGetSymbolAddress((void**)&ms,   g_ms);
    cudaGetSymbolAddress((void**)&su,   g_su);
    cudaGetSymbolAddress((void**)&U,    g_u);
    cudaGetSymbolAddress((void**)&wdp,  g_wdp);
    cudaGetSymbolAddress((void**)&wdkp, g_wdkp);
    cudaGetSymbolAddress((void**)&wdvp, g_wdvp);
    cudaGetSymbolAddress((void**)&cnt,  g_cnt);
    cudaGetSymbolAddress((void**)&off,  g_off);
    cudaGetSymbolAddress((void**)&pos,  g_pos);
    cudaGetSymbolAddress((void**)&eidx, g_eidx);

    const int SMEM_SMALL = (2 + 1 * 2) * ABUFU * 4;   // 40960
    cudaFuncSetAttribute(mma_fp16<0, 1>, cudaFuncAttributeMaxDynamicSharedMemorySize, SMEM_SMALL);
    cudaFuncSetAttribute(mma_fp16<1, 1>, cudaFuncAttributeMaxDynamicSharedMemorySize, SMEM_SMALL);

    // CSR build
    zero_int<<<(NN + 255) / 256, 256>>>(cnt, NN);
    csr_hist<<<(NE + 255) / 256, 256>>>(nbrs, cnt);
    csr_scan<<<1, 256>>>(cnt, off, pos);
    csr_scatter<<<(NE + 255) / 256, 256>>>(nbrs, pos, eidx);

    // weight pre-permutation: wdp = Wd cols 0-127 only
    conv_B<<<(128 * 16 * 16 + 255) / 256, 256>>>(Wd, wdp, 128, 16, 512, 384);
    conv_B<<<(512 * 2 * 16 + 255) / 256, 256>>>(Wdk, wdkp, 512, 2, 50, 512);
    conv_B<<<(512 * 2 * 16 + 255) / 256, 256>>>(Wdv, wdvp, 512, 2, 50, 512);

    ln_kernel<<<NN, 128>>>(s_j, ln_g, ln_b, x);

    dim3 gq3(12, (NN + 127) / 128);
    qkv_gemm<<<gq3, 256>>>(x, Wq, Wk, Wv, bq, bk, bv, qkv);

    edge_prep<<<(NE + 255) / 256, 256>>>(r_ij, rbf, unit);

    int mtiles = (NE + 127) / 128;   // 1954
    dim3 ge(4, mtiles);
    mma_fp16<0, 1><<<ge, 256, SMEM_SMALL>>>(rbf, wdkp, bdk, dkdv, 1024, nullptr,
                                            NE, RBFP, 2);
    mma_fp16<0, 1><<<ge, 256, SMEM_SMALL>>>(rbf, wdvp, bdv, dkdv + 512, 1024, nullptr,
                                            NE, RBFP, 2);

    attn_msg<<<(NE + 7) / 8, 256>>>(qkv, dkdv, nbrs, msg);

    // node-side sums: ms, T0..T2, su
    msg_segsum<<<NN, 128>>>(off, eidx, msg, unit, ms, su);

    // node GEMMs: ds (which=0) + U planes (which=1..3)
    dim3 gnode(4, (NN + 127) / 128);
    node_gemm<<<gnode, 256>>>(ms, Wd, bd, off, su, out, U);

    // edge GEMM: s0 only
    mma_fp16<1, 1><<<mtiles, 256, SMEM_SMALL>>>(msg, wdp, bd, nullptr, 0, eout,
                                                NE, 512, 16);

    gather_kernel<<<NN, 128>>>(off, eidx, nbrs, v_j, eout, U,
                               out + NN * FF);
}

// round 15
// speedup vs baseline: 1.1143x; 1.0219x over previous
#include <cuda_runtime.h>
#include <cuda_fp16.h>
#include <math.h>
#include <stdint.h>

#define NN   10000
#define NE   250000
#define FF   128
#define NRBF 50
#define RBFP 64

typedef unsigned long long ull;

// ---------------- scratch (all edge arrays in CSR "p" order) ----------------
__device__ float  g_x[NN * FF];
__device__ float  g_qkv[NN * 3 * 512];
__device__ __half g_rbf[(size_t)NE * RBFP];
__device__ float  g_unitc[(size_t)NE * 3];
__device__ int2   g_ij[NE];
__device__ __half g_dkdv[(size_t)NE * 1024];
__device__ __half g_msg[(size_t)NE * 512];
__device__ float  g_eout[(size_t)NE * 128];
__device__ float  g_ms[(size_t)4 * NN * 512];     // [ms | T0 | T1 | T2]
__device__ float  g_su[NN * 3];
__device__ float  g_u[(size_t)3 * NN * 128];
__device__ uint32_t g_wdp[128 * 16 * 16];
__device__ uint32_t g_wdkp[512 * 2 * 16];
__device__ uint32_t g_wdvp[512 * 2 * 16];
__device__ int g_cnt[NN];
__device__ int g_off[NN + 1];
__device__ int g_pos[NN];
__device__ int g_eidx[NE];

#define FMA2(acc, a, b) asm("fma.rn.f32x2 %0, %1, %2, %0;" : "+l"(acc) : "l"(a), "l"(b))
#define PACK2(dst, f)   asm("mov.b64 %0, {%1, %1};" : "=l"(dst) : "f"(f))
#define UNPACK2(lo, hi, v) asm("mov.b64 {%0, %1}, %2;" : "=f"(lo), "=f"(hi) : "l"(v))

__device__ __forceinline__ uint32_t smem_u32(const void* p) {
    uint32_t a;
    asm("{ .reg .u64 t; cvta.to.shared.u64 t, %1; cvt.u32.u64 %0, t; }" : "=r"(a) : "l"(p));
    return a;
}
__device__ __forceinline__ float silu_f(float v) {
    return v / (1.f + __expf(-v));
}

#define MMA_F16(c, a0, a1, a2, a3, b0, b1)                                \
    asm volatile("mma.sync.aligned.m16n8k16.row.col.f32.f16.f16.f32 "     \
        "{%0,%1,%2,%3}, {%4,%5,%6,%7}, {%8,%9}, {%0,%1,%2,%3};"           \
        : "+f"((c)[0]), "+f"((c)[1]), "+f"((c)[2]), "+f"((c)[3])          \
        : "r"(a0), "r"(a1), "r"(a2), "r"(a3), "r"(b0), "r"(b1))

#define CP_ASYNC16(dst, src) \
    asm volatile("cp.async.ca.shared.global [%0], [%1], 16;" :: "r"(dst), "l"(src))
#define CP_COMMIT() asm volatile("cp.async.commit_group;" ::: "memory")
#define CP_WAIT0()  asm volatile("cp.async.wait_group 0;" ::: "memory")

// ================= CSR build =================
__global__ void zero_int(int* __restrict__ p, int n) {
    int i = blockIdx.x * blockDim.x + threadIdx.x;
    if (i < n) p[i] = 0;
}
__global__ void csr_hist(const int* __restrict__ nbrs, int* __restrict__ cnt) {
    int e = blockIdx.x * 256 + threadIdx.x;
    if (e < NE) atomicAdd(&cnt[nbrs[2 * e]], 1);
}
__global__ void __launch_bounds__(256) csr_scan(const int* __restrict__ cnt,
                                                int* __restrict__ off,
                                                int* __restrict__ pos) {
    __shared__ int base;
    __shared__ int wsum[8];
    if (threadIdx.x == 0) base = 0;
    __syncthreads();
    for (int c0 = 0; c0 < NN; c0 += 256) {
        int i = c0 + threadIdx.x;
        int v = (i < NN) ? cnt[i] : 0;
        int lane = threadIdx.x & 31, w = threadIdx.x >> 5;
        int x = v;
        #pragma unroll
        for (int o = 1; o < 32; o <<= 1) {
            int y = __shfl_up_sync(0xffffffffu, x, o);
            if (lane >= o) x += y;
        }
        if (lane == 31) wsum[w] = x;
        __syncthreads();
        int add = 0;
        #pragma unroll
        for (int k = 0; k < 8; k++) if (k < w) add += wsum[k];
        int incl = x + add;
        if (i < NN) {
            int excl = base + incl - v;
            off[i] = excl;
            pos[i] = excl;
        }
        __syncthreads();
        if (threadIdx.x == 255) base += incl;
        __syncthreads();
    }
    if (threadIdx.x == 0) off[NN] = base;
}
__global__ void csr_scatter(const int* __restrict__ nbrs, int* __restrict__ pos,
                            int* __restrict__ eidx) {
    int e = blockIdx.x * 256 + threadIdx.x;
    if (e < NE) {
        int p = atomicAdd(&pos[nbrs[2 * e]], 1);
        eidx[p] = e;
    }
}

// ================= edge prep in CSR order =================
__global__ void __launch_bounds__(256) edge_prep(const int* __restrict__ eidx,
                                                 const int* __restrict__ nbrs,
                                                 const float* __restrict__ r,
                                                 __half* __restrict__ rbf,
                                                 float* __restrict__ unitc,
                                                 int2* __restrict__ ij) {
    int p = blockIdx.x * 256 + threadIdx.x;
    if (p >= NE) return;
    int e = __ldg(eidx + p);
    ij[p] = make_int2(__ldg(nbrs + 2 * e), __ldg(nbrs + 2 * e + 1));
    float x = __ldg(r + 3 * e), y = __ldg(r + 3 * e + 1), z = __ldg(r + 3 * e + 2);
    float d = sqrtf(x * x + y * y + z * z + 3e-15f);
    float inv = 1.f / d;
    unitc[3 * p] = x * inv; unitc[3 * p + 1] = y * inv; unitc[3 * p + 2] = z * inv;
    const float width = 5.0f / 49.0f;
    const float gam = 0.5f / (width * width);
    __half2 buf[32];
    #pragma unroll
    for (int k2 = 0; k2 < 32; k2++) {
        int k0 = k2 * 2, k1 = k2 * 2 + 1;
        float d0 = d - (float)k0 * width;
        float d1 = d - (float)k1 * width;
        float v0 = (k0 < NRBF) ? __expf(-gam * d0 * d0) : 0.f;
        float v1 = (k1 < NRBF) ? __expf(-gam * d1 * d1) : 0.f;
        buf[k2] = __floats2half2_rn(v0, v1);
    }
    uint4* dst = (uint4*)(rbf + (size_t)p * RBFP);
    const uint4* src = (const uint4*)buf;
    #pragma unroll
    for (int q = 0; q < 8; q++) dst[q] = src[q];
}

// ================= msg segment-sum + unit-weighted sums (sequential) =================
__global__ void __launch_bounds__(128)
msg_segsum(const int* __restrict__ off,
           const __half* __restrict__ msg, const float* __restrict__ unitc,
           float* __restrict__ ms, float* __restrict__ su) {
    int i = blockIdx.x;
    int t = threadIdx.x;
    int s = off[i], tend = off[i + 1];
    float a[4]  = {0.f, 0.f, 0.f, 0.f};
    float t0[4] = {0.f, 0.f, 0.f, 0.f};
    float t1[4] = {0.f, 0.f, 0.f, 0.f};
    float t2[4] = {0.f, 0.f, 0.f, 0.f};
    float sux = 0.f, suy = 0.f, suz = 0.f;
    for (int p = s; p < tend; p++) {
        float ux = __ldg(unitc + 3 * p), uy = __ldg(unitc + 3 * p + 1), uz = __ldg(unitc + 3 * p + 2);
        uint2 m = *(const uint2*)(msg + (size_t)p * 512 + t * 4);
        float2 x0 = __half22float2(*(__half2*)&m.x);
        float2 x1 = __half22float2(*(__half2*)&m.y);
        float v[4] = {x0.x, x0.y, x1.x, x1.y};
        #pragma unroll
        for (int q = 0; q < 4; q++) {
            a[q]  += v[q];
            t0[q] += v[q] * ux;
            t1[q] += v[q] * uy;
            t2[q] += v[q] * uz;
        }
        sux += ux; suy += uy; suz += uz;
    }
    size_t base = (size_t)i * 512 + t * 4;
    const size_t plane = (size_t)NN * 512;
    *(float4*)(ms + base)             = make_float4(a[0], a[1], a[2], a[3]);
    *(float4*)(ms + plane + base)     = make_float4(t0[0], t0[1], t0[2], t0[3]);
    *(float4*)(ms + 2 * plane + base) = make_float4(t1[0], t1[1], t1[2], t1[3]);
    *(float4*)(ms + 3 * plane + base) = make_float4(t2[0], t2[1], t2[2], t2[3]);
    if (t == 0) {
        su[3 * i] = sux; su[3 * i + 1] = suy; su[3 * i + 2] = suz;
    }
}

// ================= node GEMM: ds and U planes =================
__global__ void __launch_bounds__(256, 2)
node_gemm(const float* __restrict__ msbase, const float* __restrict__ Wd,
          const float* __restrict__ bd, const int* __restrict__ off,
          const float* __restrict__ su,
          float* __restrict__ dsout, float* __restrict__ U) {
    const int M = NN, K = 512;
    int which = blockIdx.x;
    const float* A    = msbase + (size_t)which * NN * 512;
    const float* B    = Wd + ((which == 0) ? 128 : 256);
    const float* bias = bd + ((which == 0) ? 128 : 256);
    float* C = (which == 0) ? dsout : (U + (size_t)(which - 1) * NN * 128);
    int row0 = blockIdx.y * 128;

    __shared__ float As[2][8][128];
    __shared__ float Bs[2][8][128];

    int t  = threadIdx.x;
    int ty = t >> 4, tx = t & 15;

    int arow = t >> 1;
    int acol = (t & 1) * 4;
    int am   = min(row0 + arow, M - 1);
    const float* Aptr = A + (size_t)am * K + acol;

    int bk_ = t >> 5;
    int bn  = (t & 31) * 4;

    float4 ar, br;
    ar = *(const float4*)(Aptr);
    br = *(const float4*)(B + (size_t)bk_ * 384 + bn);

    As[0][acol + 0][arow] = ar.x;
    As[0][acol + 1][arow] = ar.y;
    As[0][acol + 2][arow] = ar.z;
    As[0][acol + 3][arow] = ar.w;
    *(float4*)&Bs[0][bk_][bn] = br;
    __syncthreads();

    ull acc[8][4];
    #pragma unroll
    for (int i = 0; i < 8; i++)
        #pragma unroll
        for (int j = 0; j < 4; j++) acc[i][j] = 0ULL;

    const int nstage = K >> 3;
    for (int s = 0; s < nstage; s++) {
        int cur = s & 1, nxt = cur ^ 1;
        bool more = (s + 1 < nstage);
        if (more) {
            int kk = (s + 1) << 3;
            ar = *(const float4*)(Aptr + kk);
            br = *(const float4*)(B + (size_t)(kk + bk_) * 384 + bn);
        }
        #pragma unroll
        for (int k = 0; k < 8; k++) {
            float4 a0 = *(float4*)&As[cur][k][ty * 8];
            float4 a1 = *(float4*)&As[cur][k][ty * 8 + 4];
            ulonglong2 b0 = *(ulonglong2*)&Bs[cur][k][tx * 8];
            ulonglong2 b1 = *(ulonglong2*)&Bs[cur][k][tx * 8 + 4];
            ull a2[8];
            PACK2(a2[0], a0.x); PACK2(a2[1], a0.y);
            PACK2(a2[2], a0.z); PACK2(a2[3], a0.w);
            PACK2(a2[4], a1.x); PACK2(a2[5], a1.y);
            PACK2(a2[6], a1.z); PACK2(a2[7], a1.w);
            #pragma unroll
            for (int i = 0; i < 8; i++) {
                FMA2(acc[i][0], a2[i], b0.x);
                FMA2(acc[i][1], a2[i], b0.y);
                FMA2(acc[i][2], a2[i], b1.x);
                FMA2(acc[i][3], a2[i], b1.y);
            }
        }
        if (more) {
            As[nxt][acol + 0][arow] = ar.x;
            As[nxt][acol + 1][arow] = ar.y;
            As[nxt][acol + 2][arow] = ar.z;
            As[nxt][acol + 3][arow] = ar.w;
            *(float4*)&Bs[nxt][bk_][bn] = br;
        }
        __syncthreads();
    }

    int colb = tx * 8;
    float4 bs0 = *(const float4*)(bias + colb);
    float4 bs1 = *(const float4*)(bias + colb + 4);
    #pragma unroll
    for (int i = 0; i < 8; i++) {
        int row = row0 + ty * 8 + i;
        if (row >= M) continue;
        float sc = (which == 0)
                 ? (float)(__ldg(off + row + 1) - __ldg(off + row))
                 : __ldg(su + 3 * row + (which - 1));
        float v[8];
        UNPACK2(v[0], v[1], acc[i][0]);
        UNPACK2(v[2], v[3], acc[i][1]);
        UNPACK2(v[4], v[5], acc[i][2]);
        UNPACK2(v[6], v[7], acc[i][3]);
        v[0] += sc * bs0.x; v[1] += sc * bs0.y; v[2] += sc * bs0.z; v[3] += sc * bs0.w;
        v[4] += sc * bs1.x; v[5] += sc * bs1.y; v[6] += sc * bs1.z; v[7] += sc * bs1.w;
        float* cp = C + (size_t)row * 128 + colb;
        *(float4*)cp       = make_float4(v[0], v[1], v[2], v[3]);
        *(float4*)(cp + 4) = make_float4(v[4], v[5], v[6], v[7]);
    }
}

// ================= dv gather: s0*v_j + U (sequential eout) =================
__global__ void __launch_bounds__(128)
gather_kernel(const int* __restrict__ off, const int2* __restrict__ ij,
              const float* __restrict__ v_j, const float* __restrict__ eout,
              const float* __restrict__ U, float* __restrict__ dvout) {
    int i = blockIdx.x;
    int f = threadIdx.x;
    int s = off[i], t = off[i + 1];
    float a0 = 0.f, a1 = 0.f, a2 = 0.f;
    for (int p = s; p < t; p++) {
        int jj = __ldg(&ij[p].y);
        float s0 = __ldg(eout + (size_t)p * 128 + f);
        const float* vj = v_j + ((size_t)jj * FF + f) * 3;
        a0 += s0 * vj[0];
        a1 += s0 * vj[1];
        a2 += s0 * vj[2];
    }
    size_t idx = (size_t)i * 128 + f;
    const size_t pl = (size_t)NN * 128;
    float* dv = dvout + idx * 3;
    dv[0] = a0 + __ldg(U + idx);
    dv[1] = a1 + __ldg(U + pl + idx);
    dv[2] = a2 + __ldg(U + 2 * pl + idx);
}

// ================= B pre-permutation =================
__global__ void conv_B(const float* __restrict__ W, uint32_t* __restrict__ out,
                       int N, int nst, int Kreal, int Nld) {
    int i = blockIdx.x * 256 + threadIdx.x;
    int total = N * nst * 16;
    if (i >= total) return;
    int n = i / (nst * 16);
    int rem = i % (nst * 16);
    int s = rem >> 4, p = rem & 15;
    int bp = (p & 3) * 4 + (p >> 2);
    int k = s * 32 + bp * 2;
    float lo = (k < Kreal)     ? W[(size_t)k * Nld + n]       : 0.f;
    float hi = (k + 1 < Kreal) ? W[(size_t)(k + 1) * Nld + n] : 0.f;
    __half2 h = __floats2half2_rn(lo, hi);
    out[i] = *(uint32_t*)&h;
}

__global__ void __launch_bounds__(128) ln_kernel(const float* __restrict__ s,
                                                 const float* __restrict__ gam,
                                                 const float* __restrict__ bet,
                                                 float* __restrict__ x) {
    int n = blockIdx.x, t = threadIdx.x;
    float v = s[(size_t)n * FF + t];
    float s1 = v, s2 = v * v;
    #pragma unroll
    for (int o = 16; o; o >>= 1) {
        s1 += __shfl_down_sync(0xffffffffu, s1, o);
        s2 += __shfl_down_sync(0xffffffffu, s2, o);
    }
    __shared__ float p1[4], p2[4], mv[2];
    if ((t & 31) == 0) { p1[t >> 5] = s1; p2[t >> 5] = s2; }
    __syncthreads();
    if (t == 0) {
        float a = p1[0] + p1[1] + p1[2] + p1[3];
        float c = p2[0] + p2[1] + p2[2] + p2[3];
        float m = a / 128.f;
        mv[0] = m;
        mv[1] = rsqrtf(c / 128.f - m * m + 1e-5f);
    }
    __syncthreads();
    x[(size_t)n * FF + t] = (v - mv[0]) * mv[1] * gam[t] + bet[t];
}

// ================= qkv: fused 3-way f32x2 SGEMM =================
__global__ void __launch_bounds__(256, 2)
qkv_gemm(const float* __restrict__ Xin,
         const float* __restrict__ Wq, const float* __restrict__ Wk,
         const float* __restrict__ Wv,
         const float* __restrict__ bq, const float* __restrict__ bk,
         const float* __restrict__ bv,
         float* __restrict__ qkvout) {
    const int M = NN, N = 512, K = 128, lda = 128, ldc = 1536;
    int which = blockIdx.x >> 2;
    const float* B    = (which == 0) ? Wq : ((which == 1) ? Wk : Wv);
    const float* bias = (which == 0) ? bq : ((which == 1) ? bk : bv);
    float* C = qkvout + which * 512;
    int col0 = (blockIdx.x & 3) * 128;
    int row0 = blockIdx.y * 128;

    __shared__ float As[2][8][128];
    __shared__ float Bs[2][8][128];

    int t  = threadIdx.x;
    int ty = t >> 4, tx = t & 15;

    int arow = t >> 1;
    int acol = (t & 1) * 4;
    int am   = min(row0 + arow, M - 1);
    const float* Aptr = Xin + (size_t)am * lda + acol;

    int bk_ = t >> 5;
    int bn  = (t & 31) * 4;

    float4 ar, br;
    ar = *(const float4*)(Aptr);
    br = *(const float4*)(B + (size_t)bk_ * N + col0 + bn);

    As[0][acol + 0][arow] = ar.x;
    As[0][acol + 1][arow] = ar.y;
    As[0][acol + 2][arow] = ar.z;
    As[0][acol + 3][arow] = ar.w;
    *(float4*)&Bs[0][bk_][bn] = br;
    __syncthreads();

    ull acc[8][4];
    #pragma unroll
    for (int i = 0; i < 8; i++)
        #pragma unroll
        for (int j = 0; j < 4; j++) acc[i][j] = 0ULL;

    const int nstage = K >> 3;
    for (int s = 0; s < nstage; s++) {
        int cur = s & 1, nxt = cur ^ 1;
        bool more = (s + 1 < nstage);
        if (more) {
            int kk = (s + 1) << 3;
            ar = *(const float4*)(Aptr + kk);
            br = *(const float4*)(B + (size_t)(kk + bk_) * N + col0 + bn);
        }
        #pragma unroll
        for (int k = 0; k < 8; k++) {
            float4 a0 = *(float4*)&As[cur][k][ty * 8];
            float4 a1 = *(float4*)&As[cur][k][ty * 8 + 4];
            ulonglong2 b0 = *(ulonglong2*)&Bs[cur][k][tx * 8];
            ulonglong2 b1 = *(ulonglong2*)&Bs[cur][k][tx * 8 + 4];
            ull a2[8];
            PACK2(a2[0], a0.x); PACK2(a2[1], a0.y);
            PACK2(a2[2], a0.z); PACK2(a2[3], a0.w);
            PACK2(a2[4], a1.x); PACK2(a2[5], a1.y);
            PACK2(a2[6], a1.z); PACK2(a2[7], a1.w);
            #pragma unroll
            for (int i = 0; i < 8; i++) {
                FMA2(acc[i][0], a2[i], b0.x);
                FMA2(acc[i][1], a2[i], b0.y);
                FMA2(acc[i][2], a2[i], b1.x);
                FMA2(acc[i][3], a2[i], b1.y);
            }
        }
        if (more) {
            As[nxt][acol + 0][arow] = ar.x;
            As[nxt][acol + 1][arow] = ar.y;
            As[nxt][acol + 2][arow] = ar.z;
            As[nxt][acol + 3][arow] = ar.w;
            *(float4*)&Bs[nxt][bk_][bn] = br;
        }
        __syncthreads();
    }

    int colb = col0 + tx * 8;
    float4 bs0 = *(const float4*)(bias + colb);
    float4 bs1 = *(const float4*)(bias + colb + 4);
    #pragma unroll
    for (int i = 0; i < 8; i++) {
        int row = row0 + ty * 8 + i;
        if (row >= M) continue;
        float v[8];
        UNPACK2(v[0], v[1], acc[i][0]);
        UNPACK2(v[2], v[3], acc[i][1]);
        UNPACK2(v[4], v[5], acc[i][2]);
        UNPACK2(v[6], v[7], acc[i][3]);
        v[0] += bs0.x; v[1] += bs0.y; v[2] += bs0.z; v[3] += bs0.w;
        v[4] += bs1.x; v[5] += bs1.y; v[6] += bs1.z; v[7] += bs1.w;
        float* cp = C + (size_t)row * ldc + colb;
        *(float4*)cp       = make_float4(v[0], v[1], v[2], v[3]);
        *(float4*)(cp + 4) = make_float4(v[4], v[5], v[6], v[7]);
    }
}

// ================= attn + msg: warp-per-edge (p-space) =================
__global__ void __launch_bounds__(256) attn_msg(const float* __restrict__ qkv,
                                                const __half* __restrict__ dkdv,
                                                const int2* __restrict__ ij,
                                                __half* __restrict__ msg) {
    int p = blockIdx.x * 8 + (threadIdx.x >> 5);
    if (p >= NE) return;
    int l = threadIdx.x & 31;
    int2 eij = __ldg(&ij[p]);
    int i = eij.x, j = eij.y;
    const float4* q4 = (const float4*)(qkv + (size_t)i * 1536);
    const float4* k4 = (const float4*)(qkv + (size_t)j * 1536 + 512);
    const float4* v4 = (const float4*)(qkv + (size_t)j * 1536 + 1024);
    const uint2* dk2 = (const uint2*)(dkdv + (size_t)p * 1024);
    const uint2* dv2 = dk2 + 128;

    float4 qv[4], kv[4], vv[4];
    uint2 dkv[4], dvv[4];
    #pragma unroll
    for (int h = 0; h < 4; h++) {
        int idx = h * 32 + l;
        qv[h] = q4[idx]; kv[h] = k4[idx]; vv[h] = v4[idx];
        dkv[h] = dk2[idx]; dvv[h] = dv2[idx];
    }
    float pr[4];
    #pragma unroll
    for (int h = 0; h < 4; h++) {
        float2 f0 = __half22float2(*(__half2*)&dkv[h].x);
        float2 f1 = __half22float2(*(__half2*)&dkv[h].y);
        pr[h] = qv[h].x * kv[h].x * f0.x + qv[h].y * kv[h].y * f0.y
              + qv[h].z * kv[h].z * f1.x + qv[h].w * kv[h].w * f1.y;
    }
    #pragma unroll
    for (int o = 16; o; o >>= 1)
        #pragma unroll
        for (int h = 0; h < 4; h++) pr[h] += __shfl_xor_sync(0xffffffffu, pr[h], o);

    __half* mrow = msg + (size_t)p * 512;
    #pragma unroll
    for (int h = 0; h < 4; h++) {
        float at = silu_f(pr[h]);
        float2 g0 = __half22float2(*(__half2*)&dvv[h].x);
        float2 g1 = __half22float2(*(__half2*)&dvv[h].y);
        __half2 m0 = __floats2half2_rn(vv[h].x * g0.x * at, vv[h].y * g0.y * at);
        __half2 m1 = __floats2half2_rn(vv[h].z * g1.x * at, vv[h].w * g1.y * at);
        uint2 o2;
        o2.x = *(uint32_t*)&m0;
        o2.y = *(uint32_t*)&m1;
        *(uint2*)(mrow + h * 128 + l * 4) = o2;
    }
}

// ================= fp16 mma GEMM (2 CTAs/SM) =================
// EPI=0: dk/dv — silu + half store to C at cols n0s.
// EPI=1: s0 GEMM — biased float store to eout (stride 128).
#define SROWU 20
#define ABUFU (128 * SROWU)

template <int EPI>
__global__ void __launch_bounds__(256, 2)
mma_fp16(const __half* __restrict__ A, const uint32_t* __restrict__ Bp,
         const float* __restrict__ bias, __half* __restrict__ C, int ldc,
         float* __restrict__ eout,
         int M, int lda, int nstage) {
    extern __shared__ uint32_t sm[];
    const uint32_t sA = smem_u32(sm);
    const uint32_t sB0 = sA + 2 * ABUFU * 4;

    const int tid = threadIdx.x;
    const int wid = tid >> 5, lid = tid & 31;
    const int gq = lid >> 2, tig = lid & 3;
    const int wM = wid >> 1, wN = wid & 1;
    const int row0 = (EPI == 1 ? blockIdx.x : blockIdx.y) * 128;
    const int n0s  = (EPI == 1 ? 0 : blockIdx.x * 128);

    float acc[2][8][4];
    #pragma unroll
    for (int a = 0; a < 2; a++)
        #pragma unroll
        for (int b = 0; b < 8; b++)
            #pragma unroll
            for (int c = 0; c < 4; c++) acc[a][b][c] = 0.f;

    const int arow = tid >> 1, ac2 = (tid & 1) * 2;
    const __half* aRow = A + (size_t)min(row0 + arow, M - 1) * lda;

    auto stage_A = [&](int s, int buf) {
        const __half* src = aRow + s * 32 + ac2 * 8;
        uint32_t dst = sA + (buf * ABUFU + arow * SROWU + ac2 * 4) * 4;
        CP_ASYNC16(dst, src);
        CP_ASYNC16(dst + 16, src + 8);
    };

    auto stage_B = [&](int s, int buf) {
        #pragma unroll
        for (int i = 0; i < 2; i++) {
            int c = tid + i * 256;
            int n = c >> 2, q = c & 3;
            int ng = n0s + n;
            const uint32_t* src = Bp + ((size_t)ng * nstage + s) * 16 + q * 4;
            uint32_t dst = sB0 + (buf * ABUFU + n * SROWU + q * 4) * 4;
            CP_ASYNC16(dst, src);
        }
    };

    stage_A(0, 0);
    stage_B(0, 0);
    CP_COMMIT();
    CP_WAIT0();
    __syncthreads();

    for (int s = 0; s < nstage; s++) {
        int cur = s & 1;
        bool more = (s + 1 < nstage);
        if (more) {
            stage_A(s + 1, cur ^ 1);
            stage_B(s + 1, cur ^ 1);
            CP_COMMIT();
        }

        uint32_t af[2][2][4];
        const uint32_t* Ab = sm + cur * ABUFU;
        #pragma unroll
        for (int mf = 0; mf < 2; mf++) {
            int r0 = wM * 32 + mf * 16 + gq;
            const uint32_t* p0 = Ab + r0 * SROWU;
            const uint32_t* p1 = Ab + (r0 + 8) * SROWU;
            #pragma unroll
            for (int ks = 0; ks < 2; ks++) {
                af[mf][ks][0] = p0[tig + 8 * ks];
                af[mf][ks][1] = p1[tig + 8 * ks];
                af[mf][ks][2] = p0[tig + 4 + 8 * ks];
                af[mf][ks][3] = p1[tig + 4 + 8 * ks];
            }
        }
        const uint32_t* Bb = sm + 2 * ABUFU + cur * ABUFU;
        #pragma unroll
        for (int nf = 0; nf < 8; nf++) {
            int n = wN * 64 + nf * 8 + gq;
            uint4 bv = *(const uint4*)(Bb + n * SROWU + tig * 4);
            MMA_F16(acc[0][nf], af[0][0][0], af[0][0][1], af[0][0][2], af[0][0][3], bv.x, bv.y);
            MMA_F16(acc[1][nf], af[1][0][0], af[1][0][1], af[1][0][2], af[1][0][3], bv.x, bv.y);
            MMA_F16(acc[0][nf], af[0][1][0], af[0][1][1], af[0][1][2], af[0][1][3], bv.z, bv.w);
            MMA_F16(acc[1][nf], af[1][1][0], af[1][1][1], af[1][1][2], af[1][1][3], bv.z, bv.w);
        }
        if (more) CP_WAIT0();
        __syncthreads();
    }

    if constexpr (EPI == 0) {
        #pragma unroll
        for (int mf = 0; mf < 2; mf++)
        #pragma unroll
        for (int rs = 0; rs < 2; rs++) {
            int r = row0 + wM * 32 + mf * 16 + rs * 8 + gq;
            if (r >= M) continue;
            #pragma unroll
            for (int nf = 0; nf < 8; nf++) {
                int nc = wN * 64 + nf * 8 + tig * 2;
                float v0 = silu_f(acc[mf][nf][rs * 2 + 0] + __ldg(bias + n0s + nc));
                float v1 = silu_f(acc[mf][nf][rs * 2 + 1] + __ldg(bias + n0s + nc + 1));
                *(__half2*)(C + (size_t)r * ldc + n0s + nc) = __floats2half2_rn(v0, v1);
            }
        }
    } else {
        #pragma unroll
        for (int mf = 0; mf < 2; mf++)
        #pragma unroll
        for (int rs = 0; rs < 2; rs++) {
            int e = row0 + wM * 32 + mf * 16 + rs * 8 + gq;
            if (e >= M) continue;
            float* o = eout + (size_t)e * 128;
            #pragma unroll
            for (int nf = 0; nf < 8; nf++) {
                int f = wN * 64 + nf * 8 + tig * 2;
                float v0 = acc[mf][nf][rs * 2 + 0] + __ldg(bias + f);
                float v1 = acc[mf][nf][rs * 2 + 1] + __ldg(bias + f + 1);
                *(float2*)(o + f) = make_float2(v0, v1);
            }
        }
    }
}

// ================= launch =================
extern "C" void kernel_launch(void* const* d_in, const int* in_sizes, int n_in,
                              void* d_out, int out_size) {
    const float* s_j  = (const float*)d_in[0];
    const float* v_j  = (const float*)d_in[1];
    const float* r_ij = (const float*)d_in[2];
    const int*   nbrs = (const int*)  d_in[3];
    const float* ln_g = (const float*)d_in[4];
    const float* ln_b = (const float*)d_in[5];
    const float* Wq   = (const float*)d_in[6];
    const float* bq   = (const float*)d_in[7];
    const float* Wk   = (const float*)d_in[8];
    const float* bk   = (const float*)d_in[9];
    const float* Wv   = (const float*)d_in[10];
    const float* bv   = (const float*)d_in[11];
    const float* Wdk  = (const float*)d_in[12];
    const float* bdk  = (const float*)d_in[13];
    const float* Wdv  = (const float*)d_in[14];
    const float* bdv  = (const float*)d_in[15];
    const float* Wd   = (const float*)d_in[16];
    const float* bd   = (const float*)d_in[17];
    float* out = (float*)d_out;

    float *x, *qkv, *unitc, *eout, *ms, *su, *U;
    __half *rbf, *dkdv, *msg;
    int2* ij;
    uint32_t *wdp, *wdkp, *wdvp;
    int *cnt, *off, *pos, *eidx;
    cudaGetSymbolAddress((void**)&x,    g_x);
    cudaGetSymbolAddress((void**)&qkv,  g_qkv);
    cudaGetSymbolAddress((void**)&rbf,  g_rbf);
    cudaGetSymbolAddress((void**)&unitc, g_unitc);
    cudaGetSymbolAddress((void**)&ij,   g_ij);
    cudaGetSymbolAddress((void**)&dkdv, g_dkdv);
    cudaGetSymbolAddress((void**)&msg,  g_msg);
    cudaGetSymbolAddress((void**)&eout, g_eout);
    cudaGetSymbolAddress((void**)&ms,   g_ms);
    cudaGetSymbolAddress((void**)&su,   g_su);
    cudaGetSymbolAddress((void**)&U,    g_u);
    cudaGetSymbolAddress((void**)&wdp,  g_wdp);
    cudaGetSymbolAddress((void**)&wdkp, g_wdkp);
    cudaGetSymbolAddress((void**)&wdvp, g_wdvp);
    cudaGetSymbolAddress((void**)&cnt,  g_cnt);
    cudaGetSymbolAddress((void**)&off,  g_off);
    cudaGetSymbolAddress((void**)&pos,  g_pos);
    cudaGetSymbolAddress((void**)&eidx, g_eidx);

    const int SMEM_MMA = 4 * ABUFU * 4;   // 40960
    cudaFuncSetAttribute(mma_fp16<0>, cudaFuncAttributeMaxDynamicSharedMemorySize, SMEM_MMA);
    cudaFuncSetAttribute(mma_fp16<1>, cudaFuncAttributeMaxDynamicSharedMemorySize, SMEM_MMA);

    // CSR build
    zero_int<<<(NN + 255) / 256, 256>>>(cnt, NN);
    csr_hist<<<(NE + 255) / 256, 256>>>(nbrs, cnt);
    csr_scan<<<1, 256>>>(cnt, off, pos);
    csr_scatter<<<(NE + 255) / 256, 256>>>(nbrs, pos, eidx);

    // weight pre-permutation
    conv_B<<<(128 * 16 * 16 + 255) / 256, 256>>>(Wd, wdp, 128, 16, 512, 384);
    conv_B<<<(512 * 2 * 16 + 255) / 256, 256>>>(Wdk, wdkp, 512, 2, 50, 512);
    conv_B<<<(512 * 2 * 16 + 255) / 256, 256>>>(Wdv, wdvp, 512, 2, 50, 512);

    ln_kernel<<<NN, 128>>>(s_j, ln_g, ln_b, x);

    dim3 gq3(12, (NN + 127) / 128);
    qkv_gemm<<<gq3, 256>>>(x, Wq, Wk, Wv, bq, bk, bv, qkv);

    // edge prep in CSR order (after csr_scatter)
    edge_prep<<<(NE + 255) / 256, 256>>>(eidx, nbrs, r_ij, rbf, unitc, ij);

    int mtiles = (NE + 127) / 128;   // 1954
    dim3 ge(4, mtiles);
    mma_fp16<0><<<ge, 256, SMEM_MMA>>>(rbf, wdkp, bdk, dkdv, 1024, nullptr,
                                       NE, RBFP, 2);
    mma_fp16<0><<<ge, 256, SMEM_MMA>>>(rbf, wdvp, bdv, dkdv + 512, 1024, nullptr,
                                       NE, RBFP, 2);

    attn_msg<<<(NE + 7) / 8, 256>>>(qkv, dkdv, ij, msg);

    // node-side sums: ms, T0..T2, su
    msg_segsum<<<NN, 128>>>(off, msg, unitc, ms, su);

    // node GEMMs: ds (which=0) + U planes (which=1..3)
    dim3 gnode(4, (NN + 127) / 128);
    node_gemm<<<gnode, 256>>>(ms, Wd, bd, off, su, out, U);

    // edge GEMM: s0 only
    mma_fp16<1><<<mtiles, 256, SMEM_MMA>>>(msg, wdp, bd, nullptr, 0, eout,
                                           NE, 512, 16);

    gather_kernel<<<NN, 128>>>(off, ij, v_j, eout, U, out + NN * FF);
}

// round 16
// speedup vs baseline: 1.1571x; 1.0384x over previous
#include <cuda_runtime.h>
#include <cuda_fp16.h>
#include <math.h>
#include <stdint.h>

#define NN   10000
#define NE   250000
#define FF   128
#define NRBF 50
#define RBFP 64

typedef unsigned long long ull;

// ---------------- scratch (all edge arrays in CSR "p" order) ----------------
__device__ float  g_x[NN * FF];
__device__ float  g_qkv[NN * 3 * 512];
__device__ __half g_rbf[(size_t)NE * RBFP];
__device__ float  g_unitc[(size_t)NE * 3];
__device__ int2   g_ij[NE];
__device__ __half g_dkdv[(size_t)NE * 1024];
__device__ __half g_msg[(size_t)NE * 512];
__device__ float  g_eout[(size_t)NE * 128];
__device__ float  g_ms[(size_t)4 * NN * 512];     // [ms | T0 | T1 | T2]
__device__ float  g_su[NN * 3];
__device__ float  g_u[(size_t)3 * NN * 128];
__device__ uint32_t g_wdp[128 * 16 * 16];
__device__ uint32_t g_wdkp[512 * 2 * 16];
__device__ uint32_t g_wdvp[512 * 2 * 16];
__device__ int g_cnt[NN];
__device__ int g_off[NN + 1];
__device__ int g_pos[NN];
__device__ int g_eidx[NE];

#define FMA2(acc, a, b) asm("fma.rn.f32x2 %0, %1, %2, %0;" : "+l"(acc) : "l"(a), "l"(b))
#define PACK2(dst, f)   asm("mov.b64 %0, {%1, %1};" : "=l"(dst) : "f"(f))
#define UNPACK2(lo, hi, v) asm("mov.b64 {%0, %1}, %2;" : "=f"(lo), "=f"(hi) : "l"(v))

__device__ __forceinline__ uint32_t smem_u32(const void* p) {
    uint32_t a;
    asm("{ .reg .u64 t; cvta.to.shared.u64 t, %1; cvt.u32.u64 %0, t; }" : "=r"(a) : "l"(p));
    return a;
}
__device__ __forceinline__ float silu_f(float v) {
    return v / (1.f + __expf(-v));
}

#define MMA_F16(c, a0, a1, a2, a3, b0, b1)                                \
    asm volatile("mma.sync.aligned.m16n8k16.row.col.f32.f16.f16.f32 "     \
        "{%0,%1,%2,%3}, {%4,%5,%6,%7}, {%8,%9}, {%0,%1,%2,%3};"           \
        : "+f"((c)[0]), "+f"((c)[1]), "+f"((c)[2]), "+f"((c)[3])          \
        : "r"(a0), "r"(a1), "r"(a2), "r"(a3), "r"(b0), "r"(b1))

#define CP_ASYNC16(dst, src) \
    asm volatile("cp.async.ca.shared.global [%0], [%1], 16;" :: "r"(dst), "l"(src))
#define CP_COMMIT() asm volatile("cp.async.commit_group;" ::: "memory")
#define CP_WAIT0()  asm volatile("cp.async.wait_group 0;" ::: "memory")

// ================= CSR build =================
__global__ void zero_int(int* __restrict__ p, int n) {
    int i = blockIdx.x * blockDim.x + threadIdx.x;
    if (i < n) p[i] = 0;
}
__global__ void csr_hist(const int* __restrict__ nbrs, int* __restrict__ cnt) {
    int e = blockIdx.x * 256 + threadIdx.x;
    if (e < NE) atomicAdd(&cnt[nbrs[2 * e]], 1);
}
__global__ void __launch_bounds__(256) csr_scan(const int* __restrict__ cnt,
                                                int* __restrict__ off,
                                                int* __restrict__ pos) {
    __shared__ int base;
    __shared__ int wsum[8];
    if (threadIdx.x == 0) base = 0;
    __syncthreads();
    for (int c0 = 0; c0 < NN; c0 += 256) {
        int i = c0 + threadIdx.x;
        int v = (i < NN) ? cnt[i] : 0;
        int lane = threadIdx.x & 31, w = threadIdx.x >> 5;
        int x = v;
        #pragma unroll
        for (int o = 1; o < 32; o <<= 1) {
            int y = __shfl_up_sync(0xffffffffu, x, o);
            if (lane >= o) x += y;
        }
        if (lane == 31) wsum[w] = x;
        __syncthreads();
        int add = 0;
        #pragma unroll
        for (int k = 0; k < 8; k++) if (k < w) add += wsum[k];
        int incl = x + add;
        if (i < NN) {
            int excl = base + incl - v;
            off[i] = excl;
            pos[i] = excl;
        }
        __syncthreads();
        if (threadIdx.x == 255) base += incl;
        __syncthreads();
    }
    if (threadIdx.x == 0) off[NN] = base;
}
__global__ void csr_scatter(const int* __restrict__ nbrs, int* __restrict__ pos,
                            int* __restrict__ eidx) {
    int e = blockIdx.x * 256 + threadIdx.x;
    if (e < NE) {
        int p = atomicAdd(&pos[nbrs[2 * e]], 1);
        eidx[p] = e;
    }
}

// ================= edge prep in CSR order =================
__global__ void __launch_bounds__(256) edge_prep(const int* __restrict__ eidx,
                                                 const int* __restrict__ nbrs,
                                                 const float* __restrict__ r,
                                                 __half* __restrict__ rbf,
                                                 float* __restrict__ unitc,
                                                 int2* __restrict__ ij) {
    int p = blockIdx.x * 256 + threadIdx.x;
    if (p >= NE) return;
    int e = __ldg(eidx + p);
    ij[p] = make_int2(__ldg(nbrs + 2 * e), __ldg(nbrs + 2 * e + 1));
    float x = __ldg(r + 3 * e), y = __ldg(r + 3 * e + 1), z = __ldg(r + 3 * e + 2);
    float d = sqrtf(x * x + y * y + z * z + 3e-15f);
    float inv = 1.f / d;
    unitc[3 * p] = x * inv; unitc[3 * p + 1] = y * inv; unitc[3 * p + 2] = z * inv;
    const float width = 5.0f / 49.0f;
    const float gam = 0.5f / (width * width);
    __half2 buf[32];
    #pragma unroll
    for (int k2 = 0; k2 < 32; k2++) {
        int k0 = k2 * 2, k1 = k2 * 2 + 1;
        float d0 = d - (float)k0 * width;
        float d1 = d - (float)k1 * width;
        float v0 = (k0 < NRBF) ? __expf(-gam * d0 * d0) : 0.f;
        float v1 = (k1 < NRBF) ? __expf(-gam * d1 * d1) : 0.f;
        buf[k2] = __floats2half2_rn(v0, v1);
    }
    uint4* dst = (uint4*)(rbf + (size_t)p * RBFP);
    const uint4* src = (const uint4*)buf;
    #pragma unroll
    for (int q = 0; q < 8; q++) dst[q] = src[q];
}

// ================= msg segment-sum + unit-weighted sums =================
__global__ void __launch_bounds__(128)
msg_segsum(const int* __restrict__ off,
           const __half* __restrict__ msg, const float* __restrict__ unitc,
           float* __restrict__ ms, float* __restrict__ su) {
    int i = blockIdx.x;
    int t = threadIdx.x;
    int s = off[i], tend = off[i + 1];
    float a[4]  = {0.f, 0.f, 0.f, 0.f};
    float t0[4] = {0.f, 0.f, 0.f, 0.f};
    float t1[4] = {0.f, 0.f, 0.f, 0.f};
    float t2[4] = {0.f, 0.f, 0.f, 0.f};
    float sux = 0.f, suy = 0.f, suz = 0.f;
    for (int p = s; p < tend; p++) {
        float ux = __ldg(unitc + 3 * p), uy = __ldg(unitc + 3 * p + 1), uz = __ldg(unitc + 3 * p + 2);
        uint2 m = *(const uint2*)(msg + (size_t)p * 512 + t * 4);
        float2 x0 = __half22float2(*(__half2*)&m.x);
        float2 x1 = __half22float2(*(__half2*)&m.y);
        float v[4] = {x0.x, x0.y, x1.x, x1.y};
        #pragma unroll
        for (int q = 0; q < 4; q++) {
            a[q]  += v[q];
            t0[q] += v[q] * ux;
            t1[q] += v[q] * uy;
            t2[q] += v[q] * uz;
        }
        sux += ux; suy += uy; suz += uz;
    }
    size_t base = (size_t)i * 512 + t * 4;
    const size_t plane = (size_t)NN * 512;
    *(float4*)(ms + base)             = make_float4(a[0], a[1], a[2], a[3]);
    *(float4*)(ms + plane + base)     = make_float4(t0[0], t0[1], t0[2], t0[3]);
    *(float4*)(ms + 2 * plane + base) = make_float4(t1[0], t1[1], t1[2], t1[3]);
    *(float4*)(ms + 3 * plane + base) = make_float4(t2[0], t2[1], t2[2], t2[3]);
    if (t == 0) {
        su[3 * i] = sux; su[3 * i + 1] = suy; su[3 * i + 2] = suz;
    }
}

// ================= node GEMM: ds and U planes =================
__global__ void __launch_bounds__(256, 2)
node_gemm(const float* __restrict__ msbase, const float* __restrict__ Wd,
          const float* __restrict__ bd, const int* __restrict__ off,
          const float* __restrict__ su,
          float* __restrict__ dsout, float* __restrict__ U) {
    const int M = NN, K = 512;
    int which = blockIdx.x;
    const float* A    = msbase + (size_t)which * NN * 512;
    const float* B    = Wd + ((which == 0) ? 128 : 256);
    const float* bias = bd + ((which == 0) ? 128 : 256);
    float* C = (which == 0) ? dsout : (U + (size_t)(which - 1) * NN * 128);
    int row0 = blockIdx.y * 128;

    __shared__ float As[2][8][128];
    __shared__ float Bs[2][8][128];

    int t  = threadIdx.x;
    int ty = t >> 4, tx = t & 15;

    int arow = t >> 1;
    int acol = (t & 1) * 4;
    int am   = min(row0 + arow, M - 1);
    const float* Aptr = A + (size_t)am * K + acol;

    int bk_ = t >> 5;
    int bn  = (t & 31) * 4;

    float4 ar, br;
    ar = *(const float4*)(Aptr);
    br = *(const float4*)(B + (size_t)bk_ * 384 + bn);

    As[0][acol + 0][arow] = ar.x;
    As[0][acol + 1][arow] = ar.y;
    As[0][acol + 2][arow] = ar.z;
    As[0][acol + 3][arow] = ar.w;
    *(float4*)&Bs[0][bk_][bn] = br;
    __syncthreads();

    ull acc[8][4];
    #pragma unroll
    for (int i = 0; i < 8; i++)
        #pragma unroll
        for (int j = 0; j < 4; j++) acc[i][j] = 0ULL;

    const int nstage = K >> 3;
    for (int s = 0; s < nstage; s++) {
        int cur = s & 1, nxt = cur ^ 1;
        bool more = (s + 1 < nstage);
        if (more) {
            int kk = (s + 1) << 3;
            ar = *(const float4*)(Aptr + kk);
            br = *(const float4*)(B + (size_t)(kk + bk_) * 384 + bn);
        }
        #pragma unroll
        for (int k = 0; k < 8; k++) {
            float4 a0 = *(float4*)&As[cur][k][ty * 8];
            float4 a1 = *(float4*)&As[cur][k][ty * 8 + 4];
            ulonglong2 b0 = *(ulonglong2*)&Bs[cur][k][tx * 8];
            ulonglong2 b1 = *(ulonglong2*)&Bs[cur][k][tx * 8 + 4];
            ull a2[8];
            PACK2(a2[0], a0.x); PACK2(a2[1], a0.y);
            PACK2(a2[2], a0.z); PACK2(a2[3], a0.w);
            PACK2(a2[4], a1.x); PACK2(a2[5], a1.y);
            PACK2(a2[6], a1.z); PACK2(a2[7], a1.w);
            #pragma unroll
            for (int i = 0; i < 8; i++) {
                FMA2(acc[i][0], a2[i], b0.x);
                FMA2(acc[i][1], a2[i], b0.y);
                FMA2(acc[i][2], a2[i], b1.x);
                FMA2(acc[i][3], a2[i], b1.y);
            }
        }
        if (more) {
            As[nxt][acol + 0][arow] = ar.x;
            As[nxt][acol + 1][arow] = ar.y;
            As[nxt][acol + 2][arow] = ar.z;
            As[nxt][acol + 3][arow] = ar.w;
            *(float4*)&Bs[nxt][bk_][bn] = br;
        }
        __syncthreads();
    }

    int colb = tx * 8;
    float4 bs0 = *(const float4*)(bias + colb);
    float4 bs1 = *(const float4*)(bias + colb + 4);
    #pragma unroll
    for (int i = 0; i < 8; i++) {
        int row = row0 + ty * 8 + i;
        if (row >= M) continue;
        float sc = (which == 0)
                 ? (float)(__ldg(off + row + 1) - __ldg(off + row))
                 : __ldg(su + 3 * row + (which - 1));
        float v[8];
        UNPACK2(v[0], v[1], acc[i][0]);
        UNPACK2(v[2], v[3], acc[i][1]);
        UNPACK2(v[4], v[5], acc[i][2]);
        UNPACK2(v[6], v[7], acc[i][3]);
        v[0] += sc * bs0.x; v[1] += sc * bs0.y; v[2] += sc * bs0.z; v[3] += sc * bs0.w;
        v[4] += sc * bs1.x; v[5] += sc * bs1.y; v[6] += sc * bs1.z; v[7] += sc * bs1.w;
        float* cp = C + (size_t)row * 128 + colb;
        *(float4*)cp       = make_float4(v[0], v[1], v[2], v[3]);
        *(float4*)(cp + 4) = make_float4(v[4], v[5], v[6], v[7]);
    }
}

// ================= dv gather: s0*v_j + U =================
__global__ void __launch_bounds__(128)
gather_kernel(const int* __restrict__ off, const int2* __restrict__ ij,
              const float* __restrict__ v_j, const float* __restrict__ eout,
              const float* __restrict__ U, float* __restrict__ dvout) {
    int i = blockIdx.x;
    int f = threadIdx.x;
    int s = off[i], t = off[i + 1];
    float a0 = 0.f, a1 = 0.f, a2 = 0.f;
    for (int p = s; p < t; p++) {
        int jj = __ldg(&ij[p].y);
        float s0 = __ldg(eout + (size_t)p * 128 + f);
        const float* vj = v_j + ((size_t)jj * FF + f) * 3;
        a0 += s0 * vj[0];
        a1 += s0 * vj[1];
        a2 += s0 * vj[2];
    }
    size_t idx = (size_t)i * 128 + f;
    const size_t pl = (size_t)NN * 128;
    float* dv = dvout + idx * 3;
    dv[0] = a0 + __ldg(U + idx);
    dv[1] = a1 + __ldg(U + pl + idx);
    dv[2] = a2 + __ldg(U + 2 * pl + idx);
}

// ================= B pre-permutation =================
__global__ void conv_B(const float* __restrict__ W, uint32_t* __restrict__ out,
                       int N, int nst, int Kreal, int Nld) {
    int i = blockIdx.x * 256 + threadIdx.x;
    int total = N * nst * 16;
    if (i >= total) return;
    int n = i / (nst * 16);
    int rem = i % (nst * 16);
    int s = rem >> 4, p = rem & 15;
    int bp = (p & 3) * 4 + (p >> 2);
    int k = s * 32 + bp * 2;
    float lo = (k < Kreal)     ? W[(size_t)k * Nld + n]       : 0.f;
    float hi = (k + 1 < Kreal) ? W[(size_t)(k + 1) * Nld + n] : 0.f;
    __half2 h = __floats2half2_rn(lo, hi);
    out[i] = *(uint32_t*)&h;
}

__global__ void __launch_bounds__(128) ln_kernel(const float* __restrict__ s,
                                                 const float* __restrict__ gam,
                                                 const float* __restrict__ bet,
                                                 float* __restrict__ x) {
    int n = blockIdx.x, t = threadIdx.x;
    float v = s[(size_t)n * FF + t];
    float s1 = v, s2 = v * v;
    #pragma unroll
    for (int o = 16; o; o >>= 1) {
        s1 += __shfl_down_sync(0xffffffffu, s1, o);
        s2 += __shfl_down_sync(0xffffffffu, s2, o);
    }
    __shared__ float p1[4], p2[4], mv[2];
    if ((t & 31) == 0) { p1[t >> 5] = s1; p2[t >> 5] = s2; }
    __syncthreads();
    if (t == 0) {
        float a = p1[0] + p1[1] + p1[2] + p1[3];
        float c = p2[0] + p2[1] + p2[2] + p2[3];
        float m = a / 128.f;
        mv[0] = m;
        mv[1] = rsqrtf(c / 128.f - m * m + 1e-5f);
    }
    __syncthreads();
    x[(size_t)n * FF + t] = (v - mv[0]) * mv[1] * gam[t] + bet[t];
}

// ================= qkv: fused 3-way f32x2 SGEMM =================
__global__ void __launch_bounds__(256, 2)
qkv_gemm(const float* __restrict__ Xin,
         const float* __restrict__ Wq, const float* __restrict__ Wk,
         const float* __restrict__ Wv,
         const float* __restrict__ bq, const float* __restrict__ bk,
         const float* __restrict__ bv,
         float* __restrict__ qkvout) {
    const int M = NN, N = 512, K = 128, lda = 128, ldc = 1536;
    int which = blockIdx.x >> 2;
    const float* B    = (which == 0) ? Wq : ((which == 1) ? Wk : Wv);
    const float* bias = (which == 0) ? bq : ((which == 1) ? bk : bv);
    float* C = qkvout + which * 512;
    int col0 = (blockIdx.x & 3) * 128;
    int row0 = blockIdx.y * 128;

    __shared__ float As[2][8][128];
    __shared__ float Bs[2][8][128];

    int t  = threadIdx.x;
    int ty = t >> 4, tx = t & 15;

    int arow = t >> 1;
    int acol = (t & 1) * 4;
    int am   = min(row0 + arow, M - 1);
    const float* Aptr = Xin + (size_t)am * lda + acol;

    int bk_ = t >> 5;
    int bn  = (t & 31) * 4;

    float4 ar, br;
    ar = *(const float4*)(Aptr);
    br = *(const float4*)(B + (size_t)bk_ * N + col0 + bn);

    As[0][acol + 0][arow] = ar.x;
    As[0][acol + 1][arow] = ar.y;
    As[0][acol + 2][arow] = ar.z;
    As[0][acol + 3][arow] = ar.w;
    *(float4*)&Bs[0][bk_][bn] = br;
    __syncthreads();

    ull acc[8][4];
    #pragma unroll
    for (int i = 0; i < 8; i++)
        #pragma unroll
        for (int j = 0; j < 4; j++) acc[i][j] = 0ULL;

    const int nstage = K >> 3;
    for (int s = 0; s < nstage; s++) {
        int cur = s & 1, nxt = cur ^ 1;
        bool more = (s + 1 < nstage);
        if (more) {
            int kk = (s + 1) << 3;
            ar = *(const float4*)(Aptr + kk);
            br = *(const float4*)(B + (size_t)(kk + bk_) * N + col0 + bn);
        }
        #pragma unroll
        for (int k = 0; k < 8; k++) {
            float4 a0 = *(float4*)&As[cur][k][ty * 8];
            float4 a1 = *(float4*)&As[cur][k][ty * 8 + 4];
            ulonglong2 b0 = *(ulonglong2*)&Bs[cur][k][tx * 8];
            ulonglong2 b1 = *(ulonglong2*)&Bs[cur][k][tx * 8 + 4];
            ull a2[8];
            PACK2(a2[0], a0.x); PACK2(a2[1], a0.y);
            PACK2(a2[2], a0.z); PACK2(a2[3], a0.w);
            PACK2(a2[4], a1.x); PACK2(a2[5], a1.y);
            PACK2(a2[6], a1.z); PACK2(a2[7], a1.w);
            #pragma unroll
            for (int i = 0; i < 8; i++) {
                FMA2(acc[i][0], a2[i], b0.x);
                FMA2(acc[i][1], a2[i], b0.y);
                FMA2(acc[i][2], a2[i], b1.x);
                FMA2(acc[i][3], a2[i], b1.y);
            }
        }
        if (more) {
            As[nxt][acol + 0][arow] = ar.x;
            As[nxt][acol + 1][arow] = ar.y;
            As[nxt][acol + 2][arow] = ar.z;
            As[nxt][acol + 3][arow] = ar.w;
            *(float4*)&Bs[nxt][bk_][bn] = br;
        }
        __syncthreads();
    }

    int colb = col0 + tx * 8;
    float4 bs0 = *(const float4*)(bias + colb);
    float4 bs1 = *(const float4*)(bias + colb + 4);
    #pragma unroll
    for (int i = 0; i < 8; i++) {
        int row = row0 + ty * 8 + i;
        if (row >= M) continue;
        float v[8];
        UNPACK2(v[0], v[1], acc[i][0]);
        UNPACK2(v[2], v[3], acc[i][1]);
        UNPACK2(v[4], v[5], acc[i][2]);
        UNPACK2(v[6], v[7], acc[i][3]);
        v[0] += bs0.x; v[1] += bs0.y; v[2] += bs0.z; v[3] += bs0.w;
        v[4] += bs1.x; v[5] += bs1.y; v[6] += bs1.z; v[7] += bs1.w;
        float* cp = C + (size_t)row * ldc + colb;
        *(float4*)cp       = make_float4(v[0], v[1], v[2], v[3]);
        *(float4*)(cp + 4) = make_float4(v[4], v[5], v[6], v[7]);
    }
}

// ================= attn + msg: warp-per-edge (p-space) =================
__global__ void __launch_bounds__(256) attn_msg(const float* __restrict__ qkv,
                                                const __half* __restrict__ dkdv,
                                                const int2* __restrict__ ij,
                                                __half* __restrict__ msg) {
    int p = blockIdx.x * 8 + (threadIdx.x >> 5);
    if (p >= NE) return;
    int l = threadIdx.x & 31;
    int2 eij = __ldg(&ij[p]);
    int i = eij.x, j = eij.y;
    const float4* q4 = (const float4*)(qkv + (size_t)i * 1536);
    const float4* k4 = (const float4*)(qkv + (size_t)j * 1536 + 512);
    const float4* v4 = (const float4*)(qkv + (size_t)j * 1536 + 1024);
    const uint2* dk2 = (const uint2*)(dkdv + (size_t)p * 1024);
    const uint2* dv2 = dk2 + 128;

    float4 qv[4], kv[4], vv[4];
    uint2 dkv[4], dvv[4];
    #pragma unroll
    for (int h = 0; h < 4; h++) {
        int idx = h * 32 + l;
        qv[h] = q4[idx]; kv[h] = k4[idx]; vv[h] = v4[idx];
        dkv[h] = dk2[idx]; dvv[h] = dv2[idx];
    }
    float pr[4];
    #pragma unroll
    for (int h = 0; h < 4; h++) {
        float2 f0 = __half22float2(*(__half2*)&dkv[h].x);
        float2 f1 = __half22float2(*(__half2*)&dkv[h].y);
        pr[h] = qv[h].x * kv[h].x * f0.x + qv[h].y * kv[h].y * f0.y
              + qv[h].z * kv[h].z * f1.x + qv[h].w * kv[h].w * f1.y;
    }
    #pragma unroll
    for (int o = 16; o; o >>= 1)
        #pragma unroll
        for (int h = 0; h < 4; h++) pr[h] += __shfl_xor_sync(0xffffffffu, pr[h], o);

    __half* mrow = msg + (size_t)p * 512;
    #pragma unroll
    for (int h = 0; h < 4; h++) {
        float at = silu_f(pr[h]);
        float2 g0 = __half22float2(*(__half2*)&dvv[h].x);
        float2 g1 = __half22float2(*(__half2*)&dvv[h].y);
        __half2 m0 = __floats2half2_rn(vv[h].x * g0.x * at, vv[h].y * g0.y * at);
        __half2 m1 = __floats2half2_rn(vv[h].z * g1.x * at, vv[h].w * g1.y * at);
        uint2 o2;
        o2.x = *(uint32_t*)&m0;
        o2.y = *(uint32_t*)&m1;
        *(uint2*)(mrow + h * 128 + l * 4) = o2;
    }
}

// ================= fp16 mma GEMM (2 CTAs/SM) =================
#define SROWU 20
#define ABUFU (128 * SROWU)

template <int EPI>
__global__ void __launch_bounds__(256, 2)
mma_fp16(const __half* __restrict__ A, const uint32_t* __restrict__ Bp,
         const float* __restrict__ bias, __half* __restrict__ C, int ldc,
         float* __restrict__ eout,
         int M, int lda, int nstage) {
    extern __shared__ uint32_t sm[];
    const uint32_t sA = smem_u32(sm);
    const uint32_t sB0 = sA + 2 * ABUFU * 4;

    const int tid = threadIdx.x;
    const int wid = tid >> 5, lid = tid & 31;
    const int gq = lid >> 2, tig = lid & 3;
    const int wM = wid >> 1, wN = wid & 1;
    const int row0 = (EPI == 1 ? blockIdx.x : blockIdx.y) * 128;
    const int n0s  = (EPI == 1 ? 0 : blockIdx.x * 128);

    float acc[2][8][4];
    #pragma unroll
    for (int a = 0; a < 2; a++)
        #pragma unroll
        for (int b = 0; b < 8; b++)
            #pragma unroll
            for (int c = 0; c < 4; c++) acc[a][b][c] = 0.f;

    const int arow = tid >> 1, ac2 = (tid & 1) * 2;
    const __half* aRow = A + (size_t)min(row0 + arow, M - 1) * lda;

    auto stage_A = [&](int s, int buf) {
        const __half* src = aRow + s * 32 + ac2 * 8;
        uint32_t dst = sA + (buf * ABUFU + arow * SROWU + ac2 * 4) * 4;
        CP_ASYNC16(dst, src);
        CP_ASYNC16(dst + 16, src + 8);
    };

    auto stage_B = [&](int s, int buf) {
        #pragma unroll
        for (int i = 0; i < 2; i++) {
            int c = tid + i * 256;
            int n = c >> 2, q = c & 3;
            int ng = n0s + n;
            const uint32_t* src = Bp + ((size_t)ng * nstage + s) * 16 + q * 4;
            uint32_t dst = sB0 + (buf * ABUFU + n * SROWU + q * 4) * 4;
            CP_ASYNC16(dst, src);
        }
    };

    stage_A(0, 0);
    stage_B(0, 0);
    CP_COMMIT();
    CP_WAIT0();
    __syncthreads();

    for (int s = 0; s < nstage; s++) {
        int cur = s & 1;
        bool more = (s + 1 < nstage);
        if (more) {
            stage_A(s + 1, cur ^ 1);
            stage_B(s + 1, cur ^ 1);
            CP_COMMIT();
        }

        uint32_t af[2][2][4];
        const uint32_t* Ab = sm + cur * ABUFU;
        #pragma unroll
        for (int mf = 0; mf < 2; mf++) {
            int r0 = wM * 32 + mf * 16 + gq;
            const uint32_t* p0 = Ab + r0 * SROWU;
            const uint32_t* p1 = Ab + (r0 + 8) * SROWU;
            #pragma unroll
            for (int ks = 0; ks < 2; ks++) {
                af[mf][ks][0] = p0[tig + 8 * ks];
                af[mf][ks][1] = p1[tig + 8 * ks];
                af[mf][ks][2] = p0[tig + 4 + 8 * ks];
                af[mf][ks][3] = p1[tig + 4 + 8 * ks];
            }
        }
        const uint32_t* Bb = sm + 2 * ABUFU + cur * ABUFU;
        #pragma unroll
        for (int nf = 0; nf < 8; nf++) {
            int n = wN * 64 + nf * 8 + gq;
            uint4 bv = *(const uint4*)(Bb + n * SROWU + tig * 4);
            MMA_F16(acc[0][nf], af[0][0][0], af[0][0][1], af[0][0][2], af[0][0][3], bv.x, bv.y);
            MMA_F16(acc[1][nf], af[1][0][0], af[1][0][1], af[1][0][2], af[1][0][3], bv.x, bv.y);
            MMA_F16(acc[0][nf], af[0][1][0], af[0][1][1], af[0][1][2], af[0][1][3], bv.z, bv.w);
            MMA_F16(acc[1][nf], af[1][1][0], af[1][1][1], af[1][1][2], af[1][1][3], bv.z, bv.w);
        }
        if (more) CP_WAIT0();
        __syncthreads();
    }

    if constexpr (EPI == 0) {
        #pragma unroll
        for (int mf = 0; mf < 2; mf++)
        #pragma unroll
        for (int rs = 0; rs < 2; rs++) {
            int r = row0 + wM * 32 + mf * 16 + rs * 8 + gq;
            if (r >= M) continue;
            #pragma unroll
            for (int nf = 0; nf < 8; nf++) {
                int nc = wN * 64 + nf * 8 + tig * 2;
                float v0 = silu_f(acc[mf][nf][rs * 2 + 0] + __ldg(bias + n0s + nc));
                float v1 = silu_f(acc[mf][nf][rs * 2 + 1] + __ldg(bias + n0s + nc + 1));
                *(__half2*)(C + (size_t)r * ldc + n0s + nc) = __floats2half2_rn(v0, v1);
            }
        }
    } else {
        #pragma unroll
        for (int mf = 0; mf < 2; mf++)
        #pragma unroll
        for (int rs = 0; rs < 2; rs++) {
            int e = row0 + wM * 32 + mf * 16 + rs * 8 + gq;
            if (e >= M) continue;
            float* o = eout + (size_t)e * 128;
            #pragma unroll
            for (int nf = 0; nf < 8; nf++) {
                int f = wN * 64 + nf * 8 + tig * 2;
                float v0 = acc[mf][nf][rs * 2 + 0] + __ldg(bias + f);
                float v1 = acc[mf][nf][rs * 2 + 1] + __ldg(bias + f + 1);
                *(float2*)(o + f) = make_float2(v0, v1);
            }
        }
    }
}

// ================= launch (multi-stream fork/join for graph capture) =================
extern "C" void kernel_launch(void* const* d_in, const int* in_sizes, int n_in,
                              void* d_out, int out_size) {
    const float* s_j  = (const float*)d_in[0];
    const float* v_j  = (const float*)d_in[1];
    const float* r_ij = (const float*)d_in[2];
    const int*   nbrs = (const int*)  d_in[3];
    const float* ln_g = (const float*)d_in[4];
    const float* ln_b = (const float*)d_in[5];
    const float* Wq   = (const float*)d_in[6];
    const float* bq   = (const float*)d_in[7];
    const float* Wk   = (const float*)d_in[8];
    const float* bk   = (const float*)d_in[9];
    const float* Wv   = (const float*)d_in[10];
    const float* bv   = (const float*)d_in[11];
    const float* Wdk  = (const float*)d_in[12];
    const float* bdk  = (const float*)d_in[13];
    const float* Wdv  = (const float*)d_in[14];
    const float* bdv  = (const float*)d_in[15];
    const float* Wd   = (const float*)d_in[16];
    const float* bd   = (const float*)d_in[17];
    float* out = (float*)d_out;

    float *x, *qkv, *unitc, *eout, *ms, *su, *U;
    __half *rbf, *dkdv, *msg;
    int2* ij;
    uint32_t *wdp, *wdkp, *wdvp;
    int *cnt, *off, *pos, *eidx;
    cudaGetSymbolAddress((void**)&x,    g_x);
    cudaGetSymbolAddress((void**)&qkv,  g_qkv);
    cudaGetSymbolAddress((void**)&rbf,  g_rbf);
    cudaGetSymbolAddress((void**)&unitc, g_unitc);
    cudaGetSymbolAddress((void**)&ij,   g_ij);
    cudaGetSymbolAddress((void**)&dkdv, g_dkdv);
    cudaGetSymbolAddress((void**)&msg,  g_msg);
    cudaGetSymbolAddress((void**)&eout, g_eout);
    cudaGetSymbolAddress((void**)&ms,   g_ms);
    cudaGetSymbolAddress((void**)&su,   g_su);
    cudaGetSymbolAddress((void**)&U,    g_u);
    cudaGetSymbolAddress((void**)&wdp,  g_wdp);
    cudaGetSymbolAddress((void**)&wdkp, g_wdkp);
    cudaGetSymbolAddress((void**)&wdvp, g_wdvp);
    cudaGetSymbolAddress((void**)&cnt,  g_cnt);
    cudaGetSymbolAddress((void**)&off,  g_off);
    cudaGetSymbolAddress((void**)&pos,  g_pos);
    cudaGetSymbolAddress((void**)&eidx, g_eidx);

    const int SMEM_MMA = 4 * ABUFU * 4;   // 40960
    cudaFuncSetAttribute(mma_fp16<0>, cudaFuncAttributeMaxDynamicSharedMemorySize, SMEM_MMA);
    cudaFuncSetAttribute(mma_fp16<1>, cudaFuncAttributeMaxDynamicSharedMemorySize, SMEM_MMA);

    // persistent streams/events (created once, outside any capture replay)
    static cudaStream_t s2 = nullptr, s3 = nullptr;
    static cudaEvent_t ev0, evC, evQ, evM, evS;
    if (!s2) {
        cudaStreamCreateWithFlags(&s2, cudaStreamNonBlocking);
        cudaStreamCreateWithFlags(&s3, cudaStreamNonBlocking);
        cudaEventCreateWithFlags(&ev0, cudaEventDisableTiming);
        cudaEventCreateWithFlags(&evC, cudaEventDisableTiming);
        cudaEventCreateWithFlags(&evQ, cudaEventDisableTiming);
        cudaEventCreateWithFlags(&evM, cudaEventDisableTiming);
        cudaEventCreateWithFlags(&evS, cudaEventDisableTiming);
    }

    // fork from capture stream (default)
    cudaEventRecord(ev0, 0);
    cudaStreamWaitEvent(s2, ev0, 0);
    cudaStreamWaitEvent(s3, ev0, 0);

    // s2: weight pre-permutation (independent)
    conv_B<<<(128 * 16 * 16 + 255) / 256, 256, 0, s2>>>(Wd, wdp, 128, 16, 512, 384);
    conv_B<<<(512 * 2 * 16 + 255) / 256, 256, 0, s2>>>(Wdk, wdkp, 512, 2, 50, 512);
    conv_B<<<(512 * 2 * 16 + 255) / 256, 256, 0, s2>>>(Wdv, wdvp, 512, 2, 50, 512);
    cudaEventRecord(evC, s2);

    // s3: layernorm + qkv (needed only by attn)
    ln_kernel<<<NN, 128, 0, s3>>>(s_j, ln_g, ln_b, x);
    dim3 gq3(12, (NN + 127) / 128);
    qkv_gemm<<<gq3, 256, 0, s3>>>(x, Wq, Wk, Wv, bq, bk, bv, qkv);
    cudaEventRecord(evQ, s3);

    // default: CSR build + edge prep
    zero_int<<<(NN + 255) / 256, 256>>>(cnt, NN);
    csr_hist<<<(NE + 255) / 256, 256>>>(nbrs, cnt);
    csr_scan<<<1, 256>>>(cnt, off, pos);
    csr_scatter<<<(NE + 255) / 256, 256>>>(nbrs, pos, eidx);
    edge_prep<<<(NE + 255) / 256, 256>>>(eidx, nbrs, r_ij, rbf, unitc, ij);

    // dk/dv GEMMs need conv_B results
    cudaStreamWaitEvent(0, evC, 0);
    int mtiles = (NE + 127) / 128;   // 1954
    dim3 ge(4, mtiles);
    mma_fp16<0><<<ge, 256, SMEM_MMA>>>(rbf, wdkp, bdk, dkdv, 1024, nullptr,
                                       NE, RBFP, 2);
    mma_fp16<0><<<ge, 256, SMEM_MMA>>>(rbf, wdvp, bdv, dkdv + 512, 1024, nullptr,
                                       NE, RBFP, 2);

    // attn needs qkv
    cudaStreamWaitEvent(0, evQ, 0);
    attn_msg<<<(NE + 7) / 8, 256>>>(qkv, dkdv, ij, msg);
    cudaEventRecord(evM, 0);

    // s2: s0 edge GEMM (independent of node path)
    cudaStreamWaitEvent(s2, evM, 0);
    mma_fp16<1><<<mtiles, 256, SMEM_MMA, s2>>>(msg, wdp, bd, nullptr, 0, eout,
                                               NE, 512, 16);
    cudaEventRecord(evS, s2);

    // default: node path (segsum + node GEMMs -> ds, U)
    msg_segsum<<<NN, 128>>>(off, msg, unitc, ms, su);
    dim3 gnode(4, (NN + 127) / 128);
    node_gemm<<<gnode, 256>>>(ms, Wd, bd, off, su, out, U);

    // join: gather needs eout (s2) + U (default)
    cudaStreamWaitEvent(0, evS, 0);
    gather_kernel<<<NN, 128>>>(off, ij, v_j, eout, U, out + NN * FF);
}

// round 17
// speedup vs baseline: 1.1573x; 1.0002x over previous
#include <cuda_runtime.h>
#include <cuda_fp16.h>
#include <math.h>
#include <stdint.h>

#define NN   10000
#define NE   250000
#define FF   128
#define NRBF 50
#define RBFP 64

typedef unsigned long long ull;

// ---------------- scratch (all edge arrays in CSR "p" order) ----------------
__device__ float  g_x[NN * FF];
__device__ float  g_qkv[NN * 3 * 512];
__device__ __half g_rbf[(size_t)NE * RBFP];
__device__ float  g_unitc[(size_t)NE * 3];
__device__ int2   g_ij[NE];
__device__ __half g_dkdv[(size_t)NE * 1024];
__device__ __half g_msg[(size_t)NE * 512];
__device__ float  g_eout[(size_t)NE * 128];
__device__ float  g_ms[(size_t)4 * NN * 512];     // [ms | T0 | T1 | T2]
__device__ float  g_su[NN * 3];
__device__ float  g_u[(size_t)3 * NN * 128];
__device__ uint32_t g_wdp[128 * 16 * 16];         // Wd cols 0-127
__device__ uint32_t g_wdkvp[1024 * 2 * 16];       // [Wdk | Wdv] concat
__device__ int g_cnt[NN];
__device__ int g_off[NN + 1];
__device__ int g_pos[NN];
__device__ int g_eidx[NE];

#define FMA2(acc, a, b) asm("fma.rn.f32x2 %0, %1, %2, %0;" : "+l"(acc) : "l"(a), "l"(b))
#define PACK2(dst, f)   asm("mov.b64 %0, {%1, %1};" : "=l"(dst) : "f"(f))
#define UNPACK2(lo, hi, v) asm("mov.b64 {%0, %1}, %2;" : "=f"(lo), "=f"(hi) : "l"(v))

__device__ __forceinline__ uint32_t smem_u32(const void* p) {
    uint32_t a;
    asm("{ .reg .u64 t; cvta.to.shared.u64 t, %1; cvt.u32.u64 %0, t; }" : "=r"(a) : "l"(p));
    return a;
}
__device__ __forceinline__ float silu_f(float v) {
    return v / (1.f + __expf(-v));
}

#define MMA_F16(c, a0, a1, a2, a3, b0, b1)                                \
    asm volatile("mma.sync.aligned.m16n8k16.row.col.f32.f16.f16.f32 "     \
        "{%0,%1,%2,%3}, {%4,%5,%6,%7}, {%8,%9}, {%0,%1,%2,%3};"           \
        : "+f"((c)[0]), "+f"((c)[1]), "+f"((c)[2]), "+f"((c)[3])          \
        : "r"(a0), "r"(a1), "r"(a2), "r"(a3), "r"(b0), "r"(b1))

#define CP_ASYNC16(dst, src) \
    asm volatile("cp.async.ca.shared.global [%0], [%1], 16;" :: "r"(dst), "l"(src))
#define CP_COMMIT() asm volatile("cp.async.commit_group;" ::: "memory")
#define CP_WAIT0()  asm volatile("cp.async.wait_group 0;" ::: "memory")

// ================= CSR build =================
__global__ void zero_int(int* __restrict__ p, int n) {
    int i = blockIdx.x * blockDim.x + threadIdx.x;
    if (i < n) p[i] = 0;
}
__global__ void csr_hist(const int* __restrict__ nbrs, int* __restrict__ cnt) {
    int e = blockIdx.x * 256 + threadIdx.x;
    if (e < NE) atomicAdd(&cnt[nbrs[2 * e]], 1);
}
__global__ void __launch_bounds__(256) csr_scan(const int* __restrict__ cnt,
                                                int* __restrict__ off,
                                                int* __restrict__ pos) {
    __shared__ int base;
    __shared__ int wsum[8];
    if (threadIdx.x == 0) base = 0;
    __syncthreads();
    for (int c0 = 0; c0 < NN; c0 += 256) {
        int i = c0 + threadIdx.x;
        int v = (i < NN) ? cnt[i] : 0;
        int lane = threadIdx.x & 31, w = threadIdx.x >> 5;
        int x = v;
        #pragma unroll
        for (int o = 1; o < 32; o <<= 1) {
            int y = __shfl_up_sync(0xffffffffu, x, o);
            if (lane >= o) x += y;
        }
        if (lane == 31) wsum[w] = x;
        __syncthreads();
        int add = 0;
        #pragma unroll
        for (int k = 0; k < 8; k++) if (k < w) add += wsum[k];
        int incl = x + add;
        if (i < NN) {
            int excl = base + incl - v;
            off[i] = excl;
            pos[i] = excl;
        }
        __syncthreads();
        if (threadIdx.x == 255) base += incl;
        __syncthreads();
    }
    if (threadIdx.x == 0) off[NN] = base;
}
__global__ void csr_scatter(const int* __restrict__ nbrs, int* __restrict__ pos,
                            int* __restrict__ eidx) {
    int e = blockIdx.x * 256 + threadIdx.x;
    if (e < NE) {
        int p = atomicAdd(&pos[nbrs[2 * e]], 1);
        eidx[p] = e;
    }
}

// ================= edge prep in CSR order =================
__global__ void __launch_bounds__(256) edge_prep(const int* __restrict__ eidx,
                                                 const int* __restrict__ nbrs,
                                                 const float* __restrict__ r,
                                                 __half* __restrict__ rbf,
                                                 float* __restrict__ unitc,
                                                 int2* __restrict__ ij) {
    int p = blockIdx.x * 256 + threadIdx.x;
    if (p >= NE) return;
    int e = __ldg(eidx + p);
    ij[p] = make_int2(__ldg(nbrs + 2 * e), __ldg(nbrs + 2 * e + 1));
    float x = __ldg(r + 3 * e), y = __ldg(r + 3 * e + 1), z = __ldg(r + 3 * e + 2);
    float d = sqrtf(x * x + y * y + z * z + 3e-15f);
    float inv = 1.f / d;
    unitc[3 * p] = x * inv; unitc[3 * p + 1] = y * inv; unitc[3 * p + 2] = z * inv;
    const float width = 5.0f / 49.0f;
    const float gam = 0.5f / (width * width);
    __half2 buf[32];
    #pragma unroll
    for (int k2 = 0; k2 < 32; k2++) {
        int k0 = k2 * 2, k1 = k2 * 2 + 1;
        float d0 = d - (float)k0 * width;
        float d1 = d - (float)k1 * width;
        float v0 = (k0 < NRBF) ? __expf(-gam * d0 * d0) : 0.f;
        float v1 = (k1 < NRBF) ? __expf(-gam * d1 * d1) : 0.f;
        buf[k2] = __floats2half2_rn(v0, v1);
    }
    uint4* dst = (uint4*)(rbf + (size_t)p * RBFP);
    const uint4* src = (const uint4*)buf;
    #pragma unroll
    for (int q = 0; q < 8; q++) dst[q] = src[q];
}

// ================= msg segment-sum + unit-weighted sums =================
__global__ void __launch_bounds__(128)
msg_segsum(const int* __restrict__ off,
           const __half* __restrict__ msg, const float* __restrict__ unitc,
           float* __restrict__ ms, float* __restrict__ su) {
    int i = blockIdx.x;
    int t = threadIdx.x;
    int s = off[i], tend = off[i + 1];
    float a[4]  = {0.f, 0.f, 0.f, 0.f};
    float t0[4] = {0.f, 0.f, 0.f, 0.f};
    float t1[4] = {0.f, 0.f, 0.f, 0.f};
    float t2[4] = {0.f, 0.f, 0.f, 0.f};
    float sux = 0.f, suy = 0.f, suz = 0.f;
    for (int p = s; p < tend; p++) {
        float ux = __ldg(unitc + 3 * p), uy = __ldg(unitc + 3 * p + 1), uz = __ldg(unitc + 3 * p + 2);
        uint2 m = *(const uint2*)(msg + (size_t)p * 512 + t * 4);
        float2 x0 = __half22float2(*(__half2*)&m.x);
        float2 x1 = __half22float2(*(__half2*)&m.y);
        float v[4] = {x0.x, x0.y, x1.x, x1.y};
        #pragma unroll
        for (int q = 0; q < 4; q++) {
            a[q]  += v[q];
            t0[q] += v[q] * ux;
            t1[q] += v[q] * uy;
            t2[q] += v[q] * uz;
        }
        sux += ux; suy += uy; suz += uz;
    }
    size_t base = (size_t)i * 512 + t * 4;
    const size_t plane = (size_t)NN * 512;
    *(float4*)(ms + base)             = make_float4(a[0], a[1], a[2], a[3]);
    *(float4*)(ms + plane + base)     = make_float4(t0[0], t0[1], t0[2], t0[3]);
    *(float4*)(ms + 2 * plane + base) = make_float4(t1[0], t1[1], t1[2], t1[3]);
    *(float4*)(ms + 3 * plane + base) = make_float4(t2[0], t2[1], t2[2], t2[3]);
    if (t == 0) {
        su[3 * i] = sux; su[3 * i + 1] = suy; su[3 * i + 2] = suz;
    }
}

// ================= node GEMM: ds and U planes =================
__global__ void __launch_bounds__(256, 2)
node_gemm(const float* __restrict__ msbase, const float* __restrict__ Wd,
          const float* __restrict__ bd, const int* __restrict__ off,
          const float* __restrict__ su,
          float* __restrict__ dsout, float* __restrict__ U) {
    const int M = NN, K = 512;
    int which = blockIdx.x;
    const float* A    = msbase + (size_t)which * NN * 512;
    const float* B    = Wd + ((which == 0) ? 128 : 256);
    const float* bias = bd + ((which == 0) ? 128 : 256);
    float* C = (which == 0) ? dsout : (U + (size_t)(which - 1) * NN * 128);
    int row0 = blockIdx.y * 128;

    __shared__ float As[2][8][128];
    __shared__ float Bs[2][8][128];

    int t  = threadIdx.x;
    int ty = t >> 4, tx = t & 15;

    int arow = t >> 1;
    int acol = (t & 1) * 4;
    int am   = min(row0 + arow, M - 1);
    const float* Aptr = A + (size_t)am * K + acol;

    int bk_ = t >> 5;
    int bn  = (t & 31) * 4;

    float4 ar, br;
    ar = *(const float4*)(Aptr);
    br = *(const float4*)(B + (size_t)bk_ * 384 + bn);

    As[0][acol + 0][arow] = ar.x;
    As[0][acol + 1][arow] = ar.y;
    As[0][acol + 2][arow] = ar.z;
    As[0][acol + 3][arow] = ar.w;
    *(float4*)&Bs[0][bk_][bn] = br;
    __syncthreads();

    ull acc[8][4];
    #pragma unroll
    for (int i = 0; i < 8; i++)
        #pragma unroll
        for (int j = 0; j < 4; j++) acc[i][j] = 0ULL;

    const int nstage = K >> 3;
    for (int s = 0; s < nstage; s++) {
        int cur = s & 1, nxt = cur ^ 1;
        bool more = (s + 1 < nstage);
        if (more) {
            int kk = (s + 1) << 3;
            ar = *(const float4*)(Aptr + kk);
            br = *(const float4*)(B + (size_t)(kk + bk_) * 384 + bn);
        }
        #pragma unroll
        for (int k = 0; k < 8; k++) {
            float4 a0 = *(float4*)&As[cur][k][ty * 8];
            float4 a1 = *(float4*)&As[cur][k][ty * 8 + 4];
            ulonglong2 b0 = *(ulonglong2*)&Bs[cur][k][tx * 8];
            ulonglong2 b1 = *(ulonglong2*)&Bs[cur][k][tx * 8 + 4];
            ull a2[8];
            PACK2(a2[0], a0.x); PACK2(a2[1], a0.y);
            PACK2(a2[2], a0.z); PACK2(a2[3], a0.w);
            PACK2(a2[4], a1.x); PACK2(a2[5], a1.y);
            PACK2(a2[6], a1.z); PACK2(a2[7], a1.w);
            #pragma unroll
            for (int i = 0; i < 8; i++) {
                FMA2(acc[i][0], a2[i], b0.x);
                FMA2(acc[i][1], a2[i], b0.y);
                FMA2(acc[i][2], a2[i], b1.x);
                FMA2(acc[i][3], a2[i], b1.y);
            }
        }
        if (more) {
            As[nxt][acol + 0][arow] = ar.x;
            As[nxt][acol + 1][arow] = ar.y;
            As[nxt][acol + 2][arow] = ar.z;
            As[nxt][acol + 3][arow] = ar.w;
            *(float4*)&Bs[nxt][bk_][bn] = br;
        }
        __syncthreads();
    }

    int colb = tx * 8;
    float4 bs0 = *(const float4*)(bias + colb);
    float4 bs1 = *(const float4*)(bias + colb + 4);
    #pragma unroll
    for (int i = 0; i < 8; i++) {
        int row = row0 + ty * 8 + i;
        if (row >= M) continue;
        float sc = (which == 0)
                 ? (float)(__ldg(off + row + 1) - __ldg(off + row))
                 : __ldg(su + 3 * row + (which - 1));
        float v[8];
        UNPACK2(v[0], v[1], acc[i][0]);
        UNPACK2(v[2], v[3], acc[i][1]);
        UNPACK2(v[4], v[5], acc[i][2]);
        UNPACK2(v[6], v[7], acc[i][3]);
        v[0] += sc * bs0.x; v[1] += sc * bs0.y; v[2] += sc * bs0.z; v[3] += sc * bs0.w;
        v[4] += sc * bs1.x; v[5] += sc * bs1.y; v[6] += sc * bs1.z; v[7] += sc * bs1.w;
        float* cp = C + (size_t)row * 128 + colb;
        *(float4*)cp       = make_float4(v[0], v[1], v[2], v[3]);
        *(float4*)(cp + 4) = make_float4(v[4], v[5], v[6], v[7]);
    }
}

// ================= dv gather: s0*v_j + U =================
__global__ void __launch_bounds__(128)
gather_kernel(const int* __restrict__ off, const int2* __restrict__ ij,
              const float* __restrict__ v_j, const float* __restrict__ eout,
              const float* __restrict__ U, float* __restrict__ dvout) {
    int i = blockIdx.x;
    int f = threadIdx.x;
    int s = off[i], t = off[i + 1];
    float a0 = 0.f, a1 = 0.f, a2 = 0.f;
    for (int p = s; p < t; p++) {
        int jj = __ldg(&ij[p].y);
        float s0 = __ldg(eout + (size_t)p * 128 + f);
        const float* vj = v_j + ((size_t)jj * FF + f) * 3;
        a0 += s0 * vj[0];
        a1 += s0 * vj[1];
        a2 += s0 * vj[2];
    }
    size_t idx = (size_t)i * 128 + f;
    const size_t pl = (size_t)NN * 128;
    float* dv = dvout + idx * 3;
    dv[0] = a0 + __ldg(U + idx);
    dv[1] = a1 + __ldg(U + pl + idx);
    dv[2] = a2 + __ldg(U + 2 * pl + idx);
}

// ================= B pre-permutation =================
__global__ void conv_B(const float* __restrict__ W, uint32_t* __restrict__ out,
                       int N, int nst, int Kreal, int Nld) {
    int i = blockIdx.x * 256 + threadIdx.x;
    int total = N * nst * 16;
    if (i >= total) return;
    int n = i / (nst * 16);
    int rem = i % (nst * 16);
    int s = rem >> 4, p = rem & 15;
    int bp = (p & 3) * 4 + (p >> 2);
    int k = s * 32 + bp * 2;
    float lo = (k < Kreal)     ? W[(size_t)k * Nld + n]       : 0.f;
    float hi = (k + 1 < Kreal) ? W[(size_t)(k + 1) * Nld + n] : 0.f;
    __half2 h = __floats2half2_rn(lo, hi);
    out[i] = *(uint32_t*)&h;
}

__global__ void __launch_bounds__(128) ln_kernel(const float* __restrict__ s,
                                                 const float* __restrict__ gam,
                                                 const float* __restrict__ bet,
                                                 float* __restrict__ x) {
    int n = blockIdx.x, t = threadIdx.x;
    float v = s[(size_t)n * FF + t];
    float s1 = v, s2 = v * v;
    #pragma unroll
    for (int o = 16; o; o >>= 1) {
        s1 += __shfl_down_sync(0xffffffffu, s1, o);
        s2 += __shfl_down_sync(0xffffffffu, s2, o);
    }
    __shared__ float p1[4], p2[4], mv[2];
    if ((t & 31) == 0) { p1[t >> 5] = s1; p2[t >> 5] = s2; }
    __syncthreads();
    if (t == 0) {
        float a = p1[0] + p1[1] + p1[2] + p1[3];
        float c = p2[0] + p2[1] + p2[2] + p2[3];
        float m = a / 128.f;
        mv[0] = m;
        mv[1] = rsqrtf(c / 128.f - m * m + 1e-5f);
    }
    __syncthreads();
    x[(size_t)n * FF + t] = (v - mv[0]) * mv[1] * gam[t] + bet[t];
}

// ================= qkv: fused 3-way f32x2 SGEMM =================
__global__ void __launch_bounds__(256, 2)
qkv_gemm(const float* __restrict__ Xin,
         const float* __restrict__ Wq, const float* __restrict__ Wk,
         const float* __restrict__ Wv,
         const float* __restrict__ bq, const float* __restrict__ bk,
         const float* __restrict__ bv,
         float* __restrict__ qkvout) {
    const int M = NN, N = 512, K = 128, lda = 128, ldc = 1536;
    int which = blockIdx.x >> 2;
    const float* B    = (which == 0) ? Wq : ((which == 1) ? Wk : Wv);
    const float* bias = (which == 0) ? bq : ((which == 1) ? bk : bv);
    float* C = qkvout + which * 512;
    int col0 = (blockIdx.x & 3) * 128;
    int row0 = blockIdx.y * 128;

    __shared__ float As[2][8][128];
    __shared__ float Bs[2][8][128];

    int t  = threadIdx.x;
    int ty = t >> 4, tx = t & 15;

    int arow = t >> 1;
    int acol = (t & 1) * 4;
    int am   = min(row0 + arow, M - 1);
    const float* Aptr = Xin + (size_t)am * lda + acol;

    int bk_ = t >> 5;
    int bn  = (t & 31) * 4;

    float4 ar, br;
    ar = *(const float4*)(Aptr);
    br = *(const float4*)(B + (size_t)bk_ * N + col0 + bn);

    As[0][acol + 0][arow] = ar.x;
    As[0][acol + 1][arow] = ar.y;
    As[0][acol + 2][arow] = ar.z;
    As[0][acol + 3][arow] = ar.w;
    *(float4*)&Bs[0][bk_][bn] = br;
    __syncthreads();

    ull acc[8][4];
    #pragma unroll
    for (int i = 0; i < 8; i++)
        #pragma unroll
        for (int j = 0; j < 4; j++) acc[i][j] = 0ULL;

    const int nstage = K >> 3;
    for (int s = 0; s < nstage; s++) {
        int cur = s & 1, nxt = cur ^ 1;
        bool more = (s + 1 < nstage);
        if (more) {
            int kk = (s + 1) << 3;
            ar = *(const float4*)(Aptr + kk);
            br = *(const float4*)(B + (size_t)(kk + bk_) * N + col0 + bn);
        }
        #pragma unroll
        for (int k = 0; k < 8; k++) {
            float4 a0 = *(float4*)&As[cur][k][ty * 8];
            float4 a1 = *(float4*)&As[cur][k][ty * 8 + 4];
            ulonglong2 b0 = *(ulonglong2*)&Bs[cur][k][tx * 8];
            ulonglong2 b1 = *(ulonglong2*)&Bs[cur][k][tx * 8 + 4];
            ull a2[8];
            PACK2(a2[0], a0.x); PACK2(a2[1], a0.y);
            PACK2(a2[2], a0.z); PACK2(a2[3], a0.w);
            PACK2(a2[4], a1.x); PACK2(a2[5], a1.y);
            PACK2(a2[6], a1.z); PACK2(a2[7], a1.w);
            #pragma unroll
            for (int i = 0; i < 8; i++) {
                FMA2(acc[i][0], a2[i], b0.x);
                FMA2(acc[i][1], a2[i], b0.y);
                FMA2(acc[i][2], a2[i], b1.x);
                FMA2(acc[i][3], a2[i], b1.y);
            }
        }
        if (more) {
            As[nxt][acol + 0][arow] = ar.x;
            As[nxt][acol + 1][arow] = ar.y;
            As[nxt][acol + 2][arow] = ar.z;
            As[nxt][acol + 3][arow] = ar.w;
            *(float4*)&Bs[nxt][bk_][bn] = br;
        }
        __syncthreads();
    }

    int colb = col0 + tx * 8;
    float4 bs0 = *(const float4*)(bias + colb);
    float4 bs1 = *(const float4*)(bias + colb + 4);
    #pragma unroll
    for (int i = 0; i < 8; i++) {
        int row = row0 + ty * 8 + i;
        if (row >= M) continue;
        float v[8];
        UNPACK2(v[0], v[1], acc[i][0]);
        UNPACK2(v[2], v[3], acc[i][1]);
        UNPACK2(v[4], v[5], acc[i][2]);
        UNPACK2(v[6], v[7], acc[i][3]);
        v[0] += bs0.x; v[1] += bs0.y; v[2] += bs0.z; v[3] += bs0.w;
        v[4] += bs1.x; v[5] += bs1.y; v[6] += bs1.z; v[7] += bs1.w;
        float* cp = C + (size_t)row * ldc + colb;
        *(float4*)cp       = make_float4(v[0], v[1], v[2], v[3]);
        *(float4*)(cp + 4) = make_float4(v[4], v[5], v[6], v[7]);
    }
}

// ================= attn + msg: warp-per-edge (p-space, chunked) =================
__global__ void __launch_bounds__(256) attn_msg(const float* __restrict__ qkv,
                                                const __half* __restrict__ dkdv,
                                                const int2* __restrict__ ij,
                                                __half* __restrict__ msg,
                                                int p0, int pcount) {
    int pr_ = blockIdx.x * 8 + (threadIdx.x >> 5);
    if (pr_ >= pcount) return;
    int p = p0 + pr_;
    int l = threadIdx.x & 31;
    int2 eij = __ldg(&ij[p]);
    int i = eij.x, j = eij.y;
    const float4* q4 = (const float4*)(qkv + (size_t)i * 1536);
    const float4* k4 = (const float4*)(qkv + (size_t)j * 1536 + 512);
    const float4* v4 = (const float4*)(qkv + (size_t)j * 1536 + 1024);
    const uint2* dk2 = (const uint2*)(dkdv + (size_t)p * 1024);
    const uint2* dv2 = dk2 + 128;

    float4 qv[4], kv[4], vv[4];
    uint2 dkv[4], dvv[4];
    #pragma unroll
    for (int h = 0; h < 4; h++) {
        int idx = h * 32 + l;
        qv[h] = q4[idx]; kv[h] = k4[idx]; vv[h] = v4[idx];
        dkv[h] = dk2[idx]; dvv[h] = dv2[idx];
    }
    float pr[4];
    #pragma unroll
    for (int h = 0; h < 4; h++) {
        float2 f0 = __half22float2(*(__half2*)&dkv[h].x);
        float2 f1 = __half22float2(*(__half2*)&dkv[h].y);
        pr[h] = qv[h].x * kv[h].x * f0.x + qv[h].y * kv[h].y * f0.y
              + qv[h].z * kv[h].z * f1.x + qv[h].w * kv[h].w * f1.y;
    }
    #pragma unroll
    for (int o = 16; o; o >>= 1)
        #pragma unroll
        for (int h = 0; h < 4; h++) pr[h] += __shfl_xor_sync(0xffffffffu, pr[h], o);

    __half* mrow = msg + (size_t)p * 512;
    #pragma unroll
    for (int h = 0; h < 4; h++) {
        float at = silu_f(pr[h]);
        float2 g0 = __half22float2(*(__half2*)&dvv[h].x);
        float2 g1 = __half22float2(*(__half2*)&dvv[h].y);
        __half2 m0 = __floats2half2_rn(vv[h].x * g0.x * at, vv[h].y * g0.y * at);
        __half2 m1 = __floats2half2_rn(vv[h].z * g1.x * at, vv[h].w * g1.y * at);
        uint2 o2;
        o2.x = *(uint32_t*)&m0;
        o2.y = *(uint32_t*)&m1;
        *(uint2*)(mrow + h * 128 + l * 4) = o2;
    }
}

// ================= fp16 mma GEMM (2 CTAs/SM, row-chunked) =================
// EPI=0: dkdv fused — silu + half store, bias from [bdk|bdv] selected by n0s.
// EPI=1: s0 GEMM — biased float store to eout (stride 128).
#define SROWU 20
#define ABUFU (128 * SROWU)

template <int EPI>
__global__ void __launch_bounds__(256, 2)
mma_fp16(const __half* __restrict__ A, const uint32_t* __restrict__ Bp,
         const float* __restrict__ bias, const float* __restrict__ bias2,
         __half* __restrict__ C, int ldc,
         float* __restrict__ eout,
         int M, int lda, int nstage, int rowoff) {
    extern __shared__ uint32_t sm[];
    const uint32_t sA = smem_u32(sm);
    const uint32_t sB0 = sA + 2 * ABUFU * 4;

    const int tid = threadIdx.x;
    const int wid = tid >> 5, lid = tid & 31;
    const int gq = lid >> 2, tig = lid & 3;
    const int wM = wid >> 1, wN = wid & 1;
    const int row0 = (EPI == 1 ? (int)blockIdx.x : (int)blockIdx.y + rowoff) * 128;
    const int n0s  = (EPI == 1 ? 0 : blockIdx.x * 128);

    float acc[2][8][4];
    #pragma unroll
    for (int a = 0; a < 2; a++)
        #pragma unroll
        for (int b = 0; b < 8; b++)
            #pragma unroll
            for (int c = 0; c < 4; c++) acc[a][b][c] = 0.f;

    const int arow = tid >> 1, ac2 = (tid & 1) * 2;
    const __half* aRow = A + (size_t)min(row0 + arow, M - 1) * lda;

    auto stage_A = [&](int s, int buf) {
        const __half* src = aRow + s * 32 + ac2 * 8;
        uint32_t dst = sA + (buf * ABUFU + arow * SROWU + ac2 * 4) * 4;
        CP_ASYNC16(dst, src);
        CP_ASYNC16(dst + 16, src + 8);
    };

    auto stage_B = [&](int s, int buf) {
        #pragma unroll
        for (int i = 0; i < 2; i++) {
            int c = tid + i * 256;
            int n = c >> 2, q = c & 3;
            int ng = n0s + n;
            const uint32_t* src = Bp + ((size_t)ng * nstage + s) * 16 + q * 4;
            uint32_t dst = sB0 + (buf * ABUFU + n * SROWU + q * 4) * 4;
            CP_ASYNC16(dst, src);
        }
    };

    stage_A(0, 0);
    stage_B(0, 0);
    CP_COMMIT();
    CP_WAIT0();
    __syncthreads();

    for (int s = 0; s < nstage; s++) {
        int cur = s & 1;
        bool more = (s + 1 < nstage);
        if (more) {
            stage_A(s + 1, cur ^ 1);
            stage_B(s + 1, cur ^ 1);
            CP_COMMIT();
        }

        uint32_t af[2][2][4];
        const uint32_t* Ab = sm + cur * ABUFU;
        #pragma unroll
        for (int mf = 0; mf < 2; mf++) {
            int r0 = wM * 32 + mf * 16 + gq;
            const uint32_t* p0 = Ab + r0 * SROWU;
            const uint32_t* p1 = Ab + (r0 + 8) * SROWU;
            #pragma unroll
            for (int ks = 0; ks < 2; ks++) {
                af[mf][ks][0] = p0[tig + 8 * ks];
                af[mf][ks][1] = p1[tig + 8 * ks];
                af[mf][ks][2] = p0[tig + 4 + 8 * ks];
                af[mf][ks][3] = p1[tig + 4 + 8 * ks];
            }
        }
        const uint32_t* Bb = sm + 2 * ABUFU + cur * ABUFU;
        #pragma unroll
        for (int nf = 0; nf < 8; nf++) {
            int n = wN * 64 + nf * 8 + gq;
            uint4 bv = *(const uint4*)(Bb + n * SROWU + tig * 4);
            MMA_F16(acc[0][nf], af[0][0][0], af[0][0][1], af[0][0][2], af[0][0][3], bv.x, bv.y);
            MMA_F16(acc[1][nf], af[1][0][0], af[1][0][1], af[1][0][2], af[1][0][3], bv.x, bv.y);
            MMA_F16(acc[0][nf], af[0][1][0], af[0][1][1], af[0][1][2], af[0][1][3], bv.z, bv.w);
            MMA_F16(acc[1][nf], af[1][1][0], af[1][1][1], af[1][1][2], af[1][1][3], bv.z, bv.w);
        }
        if (more) CP_WAIT0();
        __syncthreads();
    }

    if constexpr (EPI == 0) {
        const float* bp = (n0s < 512) ? (bias + n0s) : (bias2 + (n0s - 512));
        #pragma unroll
        for (int mf = 0; mf < 2; mf++)
        #pragma unroll
        for (int rs = 0; rs < 2; rs++) {
            int r = row0 + wM * 32 + mf * 16 + rs * 8 + gq;
            if (r >= M) continue;
            #pragma unroll
            for (int nf = 0; nf < 8; nf++) {
                int nc = wN * 64 + nf * 8 + tig * 2;
                float v0 = silu_f(acc[mf][nf][rs * 2 + 0] + __ldg(bp + nc));
                float v1 = silu_f(acc[mf][nf][rs * 2 + 1] + __ldg(bp + nc + 1));
                *(__half2*)(C + (size_t)r * ldc + n0s + nc) = __floats2half2_rn(v0, v1);
            }
        }
    } else {
        #pragma unroll
        for (int mf = 0; mf < 2; mf++)
        #pragma unroll
        for (int rs = 0; rs < 2; rs++) {
            int e = row0 + wM * 32 + mf * 16 + rs * 8 + gq;
            if (e >= M) continue;
            float* o = eout + (size_t)e * 128;
            #pragma unroll
            for (int nf = 0; nf < 8; nf++) {
                int f = wN * 64 + nf * 8 + tig * 2;
                float v0 = acc[mf][nf][rs * 2 + 0] + __ldg(bias + f);
                float v1 = acc[mf][nf][rs * 2 + 1] + __ldg(bias + f + 1);
                *(float2*)(o + f) = make_float2(v0, v1);
            }
        }
    }
}

// ================= launch =================
extern "C" void kernel_launch(void* const* d_in, const int* in_sizes, int n_in,
                              void* d_out, int out_size) {
    const float* s_j  = (const float*)d_in[0];
    const float* v_j  = (const float*)d_in[1];
    const float* r_ij = (const float*)d_in[2];
    const int*   nbrs = (const int*)  d_in[3];
    const float* ln_g = (const float*)d_in[4];
    const float* ln_b = (const float*)d_in[5];
    const float* Wq   = (const float*)d_in[6];
    const float* bq   = (const float*)d_in[7];
    const float* Wk   = (const float*)d_in[8];
    const float* bk   = (const float*)d_in[9];
    const float* Wv   = (const float*)d_in[10];
    const float* bv   = (const float*)d_in[11];
    const float* Wdk  = (const float*)d_in[12];
    const float* bdk  = (const float*)d_in[13];
    const float* Wdv  = (const float*)d_in[14];
    const float* bdv  = (const float*)d_in[15];
    const float* Wd   = (const float*)d_in[16];
    const float* bd   = (const float*)d_in[17];
    float* out = (float*)d_out;

    float *x, *qkv, *unitc, *eout, *ms, *su, *U;
    __half *rbf, *dkdv, *msg;
    int2* ij;
    uint32_t *wdp, *wdkvp;
    int *cnt, *off, *pos, *eidx;
    cudaGetSymbolAddress((void**)&x,    g_x);
    cudaGetSymbolAddress((void**)&qkv,  g_qkv);
    cudaGetSymbolAddress((void**)&rbf,  g_rbf);
    cudaGetSymbolAddress((void**)&unitc, g_unitc);
    cudaGetSymbolAddress((void**)&ij,   g_ij);
    cudaGetSymbolAddress((void**)&dkdv, g_dkdv);
    cudaGetSymbolAddress((void**)&msg,  g_msg);
    cudaGetSymbolAddress((void**)&eout, g_eout);
    cudaGetSymbolAddress((void**)&ms,   g_ms);
    cudaGetSymbolAddress((void**)&su,   g_su);
    cudaGetSymbolAddress((void**)&U,    g_u);
    cudaGetSymbolAddress((void**)&wdp,  g_wdp);
    cudaGetSymbolAddress((void**)&wdkvp, g_wdkvp);
    cudaGetSymbolAddress((void**)&cnt,  g_cnt);
    cudaGetSymbolAddress((void**)&off,  g_off);
    cudaGetSymbolAddress((void**)&pos,  g_pos);
    cudaGetSymbolAddress((void**)&eidx, g_eidx);

    const int SMEM_MMA = 4 * ABUFU * 4;   // 40960
    cudaFuncSetAttribute(mma_fp16<0>, cudaFuncAttributeMaxDynamicSharedMemorySize, SMEM_MMA);
    cudaFuncSetAttribute(mma_fp16<1>, cudaFuncAttributeMaxDynamicSharedMemorySize, SMEM_MMA);

    static cudaStream_t s2 = nullptr, s3 = nullptr;
    static cudaEvent_t ev0, evC, evQ, evA, evMA, evMB, evS;
    if (!s2) {
        cudaStreamCreateWithFlags(&s2, cudaStreamNonBlocking);
        cudaStreamCreateWithFlags(&s3, cudaStreamNonBlocking);
        cudaEventCreateWithFlags(&ev0, cudaEventDisableTiming);
        cudaEventCreateWithFlags(&evC, cudaEventDisableTiming);
        cudaEventCreateWithFlags(&evQ, cudaEventDisableTiming);
        cudaEventCreateWithFlags(&evA, cudaEventDisableTiming);
        cudaEventCreateWithFlags(&evMA, cudaEventDisableTiming);
        cudaEventCreateWithFlags(&evMB, cudaEventDisableTiming);
        cudaEventCreateWithFlags(&evS, cudaEventDisableTiming);
    }

    cudaEventRecord(ev0, 0);
    cudaStreamWaitEvent(s2, ev0, 0);
    cudaStreamWaitEvent(s3, ev0, 0);

    // s2: weight pre-permutation
    conv_B<<<(128 * 16 * 16 + 255) / 256, 256, 0, s2>>>(Wd, wdp, 128, 16, 512, 384);
    conv_B<<<(512 * 2 * 16 + 255) / 256, 256, 0, s2>>>(Wdk, wdkvp, 512, 2, 50, 512);
    conv_B<<<(512 * 2 * 16 + 255) / 256, 256, 0, s2>>>(Wdv, wdkvp + 512 * 2 * 16, 512, 2, 50, 512);
    cudaEventRecord(evC, s2);

    // s3: layernorm + qkv
    ln_kernel<<<NN, 128, 0, s3>>>(s_j, ln_g, ln_b, x);
    dim3 gq3(12, (NN + 127) / 128);
    qkv_gemm<<<gq3, 256, 0, s3>>>(x, Wq, Wk, Wv, bq, bk, bv, qkv);
    cudaEventRecord(evQ, s3);

    // default: CSR build + edge prep
    zero_int<<<(NN + 255) / 256, 256>>>(cnt, NN);
    csr_hist<<<(NE + 255) / 256, 256>>>(nbrs, cnt);
    csr_scan<<<1, 256>>>(cnt, off, pos);
    csr_scatter<<<(NE + 255) / 256, 256>>>(nbrs, pos, eidx);
    edge_prep<<<(NE + 255) / 256, 256>>>(eidx, nbrs, r_ij, rbf, unitc, ij);

    // fused dkdv GEMM in 2 row-chunks
    int mtiles = (NE + 127) / 128;   // 1954
    int mA = mtiles / 2;             // 977
    int pSplit = mA * 128;           // 125056
    cudaStreamWaitEvent(0, evC, 0);
    dim3 geA(8, mA), geB(8, mtiles - mA);
    mma_fp16<0><<<geA, 256, SMEM_MMA>>>(rbf, wdkvp, bdk, bdv, dkdv, 1024, nullptr,
                                        NE, RBFP, 2, 0);
    cudaEventRecord(evA, 0);
    mma_fp16<0><<<geB, 256, SMEM_MMA>>>(rbf, wdkvp, bdk, bdv, dkdv, 1024, nullptr,
                                        NE, RBFP, 2, mA);

    // s2: attn chunk A overlapped with dkdv chunk B
    cudaStreamWaitEvent(s2, evA, 0);
    cudaStreamWaitEvent(s2, evQ, 0);
    attn_msg<<<(pSplit + 7) / 8, 256, 0, s2>>>(qkv, dkdv, ij, msg, 0, pSplit);
    cudaEventRecord(evMA, s2);

    // default: attn chunk B
    cudaStreamWaitEvent(0, evQ, 0);
    attn_msg<<<(NE - pSplit + 7) / 8, 256>>>(qkv, dkdv, ij, msg, pSplit, NE - pSplit);
    cudaEventRecord(evMB, 0);

    // s2: s0 edge GEMM (needs all msg)
    cudaStreamWaitEvent(s2, evMB, 0);
    mma_fp16<1><<<mtiles, 256, SMEM_MMA, s2>>>(msg, wdp, bd, nullptr, nullptr, 0, eout,
                                               NE, 512, 16, 0);
    cudaEventRecord(evS, s2);

    // default: node path (needs all msg)
    cudaStreamWaitEvent(0, evMA, 0);
    msg_segsum<<<NN, 128>>>(off, msg, unitc, ms, su);
    dim3 gnode(4, (NN + 127) / 128);
    node_gemm<<<gnode, 256>>>(ms, Wd, bd, off, su, out, U);

    // join: gather needs eout (s2) + U (default)
    cudaStreamWaitEvent(0, evS, 0);
    gather_kernel<<<NN, 128>>>(off, ij, v_j, eout, U, out + NN * FF);
}